// round 1
// baseline (speedup 1.0000x reference)
#include <cuda_runtime.h>
#include <cuda_bf16.h>
#include <math.h>

// Problem constants
#define S_  2048
#define H_  1024
#define NH_ 16
#define NKV_ 4
#define HD_ 64
#define QKV_O 1536           // (NH + 2*NKV)*HD
#define I_  2816
#define E_  8
#define WIN_ 512
#define EPS_ 1e-5f

// ---------------------------------------------------------------------------
// Scratch (static device globals; no allocation in kernel_launch)
// ---------------------------------------------------------------------------
__device__ float g_xnorm[S_ * H_];
__device__ float g_qkv[S_ * QKV_O];
__device__ float g_attn[S_ * H_];
__device__ float g_tnorm[S_ * H_];
__device__ float g_act[(size_t)E_ * S_ * I_];   // silu(g)*u per expert slot (~184 MB)
__device__ int   g_counts[E_];
__device__ int   g_toklist[E_ * S_];
__device__ float g_tokw[E_ * S_];

// ---------------------------------------------------------------------------
// zero out + counts
// ---------------------------------------------------------------------------
__global__ void zero_kernel(float* out, int* counts) {
    int i = blockIdx.x * blockDim.x + threadIdx.x;
    if (i < S_ * H_) out[i] = 0.0f;
    if (i < E_) counts[i] = 0;
}

// ---------------------------------------------------------------------------
// RMSNorm: one block per row
// ---------------------------------------------------------------------------
__global__ void rmsnorm_kernel(const float* __restrict__ x,
                               const float* __restrict__ w,
                               float* __restrict__ y) {
    int row = blockIdx.x;
    int tid = threadIdx.x;           // 256 threads
    __shared__ float red[256];
    const float* xr = x + (size_t)row * H_;
    float s = 0.0f;
    for (int c = tid; c < H_; c += 256) { float v = xr[c]; s += v * v; }
    red[tid] = s; __syncthreads();
    for (int o = 128; o > 0; o >>= 1) {
        if (tid < o) red[tid] += red[tid + o];
        __syncthreads();
    }
    float inv = rsqrtf(red[0] / (float)H_ + EPS_);
    for (int c = tid; c < H_; c += 256)
        y[(size_t)row * H_ + c] = xr[c] * inv * w[c];
}

// ---------------------------------------------------------------------------
// Generic NT GEMM: C[M,N] = A[M,K] * B[N,K]^T (+ addsrc)
// 64x64 tile, BK=16, 256 threads, 4x4 per thread. N,K multiples of 64/16.
// ---------------------------------------------------------------------------
__global__ void gemm_nt_kernel(const float* __restrict__ A,
                               const float* __restrict__ B,
                               float* __restrict__ C,
                               int M, int N, int K,
                               const float* __restrict__ addsrc) {
    __shared__ float As[16][65];
    __shared__ float Bs[16][65];
    int tid = threadIdx.x;
    int tx = tid & 15, ty = tid >> 4;
    int m0 = blockIdx.y * 64, n0 = blockIdx.x * 64;
    float acc[4][4] = {};
    for (int k0 = 0; k0 < K; k0 += 16) {
        #pragma unroll
        for (int l = 0; l < 4; l++) {
            int idx = tid + l * 256;
            int kk = idx & 15, mm = idx >> 4;
            int gm = m0 + mm;
            As[kk][mm] = (gm < M) ? A[(size_t)gm * K + k0 + kk] : 0.0f;
            Bs[kk][mm] = B[(size_t)(n0 + mm) * K + k0 + kk];
        }
        __syncthreads();
        #pragma unroll
        for (int kk = 0; kk < 16; kk++) {
            float a[4], b[4];
            #pragma unroll
            for (int i = 0; i < 4; i++) a[i] = As[kk][ty * 4 + i];
            #pragma unroll
            for (int j = 0; j < 4; j++) b[j] = Bs[kk][tx * 4 + j];
            #pragma unroll
            for (int i = 0; i < 4; i++)
                #pragma unroll
                for (int j = 0; j < 4; j++)
                    acc[i][j] += a[i] * b[j];
        }
        __syncthreads();
    }
    for (int i = 0; i < 4; i++) {
        int m = m0 + ty * 4 + i;
        if (m >= M) break;
        for (int j = 0; j < 4; j++) {
            int n = n0 + tx * 4 + j;
            float v = acc[i][j];
            if (addsrc) v += addsrc[(size_t)m * N + n];
            C[(size_t)m * N + n] = v;
        }
    }
}

// ---------------------------------------------------------------------------
// Sliding-window causal attention. One block = (query i, head h), 64 threads.
// ---------------------------------------------------------------------------
__global__ void attn_kernel(const float* __restrict__ qkv,
                            float* __restrict__ out) {
    int i = blockIdx.x;
    int h = blockIdx.y;
    int tid = threadIdx.x;           // 0..63
    int kvh = h >> 2;                // GQA: NH/NKV = 4

    __shared__ float qsh[64];
    __shared__ float ksh[64][65];
    __shared__ float sc[WIN_];
    __shared__ float red[64];

    qsh[tid] = qkv[(size_t)i * QKV_O + h * HD_ + tid];
    __syncthreads();

    int j0 = (i >= WIN_ - 1) ? (i - WIN_ + 1) : 0;
    int nk = i - j0 + 1;

    float lmax = -1e30f;
    for (int base = 0; base < nk; base += 64) {
        int cnt = min(64, nk - base);
        for (int r = 0; r < cnt; ++r)
            ksh[r][tid] = qkv[(size_t)(j0 + base + r) * QKV_O + H_ + kvh * HD_ + tid];
        __syncthreads();
        if (tid < cnt) {
            float d = 0.0f;
            #pragma unroll
            for (int c = 0; c < 64; ++c) d += qsh[c] * ksh[tid][c];
            d *= 0.125f;                 // HD^-0.5
            sc[base + tid] = d;
            lmax = fmaxf(lmax, d);
        }
        __syncthreads();
    }
    red[tid] = lmax; __syncthreads();
    for (int o = 32; o > 0; o >>= 1) {
        if (tid < o) red[tid] = fmaxf(red[tid], red[tid + o]);
        __syncthreads();
    }
    float mx = red[0]; __syncthreads();

    float lsum = 0.0f;
    for (int jj = tid; jj < nk; jj += 64) {
        float p = __expf(sc[jj] - mx);
        sc[jj] = p;
        lsum += p;
    }
    red[tid] = lsum; __syncthreads();
    for (int o = 32; o > 0; o >>= 1) {
        if (tid < o) red[tid] += red[tid + o];
        __syncthreads();
    }
    float inv = 1.0f / red[0];
    __syncthreads();

    // V accumulation: thread tid owns dim d = tid (coalesced across threads)
    float acc = 0.0f;
    for (int jj = 0; jj < nk; ++jj) {
        acc += sc[jj] * qkv[(size_t)(j0 + jj) * QKV_O + H_ + NKV_ * HD_ + kvh * HD_ + tid];
    }
    out[(size_t)i * H_ + h * HD_ + tid] = acc * inv;
}

// ---------------------------------------------------------------------------
// Router: softmax over 8 experts, top-2, append to per-expert lists.
// One warp per token, 256-thread blocks (8 tokens/block).
// ---------------------------------------------------------------------------
__global__ void router_kernel(const float* __restrict__ t,
                              const float* __restrict__ rw,
                              int* counts, int* toklist, float* tokw) {
    int warp = threadIdx.x >> 5;
    int lane = threadIdx.x & 31;
    int tok = blockIdx.x * 8 + warp;
    if (tok >= S_) return;
    const float* tr = t + (size_t)tok * H_;
    float logits[E_];
    for (int e = 0; e < E_; e++) {
        float s = 0.0f;
        for (int k = lane; k < H_; k += 32) s += tr[k] * rw[e * H_ + k];
        for (int o = 16; o > 0; o >>= 1) s += __shfl_xor_sync(0xffffffff, s, o);
        logits[e] = s;
    }
    if (lane == 0) {
        float mx = logits[0];
        for (int e = 1; e < E_; e++) mx = fmaxf(mx, logits[e]);
        float p[E_], sum = 0.0f;
        for (int e = 0; e < E_; e++) { p[e] = __expf(logits[e] - mx); sum += p[e]; }
        float invs = 1.0f / sum;
        for (int e = 0; e < E_; e++) p[e] *= invs;
        int b1 = 0;
        for (int e = 1; e < E_; e++) if (p[e] > p[b1]) b1 = e;
        int b2 = -1;
        for (int e = 0; e < E_; e++) {
            if (e == b1) continue;
            if (b2 < 0 || p[e] > p[b2]) b2 = e;
        }
        int pos1 = atomicAdd(&counts[b1], 1);
        toklist[b1 * S_ + pos1] = tok; tokw[b1 * S_ + pos1] = p[b1];
        int pos2 = atomicAdd(&counts[b2], 1);
        toklist[b2 * S_ + pos2] = tok; tokw[b2 * S_ + pos2] = p[b2];
    }
}

// ---------------------------------------------------------------------------
// MoE stage 1: per expert, gathered rows: a = silu(t @ Wg^T) * (t @ Wu^T)
// ---------------------------------------------------------------------------
__global__ void moe_gu_kernel(const float* __restrict__ T,
                              const float* __restrict__ ws,
                              const int* __restrict__ counts,
                              const int* __restrict__ toklist,
                              float* __restrict__ act) {
    int e = blockIdx.z;
    int cnt = counts[e];
    int m0 = blockIdx.y * 64;
    if (m0 >= cnt) return;
    int n0 = blockIdx.x * 64;
    const float* B = ws + (size_t)e * (2 * I_) * H_;

    __shared__ float As[16][65], Bg[16][65], Bu[16][65];
    __shared__ int rows[64];
    int tid = threadIdx.x;
    if (tid < 64)
        rows[tid] = (m0 + tid < cnt) ? toklist[e * S_ + m0 + tid] : -1;
    __syncthreads();

    int tx = tid & 15, ty = tid >> 4;
    float accG[4][4] = {}, accU[4][4] = {};
    for (int k0 = 0; k0 < H_; k0 += 16) {
        #pragma unroll
        for (int l = 0; l < 4; l++) {
            int idx = tid + l * 256;
            int kk = idx & 15, mm = idx >> 4;
            int r = rows[mm];
            As[kk][mm] = (r >= 0) ? T[(size_t)r * H_ + k0 + kk] : 0.0f;
            Bg[kk][mm] = B[(size_t)(n0 + mm) * H_ + k0 + kk];
            Bu[kk][mm] = B[(size_t)(I_ + n0 + mm) * H_ + k0 + kk];
        }
        __syncthreads();
        #pragma unroll
        for (int kk = 0; kk < 16; kk++) {
            float a[4], bg[4], bu[4];
            #pragma unroll
            for (int i = 0; i < 4; i++) a[i] = As[kk][ty * 4 + i];
            #pragma unroll
            for (int j = 0; j < 4; j++) { bg[j] = Bg[kk][tx * 4 + j]; bu[j] = Bu[kk][tx * 4 + j]; }
            #pragma unroll
            for (int i = 0; i < 4; i++)
                #pragma unroll
                for (int j = 0; j < 4; j++) {
                    accG[i][j] += a[i] * bg[j];
                    accU[i][j] += a[i] * bu[j];
                }
        }
        __syncthreads();
    }
    for (int i = 0; i < 4; i++) {
        int m = m0 + ty * 4 + i;
        if (m >= cnt) break;
        float* arow = act + ((size_t)e * S_ + m) * I_;
        for (int j = 0; j < 4; j++) {
            int n = n0 + tx * 4 + j;
            float g = accG[i][j], u = accU[i][j];
            arow[n] = g / (1.0f + __expf(-g)) * u;   // silu(g)*u
        }
    }
}

// ---------------------------------------------------------------------------
// MoE stage 2: y = a @ w2s[e]^T, scaled by routing weight, atomicAdd into out
// ---------------------------------------------------------------------------
__global__ void moe_y_kernel(const float* __restrict__ act,
                             const float* __restrict__ w2s,
                             const int* __restrict__ counts,
                             const int* __restrict__ toklist,
                             const float* __restrict__ tokw,
                             float* __restrict__ out) {
    int e = blockIdx.z;
    int cnt = counts[e];
    int m0 = blockIdx.y * 64;
    if (m0 >= cnt) return;
    int n0 = blockIdx.x * 64;
    const float* A = act + (size_t)e * S_ * I_;
    const float* B = w2s + (size_t)e * H_ * I_;

    __shared__ float As[16][65], Bs[16][65];
    int tid = threadIdx.x;
    int tx = tid & 15, ty = tid >> 4;
    float acc[4][4] = {};
    for (int k0 = 0; k0 < I_; k0 += 16) {
        #pragma unroll
        for (int l = 0; l < 4; l++) {
            int idx = tid + l * 256;
            int kk = idx & 15, mm = idx >> 4;
            int gm = m0 + mm;
            As[kk][mm] = (gm < cnt) ? A[(size_t)gm * I_ + k0 + kk] : 0.0f;
            Bs[kk][mm] = B[(size_t)(n0 + mm) * I_ + k0 + kk];
        }
        __syncthreads();
        #pragma unroll
        for (int kk = 0; kk < 16; kk++) {
            float a[4], b[4];
            #pragma unroll
            for (int i = 0; i < 4; i++) a[i] = As[kk][ty * 4 + i];
            #pragma unroll
            for (int j = 0; j < 4; j++) b[j] = Bs[kk][tx * 4 + j];
            #pragma unroll
            for (int i = 0; i < 4; i++)
                #pragma unroll
                for (int j = 0; j < 4; j++)
                    acc[i][j] += a[i] * b[j];
        }
        __syncthreads();
    }
    for (int i = 0; i < 4; i++) {
        int m = m0 + ty * 4 + i;
        if (m >= cnt) break;
        int tok = toklist[e * S_ + m];
        float w = tokw[e * S_ + m];
        for (int j = 0; j < 4; j++) {
            int n = n0 + tx * 4 + j;
            atomicAdd(&out[(size_t)tok * H_ + n], w * acc[i][j]);
        }
    }
}

// ---------------------------------------------------------------------------
// Launcher
// ---------------------------------------------------------------------------
extern "C" void kernel_launch(void* const* d_in, const int* in_sizes, int n_in,
                              void* d_out, int out_size) {
    const float* hidden   = (const float*)d_in[0];
    // d_in[1] = positions (unused by reference math)
    const float* w_qkv    = (const float*)d_in[2];
    const float* w_o      = (const float*)d_in[3];
    const float* router_w = (const float*)d_in[4];
    const float* ws       = (const float*)d_in[5];
    const float* w2s      = (const float*)d_in[6];
    const float* ln1      = (const float*)d_in[7];
    const float* ln2      = (const float*)d_in[8];

    float* out    = (float*)d_out;            // [0, S*H): MoE out
    float* resid2 = out + (size_t)S_ * H_;    // [S*H, 2*S*H): residual2

    float *xnorm, *qkv, *attn, *tnorm, *act, *tokw;
    int *counts, *toklist;
    cudaGetSymbolAddress((void**)&xnorm,   g_xnorm);
    cudaGetSymbolAddress((void**)&qkv,     g_qkv);
    cudaGetSymbolAddress((void**)&attn,    g_attn);
    cudaGetSymbolAddress((void**)&tnorm,   g_tnorm);
    cudaGetSymbolAddress((void**)&act,     g_act);
    cudaGetSymbolAddress((void**)&counts,  g_counts);
    cudaGetSymbolAddress((void**)&toklist, g_toklist);
    cudaGetSymbolAddress((void**)&tokw,    g_tokw);

    // 1. zero MoE output region + expert counts
    zero_kernel<<<(S_ * H_ + 255) / 256, 256>>>(out, counts);

    // 2. RMSNorm 1
    rmsnorm_kernel<<<S_, 256>>>(hidden, ln1, xnorm);

    // 3. QKV projection: [S,1536] = xnorm[S,1024] @ w_qkv[1536,1024]^T
    gemm_nt_kernel<<<dim3(QKV_O / 64, S_ / 64), 256>>>(
        xnorm, w_qkv, qkv, S_, QKV_O, H_, nullptr);

    // 4. Sliding-window attention
    attn_kernel<<<dim3(S_, NH_), 64>>>(qkv, attn);

    // 5. O projection + residual -> residual2 (written directly into d_out)
    gemm_nt_kernel<<<dim3(H_ / 64, S_ / 64), 256>>>(
        attn, w_o, resid2, S_, H_, H_, hidden);

    // 6. RMSNorm 2
    rmsnorm_kernel<<<S_, 256>>>(resid2, ln2, tnorm);

    // 7. Router + top-2 gather
    router_kernel<<<S_ / 8, 256>>>(tnorm, router_w, counts, toklist, tokw);

    // 8. MoE stage 1 (gathered SwiGLU activations)
    moe_gu_kernel<<<dim3(I_ / 64, S_ / 64, E_), 256>>>(
        tnorm, ws, counts, toklist, act);

    // 9. MoE stage 2 (down proj, weighted scatter-add)
    moe_y_kernel<<<dim3(H_ / 64, S_ / 64, E_), 256>>>(
        act, w2s, counts, toklist, tokw, out);
}

// round 2
// speedup vs baseline: 1.5945x; 1.5945x over previous
#include <cuda_runtime.h>
#include <cuda_bf16.h>
#include <math.h>

#define S_  2048
#define H_  1024
#define NH_ 16
#define NKV_ 4
#define HD_ 64
#define QKV_O 1536
#define I_  2816
#define E_  8
#define WIN_ 512
#define EPS_ 1e-5f

typedef unsigned long long u64;

__device__ __forceinline__ u64 pack2(float lo, float hi) {
    u64 r; asm("mov.b64 %0, {%1,%2};" : "=l"(r) : "f"(lo), "f"(hi)); return r;
}
__device__ __forceinline__ void unpack2(u64 v, float& lo, float& hi) {
    asm("mov.b64 {%0,%1}, %2;" : "=f"(lo), "=f"(hi) : "l"(v));
}
__device__ __forceinline__ void ffma2(u64& d, u64 a, u64 b) {
    asm("fma.rn.f32x2 %0, %1, %2, %0;" : "+l"(d) : "l"(a), "l"(b));
}

// ---------------------------------------------------------------------------
// Scratch
// ---------------------------------------------------------------------------
__device__ float g_xnorm[S_ * H_];
__device__ float g_qkv[S_ * QKV_O];
__device__ float g_attn[S_ * H_];
__device__ float g_tnorm[S_ * H_];
__device__ float g_gu[(size_t)E_ * S_ * 2 * I_];   // gate|up, silu in-place
__device__ int   g_counts[E_];
__device__ int   g_toklist[E_ * S_];
__device__ float g_tokw[E_ * S_];

// ---------------------------------------------------------------------------
__global__ void zero_kernel(float* out, int* counts) {
    int i = blockIdx.x * blockDim.x + threadIdx.x;
    if (i < S_ * H_) out[i] = 0.0f;
    if (i < E_) counts[i] = 0;
}

__global__ void rmsnorm_kernel(const float* __restrict__ x,
                               const float* __restrict__ w,
                               float* __restrict__ y) {
    int row = blockIdx.x;
    int tid = threadIdx.x;
    __shared__ float red[256];
    const float* xr = x + (size_t)row * H_;
    float s = 0.0f;
    for (int c = tid; c < H_; c += 256) { float v = xr[c]; s += v * v; }
    red[tid] = s; __syncthreads();
    for (int o = 128; o > 0; o >>= 1) {
        if (tid < o) red[tid] += red[tid + o];
        __syncthreads();
    }
    float inv = rsqrtf(red[0] / (float)H_ + EPS_);
    for (int c = tid; c < H_; c += 256)
        y[(size_t)row * H_ + c] = xr[c] * inv * w[c];
}

// ---------------------------------------------------------------------------
// Generic NT GEMM with f32x2 FMA.  C[M,N] = A[M,K] * B[N,K]^T
// 128x128 tile, BK=8, 256 threads, 8x8 per thread (pairs along M via f32x2).
// GATHER: A rows come from toklist. EPI: 0=store 1=+addsrc 2=weighted scatter
// ---------------------------------------------------------------------------
template<int GATHER, int EPI>
__global__ __launch_bounds__(256, 2)
void gemm128(const float* __restrict__ A, const float* __restrict__ B,
             float* __restrict__ C, int M, int N, int K, int lda, int ldc,
             const float* __restrict__ addsrc,
             const int* __restrict__ counts,
             const int* __restrict__ toklist,
             const float* __restrict__ tokw,
             size_t strideA, size_t strideB, size_t strideC)
{
    int e = blockIdx.z;
    int Mlim = counts ? counts[e] : M;
    int m0 = blockIdx.y * 128;
    if (m0 >= Mlim) return;
    int n0 = blockIdx.x * 128;
    const float* Ae = A + strideA * e;
    const float* Be = B + strideB * e;
    float*       Ce = C + strideC * e;

    __shared__ float As[8][128];
    __shared__ u64   Bs2[8][128];
    __shared__ int   rows[128];

    int tid = threadIdx.x;
    if (GATHER) {
        if (tid < 128)
            rows[tid] = (m0 + tid < Mlim) ? toklist[e * S_ + m0 + tid] : -1;
        __syncthreads();
    }

    int lr = tid >> 1;            // 0..127 (row within tile)
    int lq = (tid & 1) * 4;       // 0 or 4 (k quad)
    const float* arow; bool avalid;
    if (GATHER) {
        int r = rows[lr];
        avalid = (r >= 0);
        arow = Ae + (size_t)(avalid ? r : 0) * lda;
    } else {
        int gm = m0 + lr;
        avalid = (gm < Mlim);
        arow = Ae + (size_t)(avalid ? gm : 0) * lda;
    }
    const float* brow = Be + (size_t)(n0 + lr) * K;

    int tx = tid & 15, ty = tid >> 4;
    u64 acc[4][8];
    #pragma unroll
    for (int i = 0; i < 4; i++)
        #pragma unroll
        for (int j = 0; j < 8; j++) acc[i][j] = 0ull;

    for (int k0 = 0; k0 < K; k0 += 8) {
        float4 av = avalid ? *(const float4*)(arow + k0 + lq)
                           : make_float4(0.f, 0.f, 0.f, 0.f);
        float4 bv = *(const float4*)(brow + k0 + lq);
        __syncthreads();
        As[lq + 0][lr] = av.x; As[lq + 1][lr] = av.y;
        As[lq + 2][lr] = av.z; As[lq + 3][lr] = av.w;
        Bs2[lq + 0][lr] = pack2(bv.x, bv.x);
        Bs2[lq + 1][lr] = pack2(bv.y, bv.y);
        Bs2[lq + 2][lr] = pack2(bv.z, bv.z);
        Bs2[lq + 3][lr] = pack2(bv.w, bv.w);
        __syncthreads();
        #pragma unroll
        for (int kk = 0; kk < 8; kk++) {
            u64 aa[4], bb[8];
            #pragma unroll
            for (int i = 0; i < 4; i++)
                aa[i] = *(const u64*)&As[kk][ty * 8 + 2 * i];
            #pragma unroll
            for (int j = 0; j < 8; j++)
                bb[j] = Bs2[kk][tx + 16 * j];
            #pragma unroll
            for (int i = 0; i < 4; i++)
                #pragma unroll
                for (int j = 0; j < 8; j++)
                    ffma2(acc[i][j], aa[i], bb[j]);
        }
    }

    #pragma unroll
    for (int i = 0; i < 4; i++) {
        int mA = m0 + ty * 8 + 2 * i;
        int mB = mA + 1;
        int tokA = 0, tokB = 0; float wA = 0.f, wB = 0.f;
        if (EPI == 2) {
            if (mA < Mlim) { tokA = toklist[e * S_ + mA]; wA = tokw[e * S_ + mA]; }
            if (mB < Mlim) { tokB = toklist[e * S_ + mB]; wB = tokw[e * S_ + mB]; }
        }
        #pragma unroll
        for (int j = 0; j < 8; j++) {
            int n = n0 + tx + 16 * j;
            float lo, hi; unpack2(acc[i][j], lo, hi);
            if (EPI == 0) {
                if (mA < Mlim) Ce[(size_t)mA * ldc + n] = lo;
                if (mB < Mlim) Ce[(size_t)mB * ldc + n] = hi;
            } else if (EPI == 1) {
                Ce[(size_t)mA * ldc + n] = lo + addsrc[(size_t)mA * ldc + n];
                Ce[(size_t)mB * ldc + n] = hi + addsrc[(size_t)mB * ldc + n];
            } else {
                if (mA < Mlim) atomicAdd(&C[(size_t)tokA * H_ + n], wA * lo);
                if (mB < Mlim) atomicAdd(&C[(size_t)tokB * H_ + n], wB * hi);
            }
        }
    }
}

// ---------------------------------------------------------------------------
// Flash attention: block = (64-query tile, head). 256 threads.
// Dynamic smem: Qs[64][64], KPs[64][68] (K tile aliased with P), Vs[64][64]
// ---------------------------------------------------------------------------
__global__ __launch_bounds__(256)
void attn_flash(const float* __restrict__ qkv, float* __restrict__ out) {
    extern __shared__ float sm[];
    float* Qs  = sm;                  // [64][64]
    float* KPs = sm + 64 * 64;        // [64][68]
    float* Vs  = sm + 64 * 64 + 64 * 68; // [64][64]

    int qt = blockIdx.x, h = blockIdx.y;
    int q0 = qt * 64;
    int kvh = h >> 2;
    int tid = threadIdx.x;
    int tx = tid & 15, ty = tid >> 4;

    // load Q tile
    #pragma unroll
    for (int l = 0; l < 4; l++) {
        int idx = tid + l * 256;
        int r = idx >> 4, dq = (idx & 15) * 4;
        *(float4*)&Qs[r * 64 + dq] =
            *(const float4*)&qkv[(size_t)(q0 + r) * QKV_O + h * 64 + dq];
    }

    float acc[4][4] = {};
    float rm[4], rl[4];
    #pragma unroll
    for (int i = 0; i < 4; i++) { rm[i] = -1e30f; rl[i] = 0.f; }

    int t0 = (q0 > 511) ? ((q0 - 511) >> 6) : 0;
    for (int kt = t0; kt <= qt; kt++) {
        int j0 = kt * 64;
        __syncthreads();   // protect prior-tile P/V reads
        #pragma unroll
        for (int l = 0; l < 4; l++) {
            int idx = tid + l * 256;
            int r = idx >> 4, dq = (idx & 15) * 4;
            *(float4*)&KPs[r * 68 + dq] =
                *(const float4*)&qkv[(size_t)(j0 + r) * QKV_O + H_ + kvh * 64 + dq];
            *(float4*)&Vs[r * 64 + dq] =
                *(const float4*)&qkv[(size_t)(j0 + r) * QKV_O + H_ + NKV_ * HD_ + kvh * 64 + dq];
        }
        __syncthreads();

        // S = Q K^T
        float s[4][4] = {};
        #pragma unroll
        for (int d0 = 0; d0 < 64; d0 += 4) {
            float4 q4[4], k4[4];
            #pragma unroll
            for (int i = 0; i < 4; i++) q4[i] = *(const float4*)&Qs[(ty * 4 + i) * 64 + d0];
            #pragma unroll
            for (int j = 0; j < 4; j++) k4[j] = *(const float4*)&KPs[(tx + 16 * j) * 68 + d0];
            #pragma unroll
            for (int i = 0; i < 4; i++)
                #pragma unroll
                for (int j = 0; j < 4; j++) {
                    s[i][j] += q4[i].x * k4[j].x + q4[i].y * k4[j].y
                             + q4[i].z * k4[j].z + q4[i].w * k4[j].w;
                }
        }
        __syncthreads();   // all K reads done before P overwrites

        // mask + online softmax
        float p[4][4];
        #pragma unroll
        for (int i = 0; i < 4; i++) {
            int iq = q0 + ty * 4 + i;
            float tm = -1e30f;
            #pragma unroll
            for (int j = 0; j < 4; j++) {
                int jk = j0 + tx + 16 * j;
                bool ok = (jk <= iq) && (iq - jk < WIN_);
                s[i][j] = ok ? s[i][j] * 0.125f : -1e30f;
                tm = fmaxf(tm, s[i][j]);
            }
            #pragma unroll
            for (int o = 1; o < 16; o <<= 1)
                tm = fmaxf(tm, __shfl_xor_sync(0xffffffffu, tm, o));
            float mn = fmaxf(rm[i], tm);
            float alpha = __expf(rm[i] - mn);
            rm[i] = mn;
            float ps = 0.f;
            #pragma unroll
            for (int j = 0; j < 4; j++) { p[i][j] = __expf(s[i][j] - mn); ps += p[i][j]; }
            #pragma unroll
            for (int o = 1; o < 16; o <<= 1)
                ps += __shfl_xor_sync(0xffffffffu, ps, o);
            rl[i] = rl[i] * alpha + ps;
            #pragma unroll
            for (int j = 0; j < 4; j++) acc[i][j] *= alpha;
            // store P (aliases K buffer)
            #pragma unroll
            for (int j = 0; j < 4; j++)
                KPs[(ty * 4 + i) * 68 + tx + 16 * j] = p[i][j];
        }
        __syncthreads();

        // O += P V
        #pragma unroll 4
        for (int n = 0; n < 64; n++) {
            float pv[4], vv[4];
            #pragma unroll
            for (int i = 0; i < 4; i++) pv[i] = KPs[(ty * 4 + i) * 68 + n];
            #pragma unroll
            for (int j = 0; j < 4; j++) vv[j] = Vs[n * 64 + tx + 16 * j];
            #pragma unroll
            for (int i = 0; i < 4; i++)
                #pragma unroll
                for (int j = 0; j < 4; j++)
                    acc[i][j] += pv[i] * vv[j];
        }
    }

    #pragma unroll
    for (int i = 0; i < 4; i++) {
        float inv = 1.0f / rl[i];
        #pragma unroll
        for (int j = 0; j < 4; j++)
            out[(size_t)(q0 + ty * 4 + i) * H_ + h * 64 + tx + 16 * j] = acc[i][j] * inv;
    }
}

// ---------------------------------------------------------------------------
__global__ void router_kernel(const float* __restrict__ t,
                              const float* __restrict__ rw,
                              int* counts, int* toklist, float* tokw) {
    int warp = threadIdx.x >> 5;
    int lane = threadIdx.x & 31;
    int tok = blockIdx.x * 8 + warp;
    if (tok >= S_) return;
    const float* tr = t + (size_t)tok * H_;
    float logits[E_];
    for (int e = 0; e < E_; e++) {
        float s = 0.0f;
        for (int k = lane; k < H_; k += 32) s += tr[k] * rw[e * H_ + k];
        for (int o = 16; o > 0; o >>= 1) s += __shfl_xor_sync(0xffffffff, s, o);
        logits[e] = s;
    }
    if (lane == 0) {
        float mx = logits[0];
        for (int e = 1; e < E_; e++) mx = fmaxf(mx, logits[e]);
        float p[E_], sum = 0.0f;
        for (int e = 0; e < E_; e++) { p[e] = __expf(logits[e] - mx); sum += p[e]; }
        float invs = 1.0f / sum;
        for (int e = 0; e < E_; e++) p[e] *= invs;
        int b1 = 0;
        for (int e = 1; e < E_; e++) if (p[e] > p[b1]) b1 = e;
        int b2 = -1;
        for (int e = 0; e < E_; e++) {
            if (e == b1) continue;
            if (b2 < 0 || p[e] > p[b2]) b2 = e;
        }
        int pos1 = atomicAdd(&counts[b1], 1);
        toklist[b1 * S_ + pos1] = tok; tokw[b1 * S_ + pos1] = p[b1];
        int pos2 = atomicAdd(&counts[b2], 1);
        toklist[b2 * S_ + pos2] = tok; tokw[b2 * S_ + pos2] = p[b2];
    }
}

// silu(g)*u in-place into gate half of gu
__global__ void silu_kernel(float* __restrict__ gu, const int* __restrict__ counts) {
    int e = blockIdx.z, m = blockIdx.y;
    if (m >= counts[e]) return;
    int i = blockIdx.x * 256 + threadIdx.x;
    float* row = gu + ((size_t)e * S_ + m) * (2 * I_);
    float g = row[i], u = row[I_ + i];
    row[i] = g / (1.0f + __expf(-g)) * u;
}

// ---------------------------------------------------------------------------
extern "C" void kernel_launch(void* const* d_in, const int* in_sizes, int n_in,
                              void* d_out, int out_size) {
    const float* hidden   = (const float*)d_in[0];
    const float* w_qkv    = (const float*)d_in[2];
    const float* w_o      = (const float*)d_in[3];
    const float* router_w = (const float*)d_in[4];
    const float* ws       = (const float*)d_in[5];
    const float* w2s      = (const float*)d_in[6];
    const float* ln1      = (const float*)d_in[7];
    const float* ln2      = (const float*)d_in[8];

    float* out    = (float*)d_out;
    float* resid2 = out + (size_t)S_ * H_;

    float *xnorm, *qkv, *attn, *tnorm, *gu, *tokw;
    int *counts, *toklist;
    cudaGetSymbolAddress((void**)&xnorm,   g_xnorm);
    cudaGetSymbolAddress((void**)&qkv,     g_qkv);
    cudaGetSymbolAddress((void**)&attn,    g_attn);
    cudaGetSymbolAddress((void**)&tnorm,   g_tnorm);
    cudaGetSymbolAddress((void**)&gu,      g_gu);
    cudaGetSymbolAddress((void**)&counts,  g_counts);
    cudaGetSymbolAddress((void**)&toklist, g_toklist);
    cudaGetSymbolAddress((void**)&tokw,    g_tokw);

    int attn_smem = (64 * 64 + 64 * 68 + 64 * 64) * 4;  // 50176 B
    cudaFuncSetAttribute(attn_flash, cudaFuncAttributeMaxDynamicSharedMemorySize,
                         attn_smem);

    zero_kernel<<<(S_ * H_ + 255) / 256, 256>>>(out, counts);
    rmsnorm_kernel<<<S_, 256>>>(hidden, ln1, xnorm);

    // QKV: [2048,1536] = xnorm @ w_qkv^T
    gemm128<0, 0><<<dim3(QKV_O / 128, S_ / 128, 1), 256>>>(
        xnorm, w_qkv, qkv, S_, QKV_O, H_, H_, QKV_O,
        nullptr, nullptr, nullptr, nullptr, 0, 0, 0);

    attn_flash<<<dim3(S_ / 64, NH_), 256, attn_smem>>>(qkv, attn);

    // O proj + residual
    gemm128<0, 1><<<dim3(H_ / 128, S_ / 128, 1), 256>>>(
        attn, w_o, resid2, S_, H_, H_, H_, H_,
        hidden, nullptr, nullptr, nullptr, 0, 0, 0);

    rmsnorm_kernel<<<S_, 256>>>(resid2, ln2, tnorm);
    router_kernel<<<S_ / 8, 256>>>(tnorm, router_w, counts, toklist, tokw);

    // MoE up+gate: per expert, gathered A, N = 2*I
    gemm128<1, 0><<<dim3(2 * I_ / 128, S_ / 128, E_), 256>>>(
        tnorm, ws, gu, S_, 2 * I_, H_, H_, 2 * I_,
        nullptr, counts, toklist, nullptr,
        0, (size_t)2 * I_ * H_, (size_t)S_ * 2 * I_);

    silu_kernel<<<dim3(I_ / 256, S_, E_), 256>>>(gu, counts);

    // MoE down: A = gu (lda = 2I), weighted scatter into out
    gemm128<0, 2><<<dim3(H_ / 128, S_ / 128, E_), 256>>>(
        gu, w2s, out, S_, H_, I_, 2 * I_, H_,
        nullptr, counts, toklist, tokw,
        (size_t)S_ * 2 * I_, (size_t)H_ * I_, 0);
}

// round 4
// speedup vs baseline: 1.7216x; 1.0797x over previous
#include <cuda_runtime.h>
#include <cuda_bf16.h>
#include <math.h>
#include <stdint.h>

#define S_  2048
#define H_  1024
#define NH_ 16
#define NKV_ 4
#define HD_ 64
#define QKV_O 1536
#define I_  2816
#define E_  8
#define WIN_ 512
#define EPS_ 1e-5f

// ---------------------------------------------------------------------------
// Scratch
// ---------------------------------------------------------------------------
__device__ float g_xnorm[S_ * H_];
__device__ float g_qkv[S_ * QKV_O];
__device__ float g_attn[S_ * H_];
__device__ float g_tnorm[S_ * H_];
__device__ float g_gu[(size_t)E_ * S_ * 2 * I_];
__device__ int   g_counts[E_];
__device__ int   g_toklist[E_ * S_];
__device__ float g_tokw[E_ * S_];

// ---------------------------------------------------------------------------
__device__ __forceinline__ uint32_t smem_u32(const void* p) {
    uint32_t a;
    asm("{ .reg .u64 t; cvta.to.shared.u64 t, %1; cvt.u32.u64 %0, t; }"
        : "=r"(a) : "l"(p));
    return a;
}
__device__ __forceinline__ void ldm4(uint32_t& r0, uint32_t& r1,
                                     uint32_t& r2, uint32_t& r3, uint32_t addr) {
    asm volatile("ldmatrix.sync.aligned.m8n8.x4.shared.b16 {%0,%1,%2,%3}, [%4];"
                 : "=r"(r0), "=r"(r1), "=r"(r2), "=r"(r3) : "r"(addr));
}
__device__ __forceinline__ void mma16816(float* d, const uint32_t* a,
                                         const uint32_t* b) {
    asm volatile(
        "mma.sync.aligned.m16n8k16.row.col.f32.bf16.bf16.f32 "
        "{%0,%1,%2,%3}, {%4,%5,%6,%7}, {%8,%9}, {%0,%1,%2,%3};"
        : "+f"(d[0]), "+f"(d[1]), "+f"(d[2]), "+f"(d[3])
        : "r"(a[0]), "r"(a[1]), "r"(a[2]), "r"(a[3]), "r"(b[0]), "r"(b[1]));
}

// split fp32 float4 -> bf16 hi/lo (each 8 bytes)
__device__ __forceinline__ void store_split4(char* hp, char* lp, float4 v) {
    __nv_bfloat162 h01 = __floats2bfloat162_rn(v.x, v.y);
    __nv_bfloat162 h23 = __floats2bfloat162_rn(v.z, v.w);
    float2 f01 = __bfloat1622float2(h01);
    float2 f23 = __bfloat1622float2(h23);
    __nv_bfloat162 l01 = __floats2bfloat162_rn(v.x - f01.x, v.y - f01.y);
    __nv_bfloat162 l23 = __floats2bfloat162_rn(v.z - f23.x, v.w - f23.y);
    *(uint2*)hp = make_uint2(*(uint32_t*)&h01, *(uint32_t*)&h23);
    *(uint2*)lp = make_uint2(*(uint32_t*)&l01, *(uint32_t*)&l23);
}

// ---------------------------------------------------------------------------
// HMMA GEMM: C[M,N] = A[M,K] * B[N,K]^T with 3-term bf16 split (fp32 acc)
// CTA tile 128x128, BK=32, 8 warps (2x4), warp tile 64x32.
// Smem: A/B tiles as bf16 [128 rows][32 cols] = 64B rows, 4x16B chunks,
// chunk swizzle: phys = chunk ^ (row & 3) -> conflict-free ldmatrix.
// GATHER: A rows via toklist. EPI: 0=store 1=+addsrc 2=weighted scatter.
// FSILU: A element = silu(g)*u with u at col +I_.
// ---------------------------------------------------------------------------
template<int GATHER, int EPI, int FSILU>
__global__ __launch_bounds__(256)
void hmma_gemm(const float* __restrict__ A, const float* __restrict__ B,
               float* __restrict__ C, int M, int N, int K, int lda, int ldc,
               const float* __restrict__ addsrc,
               const int* __restrict__ counts,
               const int* __restrict__ toklist,
               const float* __restrict__ tokw,
               size_t sA, size_t sB, size_t sC)
{
    __shared__ __align__(128) char smA[2 * 128 * 64];   // hi | lo
    __shared__ __align__(128) char smB[2 * 128 * 64];
    __shared__ int rowsS[128];

    int e = blockIdx.z;
    int Mlim = counts ? counts[e] : M;
    int m0 = blockIdx.y * 128;
    if (m0 >= Mlim) return;
    int n0 = blockIdx.x * 128;
    const float* Ae = A + sA * e;
    const float* Be = B + sB * e;
    float*       Ce = C + sC * e;

    int tid = threadIdx.x;
    int wid = tid >> 5;
    int lane = tid & 31;
    int warp_m = wid & 1;          // 2 warps along M
    int warp_n = wid >> 1;         // 4 warps along N

    if (GATHER && tid < 128)
        rowsS[tid] = (m0 + tid < Mlim) ? toklist[e * S_ + m0 + tid] : -1;
    if (GATHER) __syncthreads();

    uint32_t baseAh = smem_u32(smA);
    uint32_t baseAl = baseAh + 8192;
    uint32_t baseBh = smem_u32(smB);
    uint32_t baseBl = baseBh + 8192;

    float acc[4][4][4] = {};    // [mf][nf][reg]

    // per-thread global load coords (4 float4 each for A and B per chunk)
    // idx = tid + l*256 : row = idx>>3, c4 = (idx&7)*4
    const int nchunks = K / 32;
    for (int c = 0; c < nchunks; c++) {
        int k0 = c * 32;
        __syncthreads();
        #pragma unroll
        for (int l = 0; l < 4; l++) {
            int idx = tid + l * 256;
            int row = idx >> 3;
            int c4 = (idx & 7) * 4;
            int byteoff = c4 * 2;
            int sw = row * 64 + ((((byteoff >> 4) ^ (row & 3)) << 4) | (byteoff & 8));

            float4 av;
            if (GATHER) {
                int r = rowsS[row];
                av = (r >= 0) ? *(const float4*)(Ae + (size_t)r * lda + k0 + c4)
                              : make_float4(0.f, 0.f, 0.f, 0.f);
            } else if (FSILU) {
                int gm = m0 + row;
                if (gm < Mlim) {
                    const float* ar = Ae + (size_t)gm * lda + k0 + c4;
                    float4 g = *(const float4*)ar;
                    float4 u = *(const float4*)(ar + I_);
                    av.x = g.x / (1.f + __expf(-g.x)) * u.x;
                    av.y = g.y / (1.f + __expf(-g.y)) * u.y;
                    av.z = g.z / (1.f + __expf(-g.z)) * u.z;
                    av.w = g.w / (1.f + __expf(-g.w)) * u.w;
                } else av = make_float4(0.f, 0.f, 0.f, 0.f);
            } else {
                int gm = m0 + row;
                av = (gm < Mlim) ? *(const float4*)(Ae + (size_t)gm * lda + k0 + c4)
                                 : make_float4(0.f, 0.f, 0.f, 0.f);
            }
            float4 bv = *(const float4*)(Be + (size_t)(n0 + row) * K + k0 + c4);
            store_split4(smA + sw, smA + 8192 + sw, av);
            store_split4(smB + sw, smB + 8192 + sw, bv);
        }
        __syncthreads();

        #pragma unroll
        for (int ks = 0; ks < 2; ks++) {
            // B fragments: 4 nfrags (hi & lo), via 2 ldmatrix.x4 each
            uint32_t bh[4][2], bl[4][2];
            #pragma unroll
            for (int nfp = 0; nfp < 2; nfp++) {
                int mi = lane >> 3, r = lane & 7;
                int n = warp_n * 32 + nfp * 16 + ((mi >> 1) << 3) + r;
                int chunk = ks * 2 + (mi & 1);
                uint32_t off = (uint32_t)(n * 64 + ((chunk ^ (n & 3)) << 4));
                uint32_t r0, r1, r2, r3;
                ldm4(r0, r1, r2, r3, baseBh + off);
                bh[nfp * 2 + 0][0] = r0; bh[nfp * 2 + 0][1] = r1;
                bh[nfp * 2 + 1][0] = r2; bh[nfp * 2 + 1][1] = r3;
                ldm4(r0, r1, r2, r3, baseBl + off);
                bl[nfp * 2 + 0][0] = r0; bl[nfp * 2 + 0][1] = r1;
                bl[nfp * 2 + 1][0] = r2; bl[nfp * 2 + 1][1] = r3;
            }
            #pragma unroll
            for (int mf = 0; mf < 4; mf++) {
                int mi = lane >> 3, r = lane & 7;
                int row = warp_m * 64 + mf * 16 + ((mi & 1) << 3) + r;
                int chunk = ks * 2 + (mi >> 1);
                uint32_t off = (uint32_t)(row * 64 + ((chunk ^ (row & 3)) << 4));
                uint32_t ah[4], al[4];
                ldm4(ah[0], ah[1], ah[2], ah[3], baseAh + off);
                ldm4(al[0], al[1], al[2], al[3], baseAl + off);
                #pragma unroll
                for (int nf = 0; nf < 4; nf++) {
                    mma16816(acc[mf][nf], ah, bh[nf]);
                    mma16816(acc[mf][nf], al, bh[nf]);
                    mma16816(acc[mf][nf], ah, bl[nf]);
                }
            }
        }
    }

    // ---------------- epilogue ----------------
    int lr = lane >> 2;            // 0..7
    int lc = (lane & 3) * 2;       // 0,2,4,6
    #pragma unroll
    for (int mf = 0; mf < 4; mf++) {
        int r0g = m0 + warp_m * 64 + mf * 16 + lr;
        int r1g = r0g + 8;
        if (EPI == 2) {
            int tokA = 0, tokB = 0; float wA = 0.f, wB = 0.f;
            bool vA = (r0g < Mlim), vB = (r1g < Mlim);
            if (vA) { tokA = toklist[e * S_ + r0g]; wA = tokw[e * S_ + r0g]; }
            if (vB) { tokB = toklist[e * S_ + r1g]; wB = tokw[e * S_ + r1g]; }
            #pragma unroll
            for (int nf = 0; nf < 4; nf++) {
                int col = n0 + warp_n * 32 + nf * 8 + lc;
                if (vA) {
                    atomicAdd(&C[(size_t)tokA * H_ + col],     wA * acc[mf][nf][0]);
                    atomicAdd(&C[(size_t)tokA * H_ + col + 1], wA * acc[mf][nf][1]);
                }
                if (vB) {
                    atomicAdd(&C[(size_t)tokB * H_ + col],     wB * acc[mf][nf][2]);
                    atomicAdd(&C[(size_t)tokB * H_ + col + 1], wB * acc[mf][nf][3]);
                }
            }
        } else {
            #pragma unroll
            for (int nf = 0; nf < 4; nf++) {
                int col = n0 + warp_n * 32 + nf * 8 + lc;
                if (r0g < Mlim) {
                    float2 v = make_float2(acc[mf][nf][0], acc[mf][nf][1]);
                    if (EPI == 1) {
                        const float* a2 = addsrc + (size_t)r0g * ldc + col;
                        v.x += a2[0]; v.y += a2[1];
                    }
                    *(float2*)(Ce + (size_t)r0g * ldc + col) = v;
                }
                if (r1g < Mlim) {
                    float2 v = make_float2(acc[mf][nf][2], acc[mf][nf][3]);
                    if (EPI == 1) {
                        const float* a2 = addsrc + (size_t)r1g * ldc + col;
                        v.x += a2[0]; v.y += a2[1];
                    }
                    *(float2*)(Ce + (size_t)r1g * ldc + col) = v;
                }
            }
        }
    }
}

// ---------------------------------------------------------------------------
__global__ void zero_kernel(float* out, int* counts) {
    int i = blockIdx.x * blockDim.x + threadIdx.x;
    if (i < S_ * H_) out[i] = 0.0f;
    if (i < E_) counts[i] = 0;
}

__global__ void rmsnorm_kernel(const float* __restrict__ x,
                               const float* __restrict__ w,
                               float* __restrict__ y) {
    int row = blockIdx.x;
    int tid = threadIdx.x;
    __shared__ float red[256];
    const float* xr = x + (size_t)row * H_;
    float s = 0.0f;
    for (int c = tid; c < H_; c += 256) { float v = xr[c]; s += v * v; }
    red[tid] = s; __syncthreads();
    for (int o = 128; o > 0; o >>= 1) {
        if (tid < o) red[tid] += red[tid + o];
        __syncthreads();
    }
    float inv = rsqrtf(red[0] / (float)H_ + EPS_);
    for (int c = tid; c < H_; c += 256)
        y[(size_t)row * H_ + c] = xr[c] * inv * w[c];
}

// ---------------------------------------------------------------------------
// Flash attention (fp32) — unchanged from R2 (168us)
// ---------------------------------------------------------------------------
__global__ __launch_bounds__(256)
void attn_flash(const float* __restrict__ qkv, float* __restrict__ out) {
    extern __shared__ float smf[];
    float* Qs  = smf;
    float* KPs = smf + 64 * 64;
    float* Vs  = smf + 64 * 64 + 64 * 68;

    int qt = blockIdx.x, h = blockIdx.y;
    int q0 = qt * 64;
    int kvh = h >> 2;
    int tid = threadIdx.x;
    int tx = tid & 15, ty = tid >> 4;

    #pragma unroll
    for (int l = 0; l < 4; l++) {
        int idx = tid + l * 256;
        int r = idx >> 4, dq = (idx & 15) * 4;
        *(float4*)&Qs[r * 64 + dq] =
            *(const float4*)&qkv[(size_t)(q0 + r) * QKV_O + h * 64 + dq];
    }

    float acc[4][4] = {};
    float rm[4], rl[4];
    #pragma unroll
    for (int i = 0; i < 4; i++) { rm[i] = -1e30f; rl[i] = 0.f; }

    int t0 = (q0 > 511) ? ((q0 - 511) >> 6) : 0;
    for (int kt = t0; kt <= qt; kt++) {
        int j0 = kt * 64;
        __syncthreads();
        #pragma unroll
        for (int l = 0; l < 4; l++) {
            int idx = tid + l * 256;
            int r = idx >> 4, dq = (idx & 15) * 4;
            *(float4*)&KPs[r * 68 + dq] =
                *(const float4*)&qkv[(size_t)(j0 + r) * QKV_O + H_ + kvh * 64 + dq];
            *(float4*)&Vs[r * 64 + dq] =
                *(const float4*)&qkv[(size_t)(j0 + r) * QKV_O + H_ + NKV_ * HD_ + kvh * 64 + dq];
        }
        __syncthreads();

        float s[4][4] = {};
        #pragma unroll
        for (int d0 = 0; d0 < 64; d0 += 4) {
            float4 q4[4], k4[4];
            #pragma unroll
            for (int i = 0; i < 4; i++) q4[i] = *(const float4*)&Qs[(ty * 4 + i) * 64 + d0];
            #pragma unroll
            for (int j = 0; j < 4; j++) k4[j] = *(const float4*)&KPs[(tx + 16 * j) * 68 + d0];
            #pragma unroll
            for (int i = 0; i < 4; i++)
                #pragma unroll
                for (int j = 0; j < 4; j++)
                    s[i][j] += q4[i].x * k4[j].x + q4[i].y * k4[j].y
                             + q4[i].z * k4[j].z + q4[i].w * k4[j].w;
        }
        __syncthreads();

        float p[4][4];
        #pragma unroll
        for (int i = 0; i < 4; i++) {
            int iq = q0 + ty * 4 + i;
            float tm = -1e30f;
            #pragma unroll
            for (int j = 0; j < 4; j++) {
                int jk = j0 + tx + 16 * j;
                bool ok = (jk <= iq) && (iq - jk < WIN_);
                s[i][j] = ok ? s[i][j] * 0.125f : -1e30f;
                tm = fmaxf(tm, s[i][j]);
            }
            #pragma unroll
            for (int o = 1; o < 16; o <<= 1)
                tm = fmaxf(tm, __shfl_xor_sync(0xffffffffu, tm, o));
            float mn = fmaxf(rm[i], tm);
            float alpha = __expf(rm[i] - mn);
            rm[i] = mn;
            float ps = 0.f;
            #pragma unroll
            for (int j = 0; j < 4; j++) { p[i][j] = __expf(s[i][j] - mn); ps += p[i][j]; }
            #pragma unroll
            for (int o = 1; o < 16; o <<= 1)
                ps += __shfl_xor_sync(0xffffffffu, ps, o);
            rl[i] = rl[i] * alpha + ps;
            #pragma unroll
            for (int j = 0; j < 4; j++) acc[i][j] *= alpha;
            #pragma unroll
            for (int j = 0; j < 4; j++)
                KPs[(ty * 4 + i) * 68 + tx + 16 * j] = p[i][j];
        }
        __syncthreads();

        #pragma unroll 4
        for (int n = 0; n < 64; n++) {
            float pv[4], vv[4];
            #pragma unroll
            for (int i = 0; i < 4; i++) pv[i] = KPs[(ty * 4 + i) * 68 + n];
            #pragma unroll
            for (int j = 0; j < 4; j++) vv[j] = Vs[n * 64 + tx + 16 * j];
            #pragma unroll
            for (int i = 0; i < 4; i++)
                #pragma unroll
                for (int j = 0; j < 4; j++)
                    acc[i][j] += pv[i] * vv[j];
        }
    }

    #pragma unroll
    for (int i = 0; i < 4; i++) {
        float inv = 1.0f / rl[i];
        #pragma unroll
        for (int j = 0; j < 4; j++)
            out[(size_t)(q0 + ty * 4 + i) * H_ + h * 64 + tx + 16 * j] = acc[i][j] * inv;
    }
}

// ---------------------------------------------------------------------------
__global__ void router_kernel(const float* __restrict__ t,
                              const float* __restrict__ rw,
                              int* counts, int* toklist, float* tokw) {
    int warp = threadIdx.x >> 5;
    int lane = threadIdx.x & 31;
    int tok = blockIdx.x * 8 + warp;
    if (tok >= S_) return;
    const float* tr = t + (size_t)tok * H_;
    float logits[E_];
    for (int e = 0; e < E_; e++) {
        float s = 0.0f;
        for (int k = lane; k < H_; k += 32) s += tr[k] * rw[e * H_ + k];
        for (int o = 16; o > 0; o >>= 1) s += __shfl_xor_sync(0xffffffff, s, o);
        logits[e] = s;
    }
    if (lane == 0) {
        float mx = logits[0];
        for (int e = 1; e < E_; e++) mx = fmaxf(mx, logits[e]);
        float p[E_], sum = 0.0f;
        for (int e = 0; e < E_; e++) { p[e] = __expf(logits[e] - mx); sum += p[e]; }
        float invs = 1.0f / sum;
        for (int e = 0; e < E_; e++) p[e] *= invs;
        int b1 = 0;
        for (int e = 1; e < E_; e++) if (p[e] > p[b1]) b1 = e;
        int b2 = -1;
        for (int e = 0; e < E_; e++) {
            if (e == b1) continue;
            if (b2 < 0 || p[e] > p[b2]) b2 = e;
        }
        int pos1 = atomicAdd(&counts[b1], 1);
        toklist[b1 * S_ + pos1] = tok; tokw[b1 * S_ + pos1] = p[b1];
        int pos2 = atomicAdd(&counts[b2], 1);
        toklist[b2 * S_ + pos2] = tok; tokw[b2 * S_ + pos2] = p[b2];
    }
}

// ---------------------------------------------------------------------------
extern "C" void kernel_launch(void* const* d_in, const int* in_sizes, int n_in,
                              void* d_out, int out_size) {
    const float* hidden   = (const float*)d_in[0];
    const float* w_qkv    = (const float*)d_in[2];
    const float* w_o      = (const float*)d_in[3];
    const float* router_w = (const float*)d_in[4];
    const float* ws       = (const float*)d_in[5];
    const float* w2s      = (const float*)d_in[6];
    const float* ln1      = (const float*)d_in[7];
    const float* ln2      = (const float*)d_in[8];

    float* out    = (float*)d_out;
    float* resid2 = out + (size_t)S_ * H_;

    float *xnorm, *qkv, *attn, *tnorm, *gu, *tokw;
    int *counts, *toklist;
    cudaGetSymbolAddress((void**)&xnorm,   g_xnorm);
    cudaGetSymbolAddress((void**)&qkv,     g_qkv);
    cudaGetSymbolAddress((void**)&attn,    g_attn);
    cudaGetSymbolAddress((void**)&tnorm,   g_tnorm);
    cudaGetSymbolAddress((void**)&gu,      g_gu);
    cudaGetSymbolAddress((void**)&counts,  g_counts);
    cudaGetSymbolAddress((void**)&toklist, g_toklist);
    cudaGetSymbolAddress((void**)&tokw,    g_tokw);

    int attn_smem = (64 * 64 + 64 * 68 + 64 * 64) * 4;
    cudaFuncSetAttribute(attn_flash, cudaFuncAttributeMaxDynamicSharedMemorySize, attn_smem);

    zero_kernel<<<(S_ * H_ + 255) / 256, 256>>>(out, counts);
    rmsnorm_kernel<<<S_, 256>>>(hidden, ln1, xnorm);

    // QKV: [2048,1536]
    hmma_gemm<0,0,0><<<dim3(QKV_O / 128, S_ / 128, 1), 256>>>(
        xnorm, w_qkv, qkv, S_, QKV_O, H_, H_, QKV_O,
        nullptr, nullptr, nullptr, nullptr, 0, 0, 0);

    attn_flash<<<dim3(S_ / 64, NH_), 256, attn_smem>>>(qkv, attn);

    // O proj + residual
    hmma_gemm<0,1,0><<<dim3(H_ / 128, S_ / 128, 1), 256>>>(
        attn, w_o, resid2, S_, H_, H_, H_, H_,
        hidden, nullptr, nullptr, nullptr, 0, 0, 0);

    rmsnorm_kernel<<<S_, 256>>>(resid2, ln2, tnorm);
    router_kernel<<<S_ / 8, 256>>>(tnorm, router_w, counts, toklist, tokw);

    // MoE up+gate (gathered rows, N = 2*I)
    hmma_gemm<1,0,0><<<dim3(2 * I_ / 128, S_ / 128, E_), 256>>>(
        tnorm, ws, gu, S_, 2 * I_, H_, H_, 2 * I_,
        nullptr, counts, toklist, nullptr,
        0, (size_t)2 * I_ * H_, (size_t)S_ * 2 * I_);

    // MoE down (silu fused into A load, weighted atomic scatter)
    hmma_gemm<0,2,1><<<dim3(H_ / 128, S_ / 128, E_), 256>>>(
        gu, w2s, out, S_, H_, I_, 2 * I_, H_,
        nullptr, counts, toklist, tokw,
        (size_t)S_ * 2 * I_, (size_t)H_ * I_, 0);
}

// round 5
// speedup vs baseline: 4.2267x; 2.4551x over previous
#include <cuda_runtime.h>
#include <cuda_bf16.h>
#include <math.h>
#include <stdint.h>

#define S_  2048
#define H_  1024
#define NH_ 16
#define NKV_ 4
#define HD_ 64
#define QKV_O 1536
#define I_  2816
#define E_  8
#define WIN_ 512
#define EPS_ 1e-5f

typedef __nv_bfloat16 bf16;

// ---------------------------------------------------------------------------
// Scratch (static device globals)
// ---------------------------------------------------------------------------
__device__ bf16 g_wqkv_h[QKV_O * H_],            g_wqkv_l[QKV_O * H_];
__device__ bf16 g_wo_h[H_ * H_],                 g_wo_l[H_ * H_];
__device__ bf16 g_ws_h[(size_t)E_ * 2 * I_ * H_], g_ws_l[(size_t)E_ * 2 * I_ * H_];
__device__ bf16 g_w2s_h[(size_t)E_ * H_ * I_],    g_w2s_l[(size_t)E_ * H_ * I_];
__device__ bf16 g_xn_h[S_ * H_],  g_xn_l[S_ * H_];
__device__ bf16 g_at_h[S_ * H_],  g_at_l[S_ * H_];
__device__ bf16 g_tn_h[S_ * H_],  g_tn_l[S_ * H_];
__device__ bf16 g_act_h[(size_t)E_ * S_ * I_],    g_act_l[(size_t)E_ * S_ * I_];
__device__ float g_qkv[S_ * QKV_O];
__device__ float g_attn[S_ * H_];
__device__ float g_tnorm[S_ * H_];
__device__ float g_gu[(size_t)E_ * S_ * 2 * I_];
__device__ int   g_counts[E_];
__device__ int   g_toklist[E_ * S_];
__device__ float g_tokw[E_ * S_];

// ---------------------------------------------------------------------------
__device__ __forceinline__ uint32_t smem_u32(const void* p) {
    uint32_t a;
    asm("{ .reg .u64 t; cvta.to.shared.u64 t, %1; cvt.u32.u64 %0, t; }"
        : "=r"(a) : "l"(p));
    return a;
}
__device__ __forceinline__ void ldm4(uint32_t& r0, uint32_t& r1,
                                     uint32_t& r2, uint32_t& r3, uint32_t addr) {
    asm volatile("ldmatrix.sync.aligned.m8n8.x4.shared.b16 {%0,%1,%2,%3}, [%4];"
                 : "=r"(r0), "=r"(r1), "=r"(r2), "=r"(r3) : "r"(addr));
}
__device__ __forceinline__ void mma16816(float* d, const uint32_t* a,
                                         const uint32_t* b) {
    asm volatile(
        "mma.sync.aligned.m16n8k16.row.col.f32.bf16.bf16.f32 "
        "{%0,%1,%2,%3}, {%4,%5,%6,%7}, {%8,%9}, {%0,%1,%2,%3};"
        : "+f"(d[0]), "+f"(d[1]), "+f"(d[2]), "+f"(d[3])
        : "r"(a[0]), "r"(a[1]), "r"(a[2]), "r"(a[3]), "r"(b[0]), "r"(b[1]));
}
__device__ __forceinline__ void cp16(uint32_t dst, const void* src, int sz) {
    asm volatile("cp.async.cg.shared.global [%0], [%1], 16, %2;"
                 :: "r"(dst), "l"(src), "r"(sz));
}
__device__ __forceinline__ void cp_commit() {
    asm volatile("cp.async.commit_group;");
}
__device__ __forceinline__ void cp_wait0() {
    asm volatile("cp.async.wait_group 0;");
}

// split fp32 float4 -> bf16 hi/lo (8B each)
__device__ __forceinline__ void split_store4(float4 v, bf16* hp, bf16* lp) {
    __nv_bfloat162 h01 = __floats2bfloat162_rn(v.x, v.y);
    __nv_bfloat162 h23 = __floats2bfloat162_rn(v.z, v.w);
    float2 f01 = __bfloat1622float2(h01);
    float2 f23 = __bfloat1622float2(h23);
    __nv_bfloat162 l01 = __floats2bfloat162_rn(v.x - f01.x, v.y - f01.y);
    __nv_bfloat162 l23 = __floats2bfloat162_rn(v.z - f23.x, v.w - f23.y);
    *(uint2*)hp = make_uint2(*(uint32_t*)&h01, *(uint32_t*)&h23);
    *(uint2*)lp = make_uint2(*(uint32_t*)&l01, *(uint32_t*)&l23);
}

// ---------------------------------------------------------------------------
// HMMA GEMM, bf16 3-term split inputs precomputed as hi/lo planes.
// CTA tile 128x128, BK=32, 8 warps (2 m x 4 n), warp tile 64x32.
// cp.async double-buffered. Swizzle: phys_chunk = chunk ^ ((row>>1)&3).
// GATHER: A rows via toklist. EPI: 0=store 1=+addsrc 2=weighted scatter.
// ---------------------------------------------------------------------------
template<int GATHER, int EPI>
__global__ __launch_bounds__(256)
void hmma2(const bf16* __restrict__ Ah, const bf16* __restrict__ Al,
           const bf16* __restrict__ Bh, const bf16* __restrict__ Bl,
           float* __restrict__ C, int M, int N, int K, int lda, int ldc,
           const float* __restrict__ addsrc,
           const int* __restrict__ counts,
           const int* __restrict__ toklist,
           const float* __restrict__ tokw,
           size_t sA, size_t sB, size_t sC)
{
    extern __shared__ char smem[];     // 2 stages x 4 planes x 8KB = 64KB
    __shared__ int rowsS[128];

    int e = blockIdx.z;
    int Mlim = counts ? counts[e] : M;
    int m0 = blockIdx.y * 128;
    if (m0 >= Mlim) return;
    int n0 = blockIdx.x * 128;
    const bf16* Ahe = Ah + sA * e;
    const bf16* Ale = Al + sA * e;
    const bf16* Bhe = Bh + sB * e;
    const bf16* Ble = Bl + sB * e;
    float*      Ce  = C + sC * e;

    int tid = threadIdx.x;
    int wid = tid >> 5;
    int lane = tid & 31;
    int warp_m = wid & 1;
    int warp_n = wid >> 1;

    if (GATHER) {
        if (tid < 128)
            rowsS[tid] = (m0 + tid < Mlim) ? toklist[e * S_ + m0 + tid] : -1;
        __syncthreads();
    }

    uint32_t sbase = smem_u32(smem);

    auto issue = [&](int c, int buf) {
        int k0 = c * 32;
        #pragma unroll
        for (int l = 0; l < 8; l++) {
            int seg = tid + l * 256;
            int plane = seg >> 9;            // 0=Ah 1=Al 2=Bh 3=Bl
            int row = (seg >> 2) & 127;
            int ch = seg & 3;
            uint32_t dst = sbase + buf * 32768 + plane * 8192
                         + row * 64 + ((ch ^ ((row >> 1) & 3)) << 4);
            const bf16* gsrc;
            int sz = 16;
            if (plane < 2) {
                int gr;
                if (GATHER) {
                    gr = rowsS[row];
                    if (gr < 0) { gr = 0; sz = 0; }
                } else {
                    gr = m0 + row;
                    if (gr >= Mlim) { gr = 0; sz = 0; }
                }
                gsrc = (plane ? Ale : Ahe) + (size_t)gr * lda + k0 + ch * 8;
            } else {
                gsrc = ((plane == 3) ? Ble : Bhe) + (size_t)(n0 + row) * K + k0 + ch * 8;
            }
            cp16(dst, gsrc, sz);
        }
        cp_commit();
    };

    float acc[4][4][4] = {};
    const int nc = K / 32;
    issue(0, 0);

    for (int c = 0; c < nc; c++) {
        cp_wait0();
        __syncthreads();
        if (c + 1 < nc) issue(c + 1, (c + 1) & 1);

        uint32_t sb = sbase + (c & 1) * 32768;
        int mi = lane >> 3, r = lane & 7;

        #pragma unroll
        for (int ks = 0; ks < 2; ks++) {
            // B fragments (4 n-frags, hi & lo)
            uint32_t bfh[4][2], bfl[4][2];
            #pragma unroll
            for (int nfp = 0; nfp < 2; nfp++) {
                int n = warp_n * 32 + nfp * 16 + ((mi >> 1) << 3) + r;
                int ch = ks * 2 + (mi & 1);
                uint32_t off = (uint32_t)(n * 64 + ((ch ^ ((n >> 1) & 3)) << 4));
                uint32_t r0, r1, r2, r3;
                ldm4(r0, r1, r2, r3, sb + 2 * 8192 + off);
                bfh[nfp * 2 + 0][0] = r0; bfh[nfp * 2 + 0][1] = r1;
                bfh[nfp * 2 + 1][0] = r2; bfh[nfp * 2 + 1][1] = r3;
                ldm4(r0, r1, r2, r3, sb + 3 * 8192 + off);
                bfl[nfp * 2 + 0][0] = r0; bfl[nfp * 2 + 0][1] = r1;
                bfl[nfp * 2 + 1][0] = r2; bfl[nfp * 2 + 1][1] = r3;
            }
            // A fragments (4 m-frags, hi & lo)
            uint32_t afh[4][4], afl[4][4];
            #pragma unroll
            for (int mf = 0; mf < 4; mf++) {
                int row = warp_m * 64 + mf * 16 + ((mi & 1) << 3) + r;
                int ch = ks * 2 + (mi >> 1);
                uint32_t off = (uint32_t)(row * 64 + ((ch ^ ((row >> 1) & 3)) << 4));
                ldm4(afh[mf][0], afh[mf][1], afh[mf][2], afh[mf][3], sb + off);
                ldm4(afl[mf][0], afl[mf][1], afl[mf][2], afl[mf][3], sb + 8192 + off);
            }
            // term sweeps: same-acc reuse distance = 16 MMAs
            #pragma unroll
            for (int mf = 0; mf < 4; mf++)
                #pragma unroll
                for (int nf = 0; nf < 4; nf++)
                    mma16816(acc[mf][nf], afh[mf], bfh[nf]);
            #pragma unroll
            for (int mf = 0; mf < 4; mf++)
                #pragma unroll
                for (int nf = 0; nf < 4; nf++)
                    mma16816(acc[mf][nf], afl[mf], bfh[nf]);
            #pragma unroll
            for (int mf = 0; mf < 4; mf++)
                #pragma unroll
                for (int nf = 0; nf < 4; nf++)
                    mma16816(acc[mf][nf], afh[mf], bfl[nf]);
        }
    }

    // ---------------- epilogue ----------------
    int lr = lane >> 2;
    int lc = (lane & 3) * 2;
    #pragma unroll
    for (int mf = 0; mf < 4; mf++) {
        int r0g = m0 + warp_m * 64 + mf * 16 + lr;
        int r1g = r0g + 8;
        if (EPI == 2) {
            int tokA = 0, tokB = 0; float wA = 0.f, wB = 0.f;
            bool vA = (r0g < Mlim), vB = (r1g < Mlim);
            if (vA) { tokA = toklist[e * S_ + r0g]; wA = tokw[e * S_ + r0g]; }
            if (vB) { tokB = toklist[e * S_ + r1g]; wB = tokw[e * S_ + r1g]; }
            #pragma unroll
            for (int nf = 0; nf < 4; nf++) {
                int col = n0 + warp_n * 32 + nf * 8 + lc;
                if (vA) {
                    atomicAdd(&C[(size_t)tokA * H_ + col],     wA * acc[mf][nf][0]);
                    atomicAdd(&C[(size_t)tokA * H_ + col + 1], wA * acc[mf][nf][1]);
                }
                if (vB) {
                    atomicAdd(&C[(size_t)tokB * H_ + col],     wB * acc[mf][nf][2]);
                    atomicAdd(&C[(size_t)tokB * H_ + col + 1], wB * acc[mf][nf][3]);
                }
            }
        } else {
            #pragma unroll
            for (int nf = 0; nf < 4; nf++) {
                int col = n0 + warp_n * 32 + nf * 8 + lc;
                if (r0g < Mlim) {
                    float2 v = make_float2(acc[mf][nf][0], acc[mf][nf][1]);
                    if (EPI == 1) {
                        const float* a2 = addsrc + (size_t)r0g * ldc + col;
                        v.x += a2[0]; v.y += a2[1];
                    }
                    *(float2*)(Ce + (size_t)r0g * ldc + col) = v;
                }
                if (r1g < Mlim) {
                    float2 v = make_float2(acc[mf][nf][2], acc[mf][nf][3]);
                    if (EPI == 1) {
                        const float* a2 = addsrc + (size_t)r1g * ldc + col;
                        v.x += a2[0]; v.y += a2[1];
                    }
                    *(float2*)(Ce + (size_t)r1g * ldc + col) = v;
                }
            }
        }
    }
}

// ---------------------------------------------------------------------------
// fp32 -> bf16 hi/lo split prepass (vectorized float4)
// ---------------------------------------------------------------------------
__global__ void split_kernel(const float* __restrict__ src,
                             bf16* __restrict__ h, bf16* __restrict__ l,
                             size_t n4) {
    size_t i = (size_t)blockIdx.x * blockDim.x + threadIdx.x;
    if (i >= n4) return;
    float4 v = ((const float4*)src)[i];
    split_store4(v, h + i * 4, l + i * 4);
}

// silu(g)*u -> bf16 hi/lo, gathered rows only
__global__ void act_kernel(const float* __restrict__ gu,
                           const int* __restrict__ counts,
                           bf16* __restrict__ ah, bf16* __restrict__ al) {
    int e = blockIdx.z, slot = blockIdx.y;
    if (slot >= counts[e]) return;
    const float* row = gu + ((size_t)e * S_ + slot) * (2 * I_);
    bf16* hr = ah + ((size_t)e * S_ + slot) * I_;
    bf16* lr = al + ((size_t)e * S_ + slot) * I_;
    for (int i = threadIdx.x * 4; i < I_; i += blockDim.x * 4) {
        float4 g = *(const float4*)(row + i);
        float4 u = *(const float4*)(row + I_ + i);
        float4 a;
        a.x = g.x / (1.f + __expf(-g.x)) * u.x;
        a.y = g.y / (1.f + __expf(-g.y)) * u.y;
        a.z = g.z / (1.f + __expf(-g.z)) * u.z;
        a.w = g.w / (1.f + __expf(-g.w)) * u.w;
        split_store4(a, hr + i, lr + i);
    }
}

// ---------------------------------------------------------------------------
__global__ void zero_kernel(float* out, int* counts) {
    int i = blockIdx.x * blockDim.x + threadIdx.x;
    if (i < S_ * H_) out[i] = 0.0f;
    if (i < E_) counts[i] = 0;
}

// RMSNorm emitting fp32 (optional) + bf16 hi/lo planes
__global__ void rmsnorm_hl(const float* __restrict__ x,
                           const float* __restrict__ w,
                           float* __restrict__ y,
                           bf16* __restrict__ yh, bf16* __restrict__ yl) {
    int row = blockIdx.x;
    int tid = threadIdx.x;
    __shared__ float red[256];
    const float* xr = x + (size_t)row * H_;
    float s = 0.0f;
    for (int c = tid; c < H_; c += 256) { float v = xr[c]; s += v * v; }
    red[tid] = s; __syncthreads();
    for (int o = 128; o > 0; o >>= 1) {
        if (tid < o) red[tid] += red[tid + o];
        __syncthreads();
    }
    float inv = rsqrtf(red[0] / (float)H_ + EPS_);
    for (int c = tid * 4; c < H_; c += 1024) {
        float4 v = *(const float4*)(xr + c);
        float4 wv = *(const float4*)(w + c);
        v.x *= inv * wv.x; v.y *= inv * wv.y;
        v.z *= inv * wv.z; v.w *= inv * wv.w;
        if (y) *(float4*)(y + (size_t)row * H_ + c) = v;
        split_store4(v, yh + (size_t)row * H_ + c, yl + (size_t)row * H_ + c);
    }
}

// ---------------------------------------------------------------------------
// Flash attention (fp32) — unchanged
// ---------------------------------------------------------------------------
__global__ __launch_bounds__(256)
void attn_flash(const float* __restrict__ qkv, float* __restrict__ out) {
    extern __shared__ float smf[];
    float* Qs  = smf;
    float* KPs = smf + 64 * 64;
    float* Vs  = smf + 64 * 64 + 64 * 68;

    int qt = blockIdx.x, h = blockIdx.y;
    int q0 = qt * 64;
    int kvh = h >> 2;
    int tid = threadIdx.x;
    int tx = tid & 15, ty = tid >> 4;

    #pragma unroll
    for (int l = 0; l < 4; l++) {
        int idx = tid + l * 256;
        int r = idx >> 4, dq = (idx & 15) * 4;
        *(float4*)&Qs[r * 64 + dq] =
            *(const float4*)&qkv[(size_t)(q0 + r) * QKV_O + h * 64 + dq];
    }

    float acc[4][4] = {};
    float rm[4], rl[4];
    #pragma unroll
    for (int i = 0; i < 4; i++) { rm[i] = -1e30f; rl[i] = 0.f; }

    int t0 = (q0 > 511) ? ((q0 - 511) >> 6) : 0;
    for (int kt = t0; kt <= qt; kt++) {
        int j0 = kt * 64;
        __syncthreads();
        #pragma unroll
        for (int l = 0; l < 4; l++) {
            int idx = tid + l * 256;
            int r = idx >> 4, dq = (idx & 15) * 4;
            *(float4*)&KPs[r * 68 + dq] =
                *(const float4*)&qkv[(size_t)(j0 + r) * QKV_O + H_ + kvh * 64 + dq];
            *(float4*)&Vs[r * 64 + dq] =
                *(const float4*)&qkv[(size_t)(j0 + r) * QKV_O + H_ + NKV_ * HD_ + kvh * 64 + dq];
        }
        __syncthreads();

        float s[4][4] = {};
        #pragma unroll
        for (int d0 = 0; d0 < 64; d0 += 4) {
            float4 q4[4], k4[4];
            #pragma unroll
            for (int i = 0; i < 4; i++) q4[i] = *(const float4*)&Qs[(ty * 4 + i) * 64 + d0];
            #pragma unroll
            for (int j = 0; j < 4; j++) k4[j] = *(const float4*)&KPs[(tx + 16 * j) * 68 + d0];
            #pragma unroll
            for (int i = 0; i < 4; i++)
                #pragma unroll
                for (int j = 0; j < 4; j++)
                    s[i][j] += q4[i].x * k4[j].x + q4[i].y * k4[j].y
                             + q4[i].z * k4[j].z + q4[i].w * k4[j].w;
        }
        __syncthreads();

        float p[4][4];
        #pragma unroll
        for (int i = 0; i < 4; i++) {
            int iq = q0 + ty * 4 + i;
            float tm = -1e30f;
            #pragma unroll
            for (int j = 0; j < 4; j++) {
                int jk = j0 + tx + 16 * j;
                bool ok = (jk <= iq) && (iq - jk < WIN_);
                s[i][j] = ok ? s[i][j] * 0.125f : -1e30f;
                tm = fmaxf(tm, s[i][j]);
            }
            #pragma unroll
            for (int o = 1; o < 16; o <<= 1)
                tm = fmaxf(tm, __shfl_xor_sync(0xffffffffu, tm, o));
            float mn = fmaxf(rm[i], tm);
            float alpha = __expf(rm[i] - mn);
            rm[i] = mn;
            float ps = 0.f;
            #pragma unroll
            for (int j = 0; j < 4; j++) { p[i][j] = __expf(s[i][j] - mn); ps += p[i][j]; }
            #pragma unroll
            for (int o = 1; o < 16; o <<= 1)
                ps += __shfl_xor_sync(0xffffffffu, ps, o);
            rl[i] = rl[i] * alpha + ps;
            #pragma unroll
            for (int j = 0; j < 4; j++) acc[i][j] *= alpha;
            #pragma unroll
            for (int j = 0; j < 4; j++)
                KPs[(ty * 4 + i) * 68 + tx + 16 * j] = p[i][j];
        }
        __syncthreads();

        #pragma unroll 4
        for (int n = 0; n < 64; n++) {
            float pv[4], vv[4];
            #pragma unroll
            for (int i = 0; i < 4; i++) pv[i] = KPs[(ty * 4 + i) * 68 + n];
            #pragma unroll
            for (int j = 0; j < 4; j++) vv[j] = Vs[n * 64 + tx + 16 * j];
            #pragma unroll
            for (int i = 0; i < 4; i++)
                #pragma unroll
                for (int j = 0; j < 4; j++)
                    acc[i][j] += pv[i] * vv[j];
        }
    }

    #pragma unroll
    for (int i = 0; i < 4; i++) {
        float inv = 1.0f / rl[i];
        #pragma unroll
        for (int j = 0; j < 4; j++)
            out[(size_t)(q0 + ty * 4 + i) * H_ + h * 64 + tx + 16 * j] = acc[i][j] * inv;
    }
}

// ---------------------------------------------------------------------------
__global__ void router_kernel(const float* __restrict__ t,
                              const float* __restrict__ rw,
                              int* counts, int* toklist, float* tokw) {
    int warp = threadIdx.x >> 5;
    int lane = threadIdx.x & 31;
    int tok = blockIdx.x * 8 + warp;
    if (tok >= S_) return;
    const float* tr = t + (size_t)tok * H_;
    float logits[E_];
    for (int e = 0; e < E_; e++) {
        float s = 0.0f;
        for (int k = lane; k < H_; k += 32) s += tr[k] * rw[e * H_ + k];
        for (int o = 16; o > 0; o >>= 1) s += __shfl_xor_sync(0xffffffff, s, o);
        logits[e] = s;
    }
    if (lane == 0) {
        float mx = logits[0];
        for (int e = 1; e < E_; e++) mx = fmaxf(mx, logits[e]);
        float p[E_], sum = 0.0f;
        for (int e = 0; e < E_; e++) { p[e] = __expf(logits[e] - mx); sum += p[e]; }
        float invs = 1.0f / sum;
        for (int e = 0; e < E_; e++) p[e] *= invs;
        int b1 = 0;
        for (int e = 1; e < E_; e++) if (p[e] > p[b1]) b1 = e;
        int b2 = -1;
        for (int e = 0; e < E_; e++) {
            if (e == b1) continue;
            if (b2 < 0 || p[e] > p[b2]) b2 = e;
        }
        int pos1 = atomicAdd(&counts[b1], 1);
        toklist[b1 * S_ + pos1] = tok; tokw[b1 * S_ + pos1] = p[b1];
        int pos2 = atomicAdd(&counts[b2], 1);
        toklist[b2 * S_ + pos2] = tok; tokw[b2 * S_ + pos2] = p[b2];
    }
}

// ---------------------------------------------------------------------------
extern "C" void kernel_launch(void* const* d_in, const int* in_sizes, int n_in,
                              void* d_out, int out_size) {
    const float* hidden   = (const float*)d_in[0];
    const float* w_qkv    = (const float*)d_in[2];
    const float* w_o      = (const float*)d_in[3];
    const float* router_w = (const float*)d_in[4];
    const float* ws       = (const float*)d_in[5];
    const float* w2s      = (const float*)d_in[6];
    const float* ln1      = (const float*)d_in[7];
    const float* ln2      = (const float*)d_in[8];

    float* out    = (float*)d_out;
    float* resid2 = out + (size_t)S_ * H_;

    bf16 *wqh, *wql, *woh, *wol, *wsh, *wsl, *w2h, *w2l;
    bf16 *xnh, *xnl, *ath, *atl, *tnh, *tnl, *ach, *acl;
    float *qkv, *attn, *tnorm, *gu, *tokw;
    int *counts, *toklist;
    cudaGetSymbolAddress((void**)&wqh, g_wqkv_h); cudaGetSymbolAddress((void**)&wql, g_wqkv_l);
    cudaGetSymbolAddress((void**)&woh, g_wo_h);   cudaGetSymbolAddress((void**)&wol, g_wo_l);
    cudaGetSymbolAddress((void**)&wsh, g_ws_h);   cudaGetSymbolAddress((void**)&wsl, g_ws_l);
    cudaGetSymbolAddress((void**)&w2h, g_w2s_h);  cudaGetSymbolAddress((void**)&w2l, g_w2s_l);
    cudaGetSymbolAddress((void**)&xnh, g_xn_h);   cudaGetSymbolAddress((void**)&xnl, g_xn_l);
    cudaGetSymbolAddress((void**)&ath, g_at_h);   cudaGetSymbolAddress((void**)&atl, g_at_l);
    cudaGetSymbolAddress((void**)&tnh, g_tn_h);   cudaGetSymbolAddress((void**)&tnl, g_tn_l);
    cudaGetSymbolAddress((void**)&ach, g_act_h);  cudaGetSymbolAddress((void**)&acl, g_act_l);
    cudaGetSymbolAddress((void**)&qkv,   g_qkv);
    cudaGetSymbolAddress((void**)&attn,  g_attn);
    cudaGetSymbolAddress((void**)&tnorm, g_tnorm);
    cudaGetSymbolAddress((void**)&gu,    g_gu);
    cudaGetSymbolAddress((void**)&counts, g_counts);
    cudaGetSymbolAddress((void**)&toklist, g_toklist);
    cudaGetSymbolAddress((void**)&tokw,  g_tokw);

    const int GSMEM = 65536;
    cudaFuncSetAttribute(hmma2<0,0>, cudaFuncAttributeMaxDynamicSharedMemorySize, GSMEM);
    cudaFuncSetAttribute(hmma2<0,1>, cudaFuncAttributeMaxDynamicSharedMemorySize, GSMEM);
    cudaFuncSetAttribute(hmma2<1,0>, cudaFuncAttributeMaxDynamicSharedMemorySize, GSMEM);
    cudaFuncSetAttribute(hmma2<0,2>, cudaFuncAttributeMaxDynamicSharedMemorySize, GSMEM);
    int attn_smem = (64 * 64 + 64 * 68 + 64 * 64) * 4;
    cudaFuncSetAttribute(attn_flash, cudaFuncAttributeMaxDynamicSharedMemorySize, attn_smem);

    zero_kernel<<<(S_ * H_ + 255) / 256, 256>>>(out, counts);

    // weight split prepass
    split_kernel<<<(QKV_O * H_ / 4 + 255) / 256, 256>>>(w_qkv, wqh, wql, QKV_O * H_ / 4);
    split_kernel<<<(H_ * H_ / 4 + 255) / 256, 256>>>(w_o, woh, wol, H_ * H_ / 4);
    split_kernel<<<(int)(((size_t)E_ * 2 * I_ * H_ / 4 + 255) / 256), 256>>>(
        ws, wsh, wsl, (size_t)E_ * 2 * I_ * H_ / 4);
    split_kernel<<<(int)(((size_t)E_ * H_ * I_ / 4 + 255) / 256), 256>>>(
        w2s, w2h, w2l, (size_t)E_ * H_ * I_ / 4);

    rmsnorm_hl<<<S_, 256>>>(hidden, ln1, nullptr, xnh, xnl);

    // QKV
    hmma2<0,0><<<dim3(QKV_O / 128, S_ / 128, 1), 256, GSMEM>>>(
        xnh, xnl, wqh, wql, qkv, S_, QKV_O, H_, H_, QKV_O,
        nullptr, nullptr, nullptr, nullptr, 0, 0, 0);

    attn_flash<<<dim3(S_ / 64, NH_), 256, attn_smem>>>(qkv, attn);
    split_kernel<<<(S_ * H_ / 4 + 255) / 256, 256>>>(attn, ath, atl, S_ * H_ / 4);

    // O proj + residual
    hmma2<0,1><<<dim3(H_ / 128, S_ / 128, 1), 256, GSMEM>>>(
        ath, atl, woh, wol, resid2, S_, H_, H_, H_, H_,
        hidden, nullptr, nullptr, nullptr, 0, 0, 0);

    rmsnorm_hl<<<S_, 256>>>(resid2, ln2, tnorm, tnh, tnl);
    router_kernel<<<S_ / 8, 256>>>(tnorm, router_w, counts, toklist, tokw);

    // MoE up+gate (gathered A)
    hmma2<1,0><<<dim3(2 * I_ / 128, S_ / 128, E_), 256, GSMEM>>>(
        tnh, tnl, wsh, wsl, gu, S_, 2 * I_, H_, H_, 2 * I_,
        nullptr, counts, toklist, nullptr,
        0, (size_t)2 * I_ * H_, (size_t)S_ * 2 * I_);

    act_kernel<<<dim3(1, S_, E_), 256>>>(gu, counts, ach, acl);

    // MoE down (weighted scatter)
    hmma2<0,2><<<dim3(H_ / 128, S_ / 128, E_), 256, GSMEM>>>(
        ach, acl, w2h, w2l, out, S_, H_, I_, I_, H_,
        nullptr, counts, toklist, tokw,
        (size_t)S_ * I_, (size_t)H_ * I_, 0);
}

// round 6
// speedup vs baseline: 4.5585x; 1.0785x over previous
#include <cuda_runtime.h>
#include <cuda_bf16.h>
#include <math.h>
#include <stdint.h>

#define S_  2048
#define H_  1024
#define NH_ 16
#define NKV_ 4
#define HD_ 64
#define QKV_O 1536
#define I_  2816
#define E_  8
#define WIN_ 512
#define EPS_ 1e-5f

typedef __nv_bfloat16 bf16;

// ---------------------------------------------------------------------------
// Scratch (static device globals)
// ---------------------------------------------------------------------------
__device__ bf16 g_wqkv_h[QKV_O * H_],            g_wqkv_l[QKV_O * H_];
__device__ bf16 g_wo_h[H_ * H_],                 g_wo_l[H_ * H_];
__device__ bf16 g_ws_h[(size_t)E_ * 2 * I_ * H_], g_ws_l[(size_t)E_ * 2 * I_ * H_];
__device__ bf16 g_w2s_h[(size_t)E_ * H_ * I_],    g_w2s_l[(size_t)E_ * H_ * I_];
__device__ bf16 g_xn_h[S_ * H_],  g_xn_l[S_ * H_];
__device__ bf16 g_at_h[S_ * H_],  g_at_l[S_ * H_];
__device__ bf16 g_tn_h[S_ * H_],  g_tn_l[S_ * H_];
__device__ bf16 g_act_h[(size_t)E_ * S_ * I_],    g_act_l[(size_t)E_ * S_ * I_];
__device__ float g_qkv[S_ * QKV_O];
__device__ float g_tnorm[S_ * H_];
__device__ float g_gu[(size_t)E_ * S_ * 2 * I_];
__device__ int   g_counts[E_];
__device__ int   g_toklist[E_ * S_];
__device__ float g_tokw[E_ * S_];

// ---------------------------------------------------------------------------
__device__ __forceinline__ uint32_t smem_u32(const void* p) {
    uint32_t a;
    asm("{ .reg .u64 t; cvta.to.shared.u64 t, %1; cvt.u32.u64 %0, t; }"
        : "=r"(a) : "l"(p));
    return a;
}
__device__ __forceinline__ void ldm4(uint32_t& r0, uint32_t& r1,
                                     uint32_t& r2, uint32_t& r3, uint32_t addr) {
    asm volatile("ldmatrix.sync.aligned.m8n8.x4.shared.b16 {%0,%1,%2,%3}, [%4];"
                 : "=r"(r0), "=r"(r1), "=r"(r2), "=r"(r3) : "r"(addr));
}
__device__ __forceinline__ void mma16816(float* d, const uint32_t* a,
                                         const uint32_t* b) {
    asm volatile(
        "mma.sync.aligned.m16n8k16.row.col.f32.bf16.bf16.f32 "
        "{%0,%1,%2,%3}, {%4,%5,%6,%7}, {%8,%9}, {%0,%1,%2,%3};"
        : "+f"(d[0]), "+f"(d[1]), "+f"(d[2]), "+f"(d[3])
        : "r"(a[0]), "r"(a[1]), "r"(a[2]), "r"(a[3]), "r"(b[0]), "r"(b[1]));
}
__device__ __forceinline__ void cp16(uint32_t dst, const void* src, int sz) {
    asm volatile("cp.async.cg.shared.global [%0], [%1], 16, %2;"
                 :: "r"(dst), "l"(src), "r"(sz));
}
__device__ __forceinline__ void cp_commit() {
    asm volatile("cp.async.commit_group;");
}
__device__ __forceinline__ void cp_wait0() {
    asm volatile("cp.async.wait_group 0;");
}

// split fp32 float4 -> bf16 hi/lo (8B each)
__device__ __forceinline__ void split_store4(float4 v, bf16* hp, bf16* lp) {
    __nv_bfloat162 h01 = __floats2bfloat162_rn(v.x, v.y);
    __nv_bfloat162 h23 = __floats2bfloat162_rn(v.z, v.w);
    float2 f01 = __bfloat1622float2(h01);
    float2 f23 = __bfloat1622float2(h23);
    __nv_bfloat162 l01 = __floats2bfloat162_rn(v.x - f01.x, v.y - f01.y);
    __nv_bfloat162 l23 = __floats2bfloat162_rn(v.z - f23.x, v.w - f23.y);
    *(uint2*)hp = make_uint2(*(uint32_t*)&h01, *(uint32_t*)&h23);
    *(uint2*)lp = make_uint2(*(uint32_t*)&l01, *(uint32_t*)&l23);
}

// ---------------------------------------------------------------------------
// HMMA GEMM, bf16 3-term split inputs precomputed as hi/lo planes.
// CTA tile 128x128, BK=32, 8 warps (2 m x 4 n), warp tile 64x32.
// cp.async double-buffered, 2 CTAs/SM. Short-live-range term sweeps.
// GATHER: A rows via toklist. EPI: 0=store 1=+addsrc 2=weighted scatter.
// ---------------------------------------------------------------------------
template<int GATHER, int EPI>
__global__ __launch_bounds__(256, 2)
void hmma2(const bf16* __restrict__ Ah, const bf16* __restrict__ Al,
           const bf16* __restrict__ Bh, const bf16* __restrict__ Bl,
           float* __restrict__ C, int M, int N, int K, int lda, int ldc,
           const float* __restrict__ addsrc,
           const int* __restrict__ counts,
           const int* __restrict__ toklist,
           const float* __restrict__ tokw,
           size_t sA, size_t sB, size_t sC)
{
    extern __shared__ char smem[];     // 2 stages x 4 planes x 8KB = 64KB
    __shared__ int rowsS[128];

    int e = blockIdx.z;
    int Mlim = counts ? counts[e] : M;
    int m0 = blockIdx.y * 128;
    if (m0 >= Mlim) return;
    int n0 = blockIdx.x * 128;
    const bf16* Ahe = Ah + sA * e;
    const bf16* Ale = Al + sA * e;
    const bf16* Bhe = Bh + sB * e;
    const bf16* Ble = Bl + sB * e;
    float*      Ce  = C + sC * e;

    int tid = threadIdx.x;
    int wid = tid >> 5;
    int lane = tid & 31;
    int warp_m = wid & 1;
    int warp_n = wid >> 1;

    if (GATHER) {
        if (tid < 128)
            rowsS[tid] = (m0 + tid < Mlim) ? toklist[e * S_ + m0 + tid] : -1;
        __syncthreads();
    }

    uint32_t sbase = smem_u32(smem);

    auto issue = [&](int c, int buf) {
        int k0 = c * 32;
        #pragma unroll
        for (int l = 0; l < 8; l++) {
            int seg = tid + l * 256;
            int plane = seg >> 9;            // 0=Ah 1=Al 2=Bh 3=Bl
            int row = (seg >> 2) & 127;
            int ch = seg & 3;
            uint32_t dst = sbase + buf * 32768 + plane * 8192
                         + row * 64 + ((ch ^ ((row >> 1) & 3)) << 4);
            const bf16* gsrc;
            int sz = 16;
            if (plane < 2) {
                int gr;
                if (GATHER) {
                    gr = rowsS[row];
                    if (gr < 0) { gr = 0; sz = 0; }
                } else {
                    gr = m0 + row;
                    if (gr >= Mlim) { gr = 0; sz = 0; }
                }
                gsrc = (plane ? Ale : Ahe) + (size_t)gr * lda + k0 + ch * 8;
            } else {
                gsrc = ((plane == 3) ? Ble : Bhe) + (size_t)(n0 + row) * K + k0 + ch * 8;
            }
            cp16(dst, gsrc, sz);
        }
        cp_commit();
    };

    float acc[4][4][4] = {};
    const int nc = K / 32;
    issue(0, 0);

    for (int c = 0; c < nc; c++) {
        cp_wait0();
        __syncthreads();
        if (c + 1 < nc) issue(c + 1, (c + 1) & 1);

        uint32_t sb = sbase + (c & 1) * 32768;
        int mi = lane >> 3, r = lane & 7;

        #pragma unroll
        for (int ks = 0; ks < 2; ks++) {
            // ---- load A-hi and B-hi fragments ----
            uint32_t afh[4][4], bfh[4][2];
            #pragma unroll
            for (int nfp = 0; nfp < 2; nfp++) {
                int n = warp_n * 32 + nfp * 16 + ((mi >> 1) << 3) + r;
                int ch = ks * 2 + (mi & 1);
                uint32_t off = (uint32_t)(n * 64 + ((ch ^ ((n >> 1) & 3)) << 4));
                uint32_t r0, r1, r2, r3;
                ldm4(r0, r1, r2, r3, sb + 2 * 8192 + off);
                bfh[nfp * 2 + 0][0] = r0; bfh[nfp * 2 + 0][1] = r1;
                bfh[nfp * 2 + 1][0] = r2; bfh[nfp * 2 + 1][1] = r3;
            }
            #pragma unroll
            for (int mf = 0; mf < 4; mf++) {
                int row = warp_m * 64 + mf * 16 + ((mi & 1) << 3) + r;
                int ch = ks * 2 + (mi >> 1);
                uint32_t off = (uint32_t)(row * 64 + ((ch ^ ((row >> 1) & 3)) << 4));
                ldm4(afh[mf][0], afh[mf][1], afh[mf][2], afh[mf][3], sb + off);
            }
            // sweep 1: Ah x Bh
            #pragma unroll
            for (int mf = 0; mf < 4; mf++)
                #pragma unroll
                for (int nf = 0; nf < 4; nf++)
                    mma16816(acc[mf][nf], afh[mf], bfh[nf]);

            // ---- load B-lo, sweep 2: Ah x Bl ----
            {
                uint32_t bfl[4][2];
                #pragma unroll
                for (int nfp = 0; nfp < 2; nfp++) {
                    int n = warp_n * 32 + nfp * 16 + ((mi >> 1) << 3) + r;
                    int ch = ks * 2 + (mi & 1);
                    uint32_t off = (uint32_t)(n * 64 + ((ch ^ ((n >> 1) & 3)) << 4));
                    uint32_t r0, r1, r2, r3;
                    ldm4(r0, r1, r2, r3, sb + 3 * 8192 + off);
                    bfl[nfp * 2 + 0][0] = r0; bfl[nfp * 2 + 0][1] = r1;
                    bfl[nfp * 2 + 1][0] = r2; bfl[nfp * 2 + 1][1] = r3;
                }
                #pragma unroll
                for (int mf = 0; mf < 4; mf++)
                    #pragma unroll
                    for (int nf = 0; nf < 4; nf++)
                        mma16816(acc[mf][nf], afh[mf], bfl[nf]);
            }

            // ---- load A-lo, sweep 3: Al x Bh ----
            {
                uint32_t afl[4][4];
                #pragma unroll
                for (int mf = 0; mf < 4; mf++) {
                    int row = warp_m * 64 + mf * 16 + ((mi & 1) << 3) + r;
                    int ch = ks * 2 + (mi >> 1);
                    uint32_t off = (uint32_t)(row * 64 + ((ch ^ ((row >> 1) & 3)) << 4));
                    ldm4(afl[mf][0], afl[mf][1], afl[mf][2], afl[mf][3], sb + 8192 + off);
                }
                #pragma unroll
                for (int mf = 0; mf < 4; mf++)
                    #pragma unroll
                    for (int nf = 0; nf < 4; nf++)
                        mma16816(acc[mf][nf], afl[mf], bfh[nf]);
            }
        }
    }

    // ---------------- epilogue ----------------
    int lr = lane >> 2;
    int lc = (lane & 3) * 2;
    #pragma unroll
    for (int mf = 0; mf < 4; mf++) {
        int r0g = m0 + warp_m * 64 + mf * 16 + lr;
        int r1g = r0g + 8;
        if (EPI == 2) {
            int tokA = 0, tokB = 0; float wA = 0.f, wB = 0.f;
            bool vA = (r0g < Mlim), vB = (r1g < Mlim);
            if (vA) { tokA = toklist[e * S_ + r0g]; wA = tokw[e * S_ + r0g]; }
            if (vB) { tokB = toklist[e * S_ + r1g]; wB = tokw[e * S_ + r1g]; }
            #pragma unroll
            for (int nf = 0; nf < 4; nf++) {
                int col = n0 + warp_n * 32 + nf * 8 + lc;
                if (vA) {
                    atomicAdd(&C[(size_t)tokA * H_ + col],     wA * acc[mf][nf][0]);
                    atomicAdd(&C[(size_t)tokA * H_ + col + 1], wA * acc[mf][nf][1]);
                }
                if (vB) {
                    atomicAdd(&C[(size_t)tokB * H_ + col],     wB * acc[mf][nf][2]);
                    atomicAdd(&C[(size_t)tokB * H_ + col + 1], wB * acc[mf][nf][3]);
                }
            }
        } else {
            #pragma unroll
            for (int nf = 0; nf < 4; nf++) {
                int col = n0 + warp_n * 32 + nf * 8 + lc;
                if (r0g < Mlim) {
                    float2 v = make_float2(acc[mf][nf][0], acc[mf][nf][1]);
                    if (EPI == 1) {
                        const float* a2 = addsrc + (size_t)r0g * ldc + col;
                        v.x += a2[0]; v.y += a2[1];
                    }
                    *(float2*)(Ce + (size_t)r0g * ldc + col) = v;
                }
                if (r1g < Mlim) {
                    float2 v = make_float2(acc[mf][nf][2], acc[mf][nf][3]);
                    if (EPI == 1) {
                        const float* a2 = addsrc + (size_t)r1g * ldc + col;
                        v.x += a2[0]; v.y += a2[1];
                    }
                    *(float2*)(Ce + (size_t)r1g * ldc + col) = v;
                }
            }
        }
    }
}

// ---------------------------------------------------------------------------
__global__ void split_kernel(const float* __restrict__ src,
                             bf16* __restrict__ h, bf16* __restrict__ l,
                             size_t n4) {
    size_t i = (size_t)blockIdx.x * blockDim.x + threadIdx.x;
    if (i >= n4) return;
    float4 v = ((const float4*)src)[i];
    split_store4(v, h + i * 4, l + i * 4);
}

// silu(g)*u -> bf16 hi/lo, gathered rows only
__global__ void act_kernel(const float* __restrict__ gu,
                           const int* __restrict__ counts,
                           bf16* __restrict__ ah, bf16* __restrict__ al) {
    int e = blockIdx.z, slot = blockIdx.y;
    if (slot >= counts[e]) return;
    const float* row = gu + ((size_t)e * S_ + slot) * (2 * I_);
    bf16* hr = ah + ((size_t)e * S_ + slot) * I_;
    bf16* lr = al + ((size_t)e * S_ + slot) * I_;
    for (int i = threadIdx.x * 4; i < I_; i += blockDim.x * 4) {
        float4 g = *(const float4*)(row + i);
        float4 u = *(const float4*)(row + I_ + i);
        float4 a;
        a.x = g.x / (1.f + __expf(-g.x)) * u.x;
        a.y = g.y / (1.f + __expf(-g.y)) * u.y;
        a.z = g.z / (1.f + __expf(-g.z)) * u.z;
        a.w = g.w / (1.f + __expf(-g.w)) * u.w;
        split_store4(a, hr + i, lr + i);
    }
}

// ---------------------------------------------------------------------------
__global__ void zero_kernel(float* out, int* counts) {
    int i = blockIdx.x * blockDim.x + threadIdx.x;
    if (i < S_ * H_) out[i] = 0.0f;
    if (i < E_) counts[i] = 0;
}

// RMSNorm emitting fp32 (optional) + bf16 hi/lo planes
__global__ void rmsnorm_hl(const float* __restrict__ x,
                           const float* __restrict__ w,
                           float* __restrict__ y,
                           bf16* __restrict__ yh, bf16* __restrict__ yl) {
    int row = blockIdx.x;
    int tid = threadIdx.x;
    __shared__ float red[256];
    const float* xr = x + (size_t)row * H_;
    float s = 0.0f;
    for (int c = tid; c < H_; c += 256) { float v = xr[c]; s += v * v; }
    red[tid] = s; __syncthreads();
    for (int o = 128; o > 0; o >>= 1) {
        if (tid < o) red[tid] += red[tid + o];
        __syncthreads();
    }
    float inv = rsqrtf(red[0] / (float)H_ + EPS_);
    for (int c = tid * 4; c < H_; c += 1024) {
        float4 v = *(const float4*)(xr + c);
        float4 wv = *(const float4*)(w + c);
        v.x *= inv * wv.x; v.y *= inv * wv.y;
        v.z *= inv * wv.z; v.w *= inv * wv.w;
        if (y) *(float4*)(y + (size_t)row * H_ + c) = v;
        split_store4(v, yh + (size_t)row * H_ + c, yl + (size_t)row * H_ + c);
    }
}

// ---------------------------------------------------------------------------
// Flash attention (fp32), epilogue writes bf16 hi/lo planes directly
// ---------------------------------------------------------------------------
__global__ __launch_bounds__(256)
void attn_flash(const float* __restrict__ qkv,
                bf16* __restrict__ oh, bf16* __restrict__ ol) {
    extern __shared__ float smf[];
    float* Qs  = smf;
    float* KPs = smf + 64 * 64;
    float* Vs  = smf + 64 * 64 + 64 * 68;

    int qt = blockIdx.x, h = blockIdx.y;
    int q0 = qt * 64;
    int kvh = h >> 2;
    int tid = threadIdx.x;
    int tx = tid & 15, ty = tid >> 4;

    #pragma unroll
    for (int l = 0; l < 4; l++) {
        int idx = tid + l * 256;
        int r = idx >> 4, dq = (idx & 15) * 4;
        *(float4*)&Qs[r * 64 + dq] =
            *(const float4*)&qkv[(size_t)(q0 + r) * QKV_O + h * 64 + dq];
    }

    float acc[4][4] = {};
    float rm[4], rl[4];
    #pragma unroll
    for (int i = 0; i < 4; i++) { rm[i] = -1e30f; rl[i] = 0.f; }

    int t0 = (q0 > 511) ? ((q0 - 511) >> 6) : 0;
    for (int kt = t0; kt <= qt; kt++) {
        int j0 = kt * 64;
        __syncthreads();
        #pragma unroll
        for (int l = 0; l < 4; l++) {
            int idx = tid + l * 256;
            int r = idx >> 4, dq = (idx & 15) * 4;
            *(float4*)&KPs[r * 68 + dq] =
                *(const float4*)&qkv[(size_t)(j0 + r) * QKV_O + H_ + kvh * 64 + dq];
            *(float4*)&Vs[r * 64 + dq] =
                *(const float4*)&qkv[(size_t)(j0 + r) * QKV_O + H_ + NKV_ * HD_ + kvh * 64 + dq];
        }
        __syncthreads();

        float s[4][4] = {};
        #pragma unroll
        for (int d0 = 0; d0 < 64; d0 += 4) {
            float4 q4[4], k4[4];
            #pragma unroll
            for (int i = 0; i < 4; i++) q4[i] = *(const float4*)&Qs[(ty * 4 + i) * 64 + d0];
            #pragma unroll
            for (int j = 0; j < 4; j++) k4[j] = *(const float4*)&KPs[(tx + 16 * j) * 68 + d0];
            #pragma unroll
            for (int i = 0; i < 4; i++)
                #pragma unroll
                for (int j = 0; j < 4; j++)
                    s[i][j] += q4[i].x * k4[j].x + q4[i].y * k4[j].y
                             + q4[i].z * k4[j].z + q4[i].w * k4[j].w;
        }
        __syncthreads();

        float p[4][4];
        #pragma unroll
        for (int i = 0; i < 4; i++) {
            int iq = q0 + ty * 4 + i;
            float tm = -1e30f;
            #pragma unroll
            for (int j = 0; j < 4; j++) {
                int jk = j0 + tx + 16 * j;
                bool ok = (jk <= iq) && (iq - jk < WIN_);
                s[i][j] = ok ? s[i][j] * 0.125f : -1e30f;
                tm = fmaxf(tm, s[i][j]);
            }
            #pragma unroll
            for (int o = 1; o < 16; o <<= 1)
                tm = fmaxf(tm, __shfl_xor_sync(0xffffffffu, tm, o));
            float mn = fmaxf(rm[i], tm);
            float alpha = __expf(rm[i] - mn);
            rm[i] = mn;
            float ps = 0.f;
            #pragma unroll
            for (int j = 0; j < 4; j++) { p[i][j] = __expf(s[i][j] - mn); ps += p[i][j]; }
            #pragma unroll
            for (int o = 1; o < 16; o <<= 1)
                ps += __shfl_xor_sync(0xffffffffu, ps, o);
            rl[i] = rl[i] * alpha + ps;
            #pragma unroll
            for (int j = 0; j < 4; j++) acc[i][j] *= alpha;
            #pragma unroll
            for (int j = 0; j < 4; j++)
                KPs[(ty * 4 + i) * 68 + tx + 16 * j] = p[i][j];
        }
        __syncthreads();

        #pragma unroll 4
        for (int n = 0; n < 64; n++) {
            float pv[4], vv[4];
            #pragma unroll
            for (int i = 0; i < 4; i++) pv[i] = KPs[(ty * 4 + i) * 68 + n];
            #pragma unroll
            for (int j = 0; j < 4; j++) vv[j] = Vs[n * 64 + tx + 16 * j];
            #pragma unroll
            for (int i = 0; i < 4; i++)
                #pragma unroll
                for (int j = 0; j < 4; j++)
                    acc[i][j] += pv[i] * vv[j];
        }
    }

    #pragma unroll
    for (int i = 0; i < 4; i++) {
        float inv = 1.0f / rl[i];
        size_t base = (size_t)(q0 + ty * 4 + i) * H_ + h * 64;
        #pragma unroll
        for (int j = 0; j < 4; j++) {
            float v = acc[i][j] * inv;
            bf16 hb = __float2bfloat16(v);
            bf16 lb = __float2bfloat16(v - __bfloat162float(hb));
            oh[base + tx + 16 * j] = hb;
            ol[base + tx + 16 * j] = lb;
        }
    }
}

// ---------------------------------------------------------------------------
__global__ void router_kernel(const float* __restrict__ t,
                              const float* __restrict__ rw,
                              int* counts, int* toklist, float* tokw) {
    int warp = threadIdx.x >> 5;
    int lane = threadIdx.x & 31;
    int tok = blockIdx.x * 8 + warp;
    if (tok >= S_) return;
    const float* tr = t + (size_t)tok * H_;
    float logits[E_];
    for (int e = 0; e < E_; e++) {
        float s = 0.0f;
        for (int k = lane; k < H_; k += 32) s += tr[k] * rw[e * H_ + k];
        for (int o = 16; o > 0; o >>= 1) s += __shfl_xor_sync(0xffffffff, s, o);
        logits[e] = s;
    }
    if (lane == 0) {
        float mx = logits[0];
        for (int e = 1; e < E_; e++) mx = fmaxf(mx, logits[e]);
        float p[E_], sum = 0.0f;
        for (int e = 0; e < E_; e++) { p[e] = __expf(logits[e] - mx); sum += p[e]; }
        float invs = 1.0f / sum;
        for (int e = 0; e < E_; e++) p[e] *= invs;
        int b1 = 0;
        for (int e = 1; e < E_; e++) if (p[e] > p[b1]) b1 = e;
        int b2 = -1;
        for (int e = 0; e < E_; e++) {
            if (e == b1) continue;
            if (b2 < 0 || p[e] > p[b2]) b2 = e;
        }
        int pos1 = atomicAdd(&counts[b1], 1);
        toklist[b1 * S_ + pos1] = tok; tokw[b1 * S_ + pos1] = p[b1];
        int pos2 = atomicAdd(&counts[b2], 1);
        toklist[b2 * S_ + pos2] = tok; tokw[b2 * S_ + pos2] = p[b2];
    }
}

// ---------------------------------------------------------------------------
extern "C" void kernel_launch(void* const* d_in, const int* in_sizes, int n_in,
                              void* d_out, int out_size) {
    const float* hidden   = (const float*)d_in[0];
    const float* w_qkv    = (const float*)d_in[2];
    const float* w_o      = (const float*)d_in[3];
    const float* router_w = (const float*)d_in[4];
    const float* ws       = (const float*)d_in[5];
    const float* w2s      = (const float*)d_in[6];
    const float* ln1      = (const float*)d_in[7];
    const float* ln2      = (const float*)d_in[8];

    float* out    = (float*)d_out;
    float* resid2 = out + (size_t)S_ * H_;

    bf16 *wqh, *wql, *woh, *wol, *wsh, *wsl, *w2h, *w2l;
    bf16 *xnh, *xnl, *ath, *atl, *tnh, *tnl, *ach, *acl;
    float *qkv, *tnorm, *gu, *tokw;
    int *counts, *toklist;
    cudaGetSymbolAddress((void**)&wqh, g_wqkv_h); cudaGetSymbolAddress((void**)&wql, g_wqkv_l);
    cudaGetSymbolAddress((void**)&woh, g_wo_h);   cudaGetSymbolAddress((void**)&wol, g_wo_l);
    cudaGetSymbolAddress((void**)&wsh, g_ws_h);   cudaGetSymbolAddress((void**)&wsl, g_ws_l);
    cudaGetSymbolAddress((void**)&w2h, g_w2s_h);  cudaGetSymbolAddress((void**)&w2l, g_w2s_l);
    cudaGetSymbolAddress((void**)&xnh, g_xn_h);   cudaGetSymbolAddress((void**)&xnl, g_xn_l);
    cudaGetSymbolAddress((void**)&ath, g_at_h);   cudaGetSymbolAddress((void**)&atl, g_at_l);
    cudaGetSymbolAddress((void**)&tnh, g_tn_h);   cudaGetSymbolAddress((void**)&tnl, g_tn_l);
    cudaGetSymbolAddress((void**)&ach, g_act_h);  cudaGetSymbolAddress((void**)&acl, g_act_l);
    cudaGetSymbolAddress((void**)&qkv,   g_qkv);
    cudaGetSymbolAddress((void**)&tnorm, g_tnorm);
    cudaGetSymbolAddress((void**)&gu,    g_gu);
    cudaGetSymbolAddress((void**)&counts, g_counts);
    cudaGetSymbolAddress((void**)&toklist, g_toklist);
    cudaGetSymbolAddress((void**)&tokw,  g_tokw);

    const int GSMEM = 65536;
    cudaFuncSetAttribute(hmma2<0,0>, cudaFuncAttributeMaxDynamicSharedMemorySize, GSMEM);
    cudaFuncSetAttribute(hmma2<0,1>, cudaFuncAttributeMaxDynamicSharedMemorySize, GSMEM);
    cudaFuncSetAttribute(hmma2<1,0>, cudaFuncAttributeMaxDynamicSharedMemorySize, GSMEM);
    cudaFuncSetAttribute(hmma2<0,2>, cudaFuncAttributeMaxDynamicSharedMemorySize, GSMEM);
    int attn_smem = (64 * 64 + 64 * 68 + 64 * 64) * 4;
    cudaFuncSetAttribute(attn_flash, cudaFuncAttributeMaxDynamicSharedMemorySize, attn_smem);

    zero_kernel<<<(S_ * H_ + 255) / 256, 256>>>(out, counts);

    // weight split prepass
    split_kernel<<<(QKV_O * H_ / 4 + 255) / 256, 256>>>(w_qkv, wqh, wql, QKV_O * H_ / 4);
    split_kernel<<<(H_ * H_ / 4 + 255) / 256, 256>>>(w_o, woh, wol, H_ * H_ / 4);
    split_kernel<<<(int)(((size_t)E_ * 2 * I_ * H_ / 4 + 255) / 256), 256>>>(
        ws, wsh, wsl, (size_t)E_ * 2 * I_ * H_ / 4);
    split_kernel<<<(int)(((size_t)E_ * H_ * I_ / 4 + 255) / 256), 256>>>(
        w2s, w2h, w2l, (size_t)E_ * H_ * I_ / 4);

    rmsnorm_hl<<<S_, 256>>>(hidden, ln1, nullptr, xnh, xnl);

    // QKV
    hmma2<0,0><<<dim3(QKV_O / 128, S_ / 128, 1), 256, GSMEM>>>(
        xnh, xnl, wqh, wql, qkv, S_, QKV_O, H_, H_, QKV_O,
        nullptr, nullptr, nullptr, nullptr, 0, 0, 0);

    attn_flash<<<dim3(S_ / 64, NH_), 256, attn_smem>>>(qkv, ath, atl);

    // O proj + residual
    hmma2<0,1><<<dim3(H_ / 128, S_ / 128, 1), 256, GSMEM>>>(
        ath, atl, woh, wol, resid2, S_, H_, H_, H_, H_,
        hidden, nullptr, nullptr, nullptr, 0, 0, 0);

    rmsnorm_hl<<<S_, 256>>>(resid2, ln2, tnorm, tnh, tnl);
    router_kernel<<<S_ / 8, 256>>>(tnorm, router_w, counts, toklist, tokw);

    // MoE up+gate (gathered A)
    hmma2<1,0><<<dim3(2 * I_ / 128, S_ / 128, E_), 256, GSMEM>>>(
        tnh, tnl, wsh, wsl, gu, S_, 2 * I_, H_, H_, 2 * I_,
        nullptr, counts, toklist, nullptr,
        0, (size_t)2 * I_ * H_, (size_t)S_ * 2 * I_);

    act_kernel<<<dim3(1, S_, E_), 256>>>(gu, counts, ach, acl);

    // MoE down (weighted scatter)
    hmma2<0,2><<<dim3(H_ / 128, S_ / 128, E_), 256, GSMEM>>>(
        ach, acl, w2h, w2l, out, S_, H_, I_, I_, H_,
        nullptr, counts, toklist, tokw,
        (size_t)S_ * I_, (size_t)H_ * I_, 0);
}

// round 7
// speedup vs baseline: 4.5927x; 1.0075x over previous
#include <cuda_runtime.h>
#include <cuda_bf16.h>
#include <math.h>
#include <stdint.h>

#define S_  2048
#define H_  1024
#define NH_ 16
#define NKV_ 4
#define HD_ 64
#define QKV_O 1536
#define I_  2816
#define E_  8
#define WIN_ 512
#define EPS_ 1e-5f

typedef __nv_bfloat16 bf16;

// ---------------------------------------------------------------------------
// Scratch (static device globals)
// ---------------------------------------------------------------------------
__device__ bf16 g_wqkv_h[QKV_O * H_],            g_wqkv_l[QKV_O * H_];
__device__ bf16 g_wo_h[H_ * H_],                 g_wo_l[H_ * H_];
__device__ bf16 g_ws_h[(size_t)E_ * 2 * I_ * H_], g_ws_l[(size_t)E_ * 2 * I_ * H_];
__device__ bf16 g_w2s_h[(size_t)E_ * H_ * I_],    g_w2s_l[(size_t)E_ * H_ * I_];
__device__ bf16 g_xn_h[S_ * H_],  g_xn_l[S_ * H_];
__device__ bf16 g_at_h[S_ * H_],  g_at_l[S_ * H_];
__device__ bf16 g_tn_h[S_ * H_],  g_tn_l[S_ * H_];
__device__ bf16 g_act_h[(size_t)E_ * S_ * I_],    g_act_l[(size_t)E_ * S_ * I_];
__device__ float g_qkv[S_ * QKV_O];
__device__ float g_tnorm[S_ * H_];
__device__ int   g_counts[E_];
__device__ int   g_toklist[E_ * S_];
__device__ float g_tokw[E_ * S_];

// ---------------------------------------------------------------------------
__device__ __forceinline__ uint32_t smem_u32(const void* p) {
    uint32_t a;
    asm("{ .reg .u64 t; cvta.to.shared.u64 t, %1; cvt.u32.u64 %0, t; }"
        : "=r"(a) : "l"(p));
    return a;
}
__device__ __forceinline__ void ldm4(uint32_t& r0, uint32_t& r1,
                                     uint32_t& r2, uint32_t& r3, uint32_t addr) {
    asm volatile("ldmatrix.sync.aligned.m8n8.x4.shared.b16 {%0,%1,%2,%3}, [%4];"
                 : "=r"(r0), "=r"(r1), "=r"(r2), "=r"(r3) : "r"(addr));
}
__device__ __forceinline__ void mma16816(float* d, const uint32_t* a,
                                         const uint32_t* b) {
    asm volatile(
        "mma.sync.aligned.m16n8k16.row.col.f32.bf16.bf16.f32 "
        "{%0,%1,%2,%3}, {%4,%5,%6,%7}, {%8,%9}, {%0,%1,%2,%3};"
        : "+f"(d[0]), "+f"(d[1]), "+f"(d[2]), "+f"(d[3])
        : "r"(a[0]), "r"(a[1]), "r"(a[2]), "r"(a[3]), "r"(b[0]), "r"(b[1]));
}
__device__ __forceinline__ void cp16(uint32_t dst, const void* src, int sz) {
    asm volatile("cp.async.cg.shared.global [%0], [%1], 16, %2;"
                 :: "r"(dst), "l"(src), "r"(sz));
}
__device__ __forceinline__ void cp_commit() {
    asm volatile("cp.async.commit_group;");
}
__device__ __forceinline__ void cp_wait0() {
    asm volatile("cp.async.wait_group 0;");
}

// split fp32 float4 -> bf16 hi/lo (8B each)
__device__ __forceinline__ void split_store4(float4 v, bf16* hp, bf16* lp) {
    __nv_bfloat162 h01 = __floats2bfloat162_rn(v.x, v.y);
    __nv_bfloat162 h23 = __floats2bfloat162_rn(v.z, v.w);
    float2 f01 = __bfloat1622float2(h01);
    float2 f23 = __bfloat1622float2(h23);
    __nv_bfloat162 l01 = __floats2bfloat162_rn(v.x - f01.x, v.y - f01.y);
    __nv_bfloat162 l23 = __floats2bfloat162_rn(v.z - f23.x, v.w - f23.y);
    *(uint2*)hp = make_uint2(*(uint32_t*)&h01, *(uint32_t*)&h23);
    *(uint2*)lp = make_uint2(*(uint32_t*)&l01, *(uint32_t*)&l23);
}
__device__ __forceinline__ void split1(float v, bf16* hp, bf16* lp) {
    bf16 hb = __float2bfloat16(v);
    *hp = hb;
    *lp = __float2bfloat16(v - __bfloat162float(hb));
}

// ---------------------------------------------------------------------------
// HMMA GEMM, bf16 3-term split planes. CTA tile 128x128, BK=32, 8 warps.
// cp.async double-buffered, 2 CTAs/SM.
// GATHER: A rows via toklist.
// EPI: 0=store 1=+addsrc 2=weighted scatter 3=swiglu->act bf16 planes
// (EPI 3 requires ws permuted so each 128-tile = 64 gate rows | 64 up rows)
// ---------------------------------------------------------------------------
template<int GATHER, int EPI>
__global__ __launch_bounds__(256, 2)
void hmma2(const bf16* __restrict__ Ah, const bf16* __restrict__ Al,
           const bf16* __restrict__ Bh, const bf16* __restrict__ Bl,
           float* __restrict__ C, int M, int N, int K, int lda, int ldc,
           const float* __restrict__ addsrc,
           const int* __restrict__ counts,
           const int* __restrict__ toklist,
           const float* __restrict__ tokw,
           bf16* __restrict__ actH, bf16* __restrict__ actL,
           size_t sA, size_t sB, size_t sC)
{
    extern __shared__ char smem[];     // 2 stages x 4 planes x 8KB = 64KB
    __shared__ int rowsS[128];

    int e = blockIdx.z;
    int Mlim = counts ? counts[e] : M;
    int m0 = blockIdx.y * 128;
    if (m0 >= Mlim) return;
    int n0 = blockIdx.x * 128;
    const bf16* Ahe = Ah + sA * e;
    const bf16* Ale = Al + sA * e;
    const bf16* Bhe = Bh + sB * e;
    const bf16* Ble = Bl + sB * e;
    float*      Ce  = C ? C + sC * e : nullptr;

    int tid = threadIdx.x;
    int wid = tid >> 5;
    int lane = tid & 31;
    int warp_m = wid & 1;
    int warp_n = wid >> 1;

    if (GATHER) {
        if (tid < 128)
            rowsS[tid] = (m0 + tid < Mlim) ? toklist[e * S_ + m0 + tid] : -1;
        __syncthreads();
    }

    uint32_t sbase = smem_u32(smem);

    auto issue = [&](int c, int buf) {
        int k0 = c * 32;
        #pragma unroll
        for (int l = 0; l < 8; l++) {
            int seg = tid + l * 256;
            int plane = seg >> 9;            // 0=Ah 1=Al 2=Bh 3=Bl
            int row = (seg >> 2) & 127;
            int ch = seg & 3;
            uint32_t dst = sbase + buf * 32768 + plane * 8192
                         + row * 64 + ((ch ^ ((row >> 1) & 3)) << 4);
            const bf16* gsrc;
            int sz = 16;
            if (plane < 2) {
                int gr;
                if (GATHER) {
                    gr = rowsS[row];
                    if (gr < 0) { gr = 0; sz = 0; }
                } else {
                    gr = m0 + row;
                    if (gr >= Mlim) { gr = 0; sz = 0; }
                }
                gsrc = (plane ? Ale : Ahe) + (size_t)gr * lda + k0 + ch * 8;
            } else {
                gsrc = ((plane == 3) ? Ble : Bhe) + (size_t)(n0 + row) * K + k0 + ch * 8;
            }
            cp16(dst, gsrc, sz);
        }
        cp_commit();
    };

    float acc[4][4][4] = {};
    const int nc = K / 32;
    issue(0, 0);

    for (int c = 0; c < nc; c++) {
        cp_wait0();
        __syncthreads();
        if (c + 1 < nc) issue(c + 1, (c + 1) & 1);

        uint32_t sb = sbase + (c & 1) * 32768;
        int mi = lane >> 3, r = lane & 7;

        #pragma unroll
        for (int ks = 0; ks < 2; ks++) {
            uint32_t afh[4][4], bfh[4][2];
            #pragma unroll
            for (int nfp = 0; nfp < 2; nfp++) {
                int n = warp_n * 32 + nfp * 16 + ((mi >> 1) << 3) + r;
                int ch = ks * 2 + (mi & 1);
                uint32_t off = (uint32_t)(n * 64 + ((ch ^ ((n >> 1) & 3)) << 4));
                uint32_t r0, r1, r2, r3;
                ldm4(r0, r1, r2, r3, sb + 2 * 8192 + off);
                bfh[nfp * 2 + 0][0] = r0; bfh[nfp * 2 + 0][1] = r1;
                bfh[nfp * 2 + 1][0] = r2; bfh[nfp * 2 + 1][1] = r3;
            }
            #pragma unroll
            for (int mf = 0; mf < 4; mf++) {
                int row = warp_m * 64 + mf * 16 + ((mi & 1) << 3) + r;
                int ch = ks * 2 + (mi >> 1);
                uint32_t off = (uint32_t)(row * 64 + ((ch ^ ((row >> 1) & 3)) << 4));
                ldm4(afh[mf][0], afh[mf][1], afh[mf][2], afh[mf][3], sb + off);
            }
            #pragma unroll
            for (int mf = 0; mf < 4; mf++)
                #pragma unroll
                for (int nf = 0; nf < 4; nf++)
                    mma16816(acc[mf][nf], afh[mf], bfh[nf]);

            {
                uint32_t bfl[4][2];
                #pragma unroll
                for (int nfp = 0; nfp < 2; nfp++) {
                    int n = warp_n * 32 + nfp * 16 + ((mi >> 1) << 3) + r;
                    int ch = ks * 2 + (mi & 1);
                    uint32_t off = (uint32_t)(n * 64 + ((ch ^ ((n >> 1) & 3)) << 4));
                    uint32_t r0, r1, r2, r3;
                    ldm4(r0, r1, r2, r3, sb + 3 * 8192 + off);
                    bfl[nfp * 2 + 0][0] = r0; bfl[nfp * 2 + 0][1] = r1;
                    bfl[nfp * 2 + 1][0] = r2; bfl[nfp * 2 + 1][1] = r3;
                }
                #pragma unroll
                for (int mf = 0; mf < 4; mf++)
                    #pragma unroll
                    for (int nf = 0; nf < 4; nf++)
                        mma16816(acc[mf][nf], afh[mf], bfl[nf]);
            }
            {
                uint32_t afl[4][4];
                #pragma unroll
                for (int mf = 0; mf < 4; mf++) {
                    int row = warp_m * 64 + mf * 16 + ((mi & 1) << 3) + r;
                    int ch = ks * 2 + (mi >> 1);
                    uint32_t off = (uint32_t)(row * 64 + ((ch ^ ((row >> 1) & 3)) << 4));
                    ldm4(afl[mf][0], afl[mf][1], afl[mf][2], afl[mf][3], sb + 8192 + off);
                }
                #pragma unroll
                for (int mf = 0; mf < 4; mf++)
                    #pragma unroll
                    for (int nf = 0; nf < 4; nf++)
                        mma16816(acc[mf][nf], afl[mf], bfh[nf]);
            }
        }
    }

    // ---------------- epilogue ----------------
    int lr = lane >> 2;
    int lc = (lane & 3) * 2;

    if (EPI == 3) {
        // swiglu: tile cols [0,64)=gate (warp_n 0,1), [64,128)=up (warp_n 2,3)
        __syncthreads();                       // mainloop smem reads done
        float (*Us)[65] = (float (*)[65])smem; // 128 x 65 fp32 = 33.3KB
        if (warp_n >= 2) {
            #pragma unroll
            for (int mf = 0; mf < 4; mf++) {
                int rl0 = warp_m * 64 + mf * 16 + lr;
                #pragma unroll
                for (int nf = 0; nf < 4; nf++) {
                    int j = (warp_n - 2) * 32 + nf * 8 + lc;
                    Us[rl0][j]         = acc[mf][nf][0];
                    Us[rl0][j + 1]     = acc[mf][nf][1];
                    Us[rl0 + 8][j]     = acc[mf][nf][2];
                    Us[rl0 + 8][j + 1] = acc[mf][nf][3];
                }
            }
        }
        __syncthreads();
        if (warp_n < 2) {
            int colbase = n0 >> 1;             // tile t covers act cols t*64..
            #pragma unroll
            for (int mf = 0; mf < 4; mf++) {
                int rl0 = warp_m * 64 + mf * 16 + lr;
                #pragma unroll
                for (int half = 0; half < 2; half++) {
                    int rl = rl0 + half * 8;
                    int m = m0 + rl;
                    if (m >= Mlim) continue;
                    size_t rowoff = ((size_t)e * S_ + m) * I_ + colbase;
                    #pragma unroll
                    for (int nf = 0; nf < 4; nf++) {
                        int j = warp_n * 32 + nf * 8 + lc;
                        #pragma unroll
                        for (int q = 0; q < 2; q++) {
                            float g = acc[mf][nf][half * 2 + q];
                            float u = Us[rl][j + q];
                            float a = g / (1.f + __expf(-g)) * u;
                            split1(a, &actH[rowoff + j + q], &actL[rowoff + j + q]);
                        }
                    }
                }
            }
        }
        return;
    }

    #pragma unroll
    for (int mf = 0; mf < 4; mf++) {
        int r0g = m0 + warp_m * 64 + mf * 16 + lr;
        int r1g = r0g + 8;
        if (EPI == 2) {
            int tokA = 0, tokB = 0; float wA = 0.f, wB = 0.f;
            bool vA = (r0g < Mlim), vB = (r1g < Mlim);
            if (vA) { tokA = toklist[e * S_ + r0g]; wA = tokw[e * S_ + r0g]; }
            if (vB) { tokB = toklist[e * S_ + r1g]; wB = tokw[e * S_ + r1g]; }
            #pragma unroll
            for (int nf = 0; nf < 4; nf++) {
                int col = n0 + warp_n * 32 + nf * 8 + lc;
                if (vA) {
                    atomicAdd(&C[(size_t)tokA * H_ + col],     wA * acc[mf][nf][0]);
                    atomicAdd(&C[(size_t)tokA * H_ + col + 1], wA * acc[mf][nf][1]);
                }
                if (vB) {
                    atomicAdd(&C[(size_t)tokB * H_ + col],     wB * acc[mf][nf][2]);
                    atomicAdd(&C[(size_t)tokB * H_ + col + 1], wB * acc[mf][nf][3]);
                }
            }
        } else {
            #pragma unroll
            for (int nf = 0; nf < 4; nf++) {
                int col = n0 + warp_n * 32 + nf * 8 + lc;
                if (r0g < Mlim) {
                    float2 v = make_float2(acc[mf][nf][0], acc[mf][nf][1]);
                    if (EPI == 1) {
                        const float* a2 = addsrc + (size_t)r0g * ldc + col;
                        v.x += a2[0]; v.y += a2[1];
                    }
                    *(float2*)(Ce + (size_t)r0g * ldc + col) = v;
                }
                if (r1g < Mlim) {
                    float2 v = make_float2(acc[mf][nf][2], acc[mf][nf][3]);
                    if (EPI == 1) {
                        const float* a2 = addsrc + (size_t)r1g * ldc + col;
                        v.x += a2[0]; v.y += a2[1];
                    }
                    *(float2*)(Ce + (size_t)r1g * ldc + col) = v;
                }
            }
        }
    }
}

// ---------------------------------------------------------------------------
__global__ void split_kernel(const float* __restrict__ src,
                             bf16* __restrict__ h, bf16* __restrict__ l,
                             size_t n4) {
    size_t i = (size_t)blockIdx.x * blockDim.x + threadIdx.x;
    if (i >= n4) return;
    float4 v = ((const float4*)src)[i];
    split_store4(v, h + i * 4, l + i * 4);
}

// ws split with gate/up interleave permutation:
// dest row p (tile t=p/128, r=p%128): src = r<64 ? t*64+r : I + t*64 + (r-64)
__global__ void split_ws_perm(const float* __restrict__ ws,
                              bf16* __restrict__ h, bf16* __restrict__ l) {
    int e = blockIdx.z, p = blockIdx.y;
    int t = p >> 7, r = p & 127;
    int src = (r < 64) ? (t * 64 + r) : (I_ + t * 64 + (r - 64));
    const float* srow = ws + ((size_t)e * 2 * I_ + src) * H_;
    bf16* hr = h + ((size_t)e * 2 * I_ + p) * H_;
    bf16* lr = l + ((size_t)e * 2 * I_ + p) * H_;
    int i = threadIdx.x * 4;
    float4 v = *(const float4*)(srow + i);
    split_store4(v, hr + i, lr + i);
}

// ---------------------------------------------------------------------------
__global__ void zero_kernel(float* out, int* counts) {
    int i = blockIdx.x * blockDim.x + threadIdx.x;
    if (i < S_ * H_) out[i] = 0.0f;
    if (i < E_) counts[i] = 0;
}

__global__ void rmsnorm_hl(const float* __restrict__ x,
                           const float* __restrict__ w,
                           float* __restrict__ y,
                           bf16* __restrict__ yh, bf16* __restrict__ yl) {
    int row = blockIdx.x;
    int tid = threadIdx.x;
    __shared__ float red[256];
    const float* xr = x + (size_t)row * H_;
    float s = 0.0f;
    for (int c = tid; c < H_; c += 256) { float v = xr[c]; s += v * v; }
    red[tid] = s; __syncthreads();
    for (int o = 128; o > 0; o >>= 1) {
        if (tid < o) red[tid] += red[tid + o];
        __syncthreads();
    }
    float inv = rsqrtf(red[0] / (float)H_ + EPS_);
    for (int c = tid * 4; c < H_; c += 1024) {
        float4 v = *(const float4*)(xr + c);
        float4 wv = *(const float4*)(w + c);
        v.x *= inv * wv.x; v.y *= inv * wv.y;
        v.z *= inv * wv.z; v.w *= inv * wv.w;
        if (y) *(float4*)(y + (size_t)row * H_ + c) = v;
        split_store4(v, yh + (size_t)row * H_ + c, yl + (size_t)row * H_ + c);
    }
}

// ---------------------------------------------------------------------------
// Flash attention (fp32): 128 threads, 8x4 register tile, bf16 hi/lo output
// ---------------------------------------------------------------------------
__global__ __launch_bounds__(128)
void attn_flash(const float* __restrict__ qkv,
                bf16* __restrict__ oh, bf16* __restrict__ ol) {
    extern __shared__ float smf[];
    float* Qs  = smf;                      // [64][64]
    float* KPs = smf + 4096;               // [64][68]
    float* Vs  = smf + 4096 + 64 * 68;     // [64][64]

    int qt = blockIdx.x, h = blockIdx.y;
    int q0 = qt * 64;
    int kvh = h >> 2;
    int tid = threadIdx.x;
    int tx = tid & 15, ty = tid >> 4;      // ty 0..7

    #pragma unroll
    for (int l = 0; l < 8; l++) {
        int idx = tid + l * 128;
        int r = idx >> 4, dq = (idx & 15) * 4;
        *(float4*)&Qs[r * 64 + dq] =
            *(const float4*)&qkv[(size_t)(q0 + r) * QKV_O + h * 64 + dq];
    }

    float acc[8][4] = {};
    float rm[8], rl[8];
    #pragma unroll
    for (int i = 0; i < 8; i++) { rm[i] = -1e30f; rl[i] = 0.f; }

    int t0 = (q0 > 511) ? ((q0 - 511) >> 6) : 0;
    for (int kt = t0; kt <= qt; kt++) {
        int j0 = kt * 64;
        __syncthreads();
        #pragma unroll
        for (int l = 0; l < 8; l++) {
            int idx = tid + l * 128;
            int r = idx >> 4, dq = (idx & 15) * 4;
            *(float4*)&KPs[r * 68 + dq] =
                *(const float4*)&qkv[(size_t)(j0 + r) * QKV_O + H_ + kvh * 64 + dq];
            *(float4*)&Vs[r * 64 + dq] =
                *(const float4*)&qkv[(size_t)(j0 + r) * QKV_O + H_ + NKV_ * HD_ + kvh * 64 + dq];
        }
        __syncthreads();

        float s[8][4] = {};
        #pragma unroll
        for (int d0 = 0; d0 < 64; d0 += 4) {
            float4 k4[4];
            #pragma unroll
            for (int j = 0; j < 4; j++) k4[j] = *(const float4*)&KPs[(tx + 16 * j) * 68 + d0];
            #pragma unroll
            for (int i = 0; i < 8; i++) {
                float4 q4 = *(const float4*)&Qs[(ty * 8 + i) * 64 + d0];
                #pragma unroll
                for (int j = 0; j < 4; j++)
                    s[i][j] += q4.x * k4[j].x + q4.y * k4[j].y
                             + q4.z * k4[j].z + q4.w * k4[j].w;
            }
        }
        __syncthreads();

        #pragma unroll
        for (int i = 0; i < 8; i++) {
            int iq = q0 + ty * 8 + i;
            float p[4];
            float tm = -1e30f;
            #pragma unroll
            for (int j = 0; j < 4; j++) {
                int jk = j0 + tx + 16 * j;
                bool ok = (jk <= iq) && (iq - jk < WIN_);
                s[i][j] = ok ? s[i][j] * 0.125f : -1e30f;
                tm = fmaxf(tm, s[i][j]);
            }
            #pragma unroll
            for (int o = 1; o < 16; o <<= 1)
                tm = fmaxf(tm, __shfl_xor_sync(0xffffffffu, tm, o));
            float mn = fmaxf(rm[i], tm);
            float alpha = __expf(rm[i] - mn);
            rm[i] = mn;
            float ps = 0.f;
            #pragma unroll
            for (int j = 0; j < 4; j++) { p[j] = __expf(s[i][j] - mn); ps += p[j]; }
            #pragma unroll
            for (int o = 1; o < 16; o <<= 1)
                ps += __shfl_xor_sync(0xffffffffu, ps, o);
            rl[i] = rl[i] * alpha + ps;
            #pragma unroll
            for (int j = 0; j < 4; j++) {
                acc[i][j] *= alpha;
                KPs[(ty * 8 + i) * 68 + tx + 16 * j] = p[j];
            }
        }
        __syncthreads();

        #pragma unroll 2
        for (int n = 0; n < 64; n += 2) {
            float2 pv[8];
            float vva[4], vvb[4];
            #pragma unroll
            for (int i = 0; i < 8; i++)
                pv[i] = *(const float2*)&KPs[(ty * 8 + i) * 68 + n];
            #pragma unroll
            for (int j = 0; j < 4; j++) {
                vva[j] = Vs[n * 64 + tx + 16 * j];
                vvb[j] = Vs[(n + 1) * 64 + tx + 16 * j];
            }
            #pragma unroll
            for (int i = 0; i < 8; i++)
                #pragma unroll
                for (int j = 0; j < 4; j++)
                    acc[i][j] += pv[i].x * vva[j] + pv[i].y * vvb[j];
        }
    }

    #pragma unroll
    for (int i = 0; i < 8; i++) {
        float inv = 1.0f / rl[i];
        size_t base = (size_t)(q0 + ty * 8 + i) * H_ + h * 64;
        #pragma unroll
        for (int j = 0; j < 4; j++)
            split1(acc[i][j] * inv, &oh[base + tx + 16 * j], &ol[base + tx + 16 * j]);
    }
}

// ---------------------------------------------------------------------------
__global__ void router_kernel(const float* __restrict__ t,
                              const float* __restrict__ rw,
                              int* counts, int* toklist, float* tokw) {
    int warp = threadIdx.x >> 5;
    int lane = threadIdx.x & 31;
    int tok = blockIdx.x * 8 + warp;
    if (tok >= S_) return;
    const float* tr = t + (size_t)tok * H_;
    float logits[E_];
    for (int e = 0; e < E_; e++) {
        float s = 0.0f;
        for (int k = lane; k < H_; k += 32) s += tr[k] * rw[e * H_ + k];
        for (int o = 16; o > 0; o >>= 1) s += __shfl_xor_sync(0xffffffff, s, o);
        logits[e] = s;
    }
    if (lane == 0) {
        float mx = logits[0];
        for (int e = 1; e < E_; e++) mx = fmaxf(mx, logits[e]);
        float p[E_], sum = 0.0f;
        for (int e = 0; e < E_; e++) { p[e] = __expf(logits[e] - mx); sum += p[e]; }
        float invs = 1.0f / sum;
        for (int e = 0; e < E_; e++) p[e] *= invs;
        int b1 = 0;
        for (int e = 1; e < E_; e++) if (p[e] > p[b1]) b1 = e;
        int b2 = -1;
        for (int e = 0; e < E_; e++) {
            if (e == b1) continue;
            if (b2 < 0 || p[e] > p[b2]) b2 = e;
        }
        int pos1 = atomicAdd(&counts[b1], 1);
        toklist[b1 * S_ + pos1] = tok; tokw[b1 * S_ + pos1] = p[b1];
        int pos2 = atomicAdd(&counts[b2], 1);
        toklist[b2 * S_ + pos2] = tok; tokw[b2 * S_ + pos2] = p[b2];
    }
}

// ---------------------------------------------------------------------------
extern "C" void kernel_launch(void* const* d_in, const int* in_sizes, int n_in,
                              void* d_out, int out_size) {
    const float* hidden   = (const float*)d_in[0];
    const float* w_qkv    = (const float*)d_in[2];
    const float* w_o      = (const float*)d_in[3];
    const float* router_w = (const float*)d_in[4];
    const float* ws       = (const float*)d_in[5];
    const float* w2s      = (const float*)d_in[6];
    const float* ln1      = (const float*)d_in[7];
    const float* ln2      = (const float*)d_in[8];

    float* out    = (float*)d_out;
    float* resid2 = out + (size_t)S_ * H_;

    bf16 *wqh, *wql, *woh, *wol, *wsh, *wsl, *w2h, *w2l;
    bf16 *xnh, *xnl, *ath, *atl, *tnh, *tnl, *ach, *acl;
    float *qkv, *tnorm, *tokw;
    int *counts, *toklist;
    cudaGetSymbolAddress((void**)&wqh, g_wqkv_h); cudaGetSymbolAddress((void**)&wql, g_wqkv_l);
    cudaGetSymbolAddress((void**)&woh, g_wo_h);   cudaGetSymbolAddress((void**)&wol, g_wo_l);
    cudaGetSymbolAddress((void**)&wsh, g_ws_h);   cudaGetSymbolAddress((void**)&wsl, g_ws_l);
    cudaGetSymbolAddress((void**)&w2h, g_w2s_h);  cudaGetSymbolAddress((void**)&w2l, g_w2s_l);
    cudaGetSymbolAddress((void**)&xnh, g_xn_h);   cudaGetSymbolAddress((void**)&xnl, g_xn_l);
    cudaGetSymbolAddress((void**)&ath, g_at_h);   cudaGetSymbolAddress((void**)&atl, g_at_l);
    cudaGetSymbolAddress((void**)&tnh, g_tn_h);   cudaGetSymbolAddress((void**)&tnl, g_tn_l);
    cudaGetSymbolAddress((void**)&ach, g_act_h);  cudaGetSymbolAddress((void**)&acl, g_act_l);
    cudaGetSymbolAddress((void**)&qkv,   g_qkv);
    cudaGetSymbolAddress((void**)&tnorm, g_tnorm);
    cudaGetSymbolAddress((void**)&counts, g_counts);
    cudaGetSymbolAddress((void**)&toklist, g_toklist);
    cudaGetSymbolAddress((void**)&tokw,  g_tokw);

    const int GSMEM = 65536;
    cudaFuncSetAttribute(hmma2<0,0>, cudaFuncAttributeMaxDynamicSharedMemorySize, GSMEM);
    cudaFuncSetAttribute(hmma2<0,1>, cudaFuncAttributeMaxDynamicSharedMemorySize, GSMEM);
    cudaFuncSetAttribute(hmma2<1,3>, cudaFuncAttributeMaxDynamicSharedMemorySize, GSMEM);
    cudaFuncSetAttribute(hmma2<0,2>, cudaFuncAttributeMaxDynamicSharedMemorySize, GSMEM);
    int attn_smem = (64 * 64 + 64 * 68 + 64 * 64) * 4;
    cudaFuncSetAttribute(attn_flash, cudaFuncAttributeMaxDynamicSharedMemorySize, attn_smem);

    zero_kernel<<<(S_ * H_ + 255) / 256, 256>>>(out, counts);

    // weight split prepasses
    split_kernel<<<(QKV_O * H_ / 4 + 255) / 256, 256>>>(w_qkv, wqh, wql, QKV_O * H_ / 4);
    split_kernel<<<(H_ * H_ / 4 + 255) / 256, 256>>>(w_o, woh, wol, H_ * H_ / 4);
    split_ws_perm<<<dim3(1, 2 * I_, E_), 256>>>(ws, wsh, wsl);
    split_kernel<<<(int)(((size_t)E_ * H_ * I_ / 4 + 255) / 256), 256>>>(
        w2s, w2h, w2l, (size_t)E_ * H_ * I_ / 4);

    rmsnorm_hl<<<S_, 256>>>(hidden, ln1, nullptr, xnh, xnl);

    // QKV
    hmma2<0,0><<<dim3(QKV_O / 128, S_ / 128, 1), 256, GSMEM>>>(
        xnh, xnl, wqh, wql, qkv, S_, QKV_O, H_, H_, QKV_O,
        nullptr, nullptr, nullptr, nullptr, nullptr, nullptr, 0, 0, 0);

    attn_flash<<<dim3(S_ / 64, NH_), 128, attn_smem>>>(qkv, ath, atl);

    // O proj + residual
    hmma2<0,1><<<dim3(H_ / 128, S_ / 128, 1), 256, GSMEM>>>(
        ath, atl, woh, wol, resid2, S_, H_, H_, H_, H_,
        hidden, nullptr, nullptr, nullptr, nullptr, nullptr, 0, 0, 0);

    rmsnorm_hl<<<S_, 256>>>(resid2, ln2, tnorm, tnh, tnl);
    router_kernel<<<S_ / 8, 256>>>(tnorm, router_w, counts, toklist, tokw);

    // MoE up+gate, swiglu fused epilogue -> act bf16 hi/lo planes
    hmma2<1,3><<<dim3(2 * I_ / 128, S_ / 128, E_), 256, GSMEM>>>(
        tnh, tnl, wsh, wsl, nullptr, S_, 2 * I_, H_, H_, 0,
        nullptr, counts, toklist, nullptr, ach, acl,
        0, (size_t)2 * I_ * H_, 0);

    // MoE down (weighted scatter)
    hmma2<0,2><<<dim3(H_ / 128, S_ / 128, E_), 256, GSMEM>>>(
        ach, acl, w2h, w2l, out, S_, H_, I_, I_, H_,
        nullptr, counts, toklist, tokw, nullptr, nullptr,
        (size_t)S_ * I_, (size_t)H_ * I_, 0);
}

// round 8
// speedup vs baseline: 4.5935x; 1.0002x over previous
#include <cuda_runtime.h>
#include <cuda_bf16.h>
#include <math.h>
#include <stdint.h>

#define S_  2048
#define H_  1024
#define NH_ 16
#define NKV_ 4
#define HD_ 64
#define QKV_O 1536
#define I_  2816
#define E_  8
#define WIN_ 512
#define EPS_ 1e-5f

typedef __nv_bfloat16 bf16;

// ---------------------------------------------------------------------------
// Scratch (static device globals)
// ---------------------------------------------------------------------------
__device__ bf16 g_wqkv_h[QKV_O * H_],            g_wqkv_l[QKV_O * H_];
__device__ bf16 g_wo_h[H_ * H_],                 g_wo_l[H_ * H_];
__device__ bf16 g_ws_h[(size_t)E_ * 2 * I_ * H_], g_ws_l[(size_t)E_ * 2 * I_ * H_];
__device__ bf16 g_w2s_h[(size_t)E_ * H_ * I_],    g_w2s_l[(size_t)E_ * H_ * I_];
__device__ bf16 g_xn_h[S_ * H_],  g_xn_l[S_ * H_];
__device__ bf16 g_at_h[S_ * H_],  g_at_l[S_ * H_];
__device__ bf16 g_tn_h[S_ * H_],  g_tn_l[S_ * H_];
__device__ bf16 g_act_h[(size_t)E_ * S_ * I_],    g_act_l[(size_t)E_ * S_ * I_];
__device__ float g_qkv[S_ * QKV_O];
__device__ float g_tnorm[S_ * H_];
__device__ int   g_counts[E_];
__device__ int   g_toklist[E_ * S_];
__device__ float g_tokw[E_ * S_];

// ---------------------------------------------------------------------------
__device__ __forceinline__ uint32_t smem_u32(const void* p) {
    uint32_t a;
    asm("{ .reg .u64 t; cvta.to.shared.u64 t, %1; cvt.u32.u64 %0, t; }"
        : "=r"(a) : "l"(p));
    return a;
}
__device__ __forceinline__ void ldm4(uint32_t& r0, uint32_t& r1,
                                     uint32_t& r2, uint32_t& r3, uint32_t addr) {
    asm volatile("ldmatrix.sync.aligned.m8n8.x4.shared.b16 {%0,%1,%2,%3}, [%4];"
                 : "=r"(r0), "=r"(r1), "=r"(r2), "=r"(r3) : "r"(addr));
}
__device__ __forceinline__ void mma16816(float* d, const uint32_t* a,
                                         const uint32_t* b) {
    asm volatile(
        "mma.sync.aligned.m16n8k16.row.col.f32.bf16.bf16.f32 "
        "{%0,%1,%2,%3}, {%4,%5,%6,%7}, {%8,%9}, {%0,%1,%2,%3};"
        : "+f"(d[0]), "+f"(d[1]), "+f"(d[2]), "+f"(d[3])
        : "r"(a[0]), "r"(a[1]), "r"(a[2]), "r"(a[3]), "r"(b[0]), "r"(b[1]));
}
__device__ __forceinline__ void cp16(uint32_t dst, const void* src, int sz) {
    asm volatile("cp.async.cg.shared.global [%0], [%1], 16, %2;"
                 :: "r"(dst), "l"(src), "r"(sz));
}
__device__ __forceinline__ void cp_commit() {
    asm volatile("cp.async.commit_group;");
}
__device__ __forceinline__ void cp_wait0() {
    asm volatile("cp.async.wait_group 0;");
}

// split fp32 float4 -> bf16 hi/lo (8B each)
__device__ __forceinline__ void split_store4(float4 v, bf16* hp, bf16* lp) {
    __nv_bfloat162 h01 = __floats2bfloat162_rn(v.x, v.y);
    __nv_bfloat162 h23 = __floats2bfloat162_rn(v.z, v.w);
    float2 f01 = __bfloat1622float2(h01);
    float2 f23 = __bfloat1622float2(h23);
    __nv_bfloat162 l01 = __floats2bfloat162_rn(v.x - f01.x, v.y - f01.y);
    __nv_bfloat162 l23 = __floats2bfloat162_rn(v.z - f23.x, v.w - f23.y);
    *(uint2*)hp = make_uint2(*(uint32_t*)&h01, *(uint32_t*)&h23);
    *(uint2*)lp = make_uint2(*(uint32_t*)&l01, *(uint32_t*)&l23);
}
__device__ __forceinline__ void split1(float v, bf16* hp, bf16* lp) {
    bf16 hb = __float2bfloat16(v);
    *hp = hb;
    *lp = __float2bfloat16(v - __bfloat162float(hb));
}

// ---------------------------------------------------------------------------
// HMMA GEMM, bf16 3-term split planes. CTA tile 128x128, BK=32, 8 warps.
// cp.async double-buffered, 2 CTAs/SM.
// GRID: blockIdx.x = M-tile (FAST — consecutive CTAs share the same B tile
// for L2 reuse), blockIdx.y = N-tile, blockIdx.z = expert.
// GATHER: A rows via toklist.
// EPI: 0=store 1=+addsrc 2=weighted scatter 3=swiglu->act bf16 planes
// ---------------------------------------------------------------------------
template<int GATHER, int EPI>
__global__ __launch_bounds__(256, 2)
void hmma2(const bf16* __restrict__ Ah, const bf16* __restrict__ Al,
           const bf16* __restrict__ Bh, const bf16* __restrict__ Bl,
           float* __restrict__ C, int M, int N, int K, int lda, int ldc,
           const float* __restrict__ addsrc,
           const int* __restrict__ counts,
           const int* __restrict__ toklist,
           const float* __restrict__ tokw,
           bf16* __restrict__ actH, bf16* __restrict__ actL,
           size_t sA, size_t sB, size_t sC)
{
    extern __shared__ char smem[];     // 2 stages x 4 planes x 8KB = 64KB
    __shared__ int rowsS[128];

    int e = blockIdx.z;
    int Mlim = counts ? counts[e] : M;
    int m0 = blockIdx.x * 128;         // M fastest
    if (m0 >= Mlim) return;
    int n0 = blockIdx.y * 128;
    const bf16* Ahe = Ah + sA * e;
    const bf16* Ale = Al + sA * e;
    const bf16* Bhe = Bh + sB * e;
    const bf16* Ble = Bl + sB * e;
    float*      Ce  = C ? C + sC * e : nullptr;

    int tid = threadIdx.x;
    int wid = tid >> 5;
    int lane = tid & 31;
    int warp_m = wid & 1;
    int warp_n = wid >> 1;

    if (GATHER) {
        if (tid < 128)
            rowsS[tid] = (m0 + tid < Mlim) ? toklist[e * S_ + m0 + tid] : -1;
        __syncthreads();
    }

    uint32_t sbase = smem_u32(smem);

    auto issue = [&](int c, int buf) {
        int k0 = c * 32;
        #pragma unroll
        for (int l = 0; l < 8; l++) {
            int seg = tid + l * 256;
            int plane = seg >> 9;            // 0=Ah 1=Al 2=Bh 3=Bl
            int row = (seg >> 2) & 127;
            int ch = seg & 3;
            uint32_t dst = sbase + buf * 32768 + plane * 8192
                         + row * 64 + ((ch ^ ((row >> 1) & 3)) << 4);
            const bf16* gsrc;
            int sz = 16;
            if (plane < 2) {
                int gr;
                if (GATHER) {
                    gr = rowsS[row];
                    if (gr < 0) { gr = 0; sz = 0; }
                } else {
                    gr = m0 + row;
                    if (gr >= Mlim) { gr = 0; sz = 0; }
                }
                gsrc = (plane ? Ale : Ahe) + (size_t)gr * lda + k0 + ch * 8;
            } else {
                gsrc = ((plane == 3) ? Ble : Bhe) + (size_t)(n0 + row) * K + k0 + ch * 8;
            }
            cp16(dst, gsrc, sz);
        }
        cp_commit();
    };

    float acc[4][4][4] = {};
    const int nc = K / 32;
    issue(0, 0);

    for (int c = 0; c < nc; c++) {
        cp_wait0();
        __syncthreads();
        if (c + 1 < nc) issue(c + 1, (c + 1) & 1);

        uint32_t sb = sbase + (c & 1) * 32768;
        int mi = lane >> 3, r = lane & 7;

        #pragma unroll
        for (int ks = 0; ks < 2; ks++) {
            uint32_t afh[4][4], bfh[4][2];
            #pragma unroll
            for (int nfp = 0; nfp < 2; nfp++) {
                int n = warp_n * 32 + nfp * 16 + ((mi >> 1) << 3) + r;
                int ch = ks * 2 + (mi & 1);
                uint32_t off = (uint32_t)(n * 64 + ((ch ^ ((n >> 1) & 3)) << 4));
                uint32_t r0, r1, r2, r3;
                ldm4(r0, r1, r2, r3, sb + 2 * 8192 + off);
                bfh[nfp * 2 + 0][0] = r0; bfh[nfp * 2 + 0][1] = r1;
                bfh[nfp * 2 + 1][0] = r2; bfh[nfp * 2 + 1][1] = r3;
            }
            #pragma unroll
            for (int mf = 0; mf < 4; mf++) {
                int row = warp_m * 64 + mf * 16 + ((mi & 1) << 3) + r;
                int ch = ks * 2 + (mi >> 1);
                uint32_t off = (uint32_t)(row * 64 + ((ch ^ ((row >> 1) & 3)) << 4));
                ldm4(afh[mf][0], afh[mf][1], afh[mf][2], afh[mf][3], sb + off);
            }
            #pragma unroll
            for (int mf = 0; mf < 4; mf++)
                #pragma unroll
                for (int nf = 0; nf < 4; nf++)
                    mma16816(acc[mf][nf], afh[mf], bfh[nf]);

            {
                uint32_t bfl[4][2];
                #pragma unroll
                for (int nfp = 0; nfp < 2; nfp++) {
                    int n = warp_n * 32 + nfp * 16 + ((mi >> 1) << 3) + r;
                    int ch = ks * 2 + (mi & 1);
                    uint32_t off = (uint32_t)(n * 64 + ((ch ^ ((n >> 1) & 3)) << 4));
                    uint32_t r0, r1, r2, r3;
                    ldm4(r0, r1, r2, r3, sb + 3 * 8192 + off);
                    bfl[nfp * 2 + 0][0] = r0; bfl[nfp * 2 + 0][1] = r1;
                    bfl[nfp * 2 + 1][0] = r2; bfl[nfp * 2 + 1][1] = r3;
                }
                #pragma unroll
                for (int mf = 0; mf < 4; mf++)
                    #pragma unroll
                    for (int nf = 0; nf < 4; nf++)
                        mma16816(acc[mf][nf], afh[mf], bfl[nf]);
            }
            {
                uint32_t afl[4][4];
                #pragma unroll
                for (int mf = 0; mf < 4; mf++) {
                    int row = warp_m * 64 + mf * 16 + ((mi & 1) << 3) + r;
                    int ch = ks * 2 + (mi >> 1);
                    uint32_t off = (uint32_t)(row * 64 + ((ch ^ ((row >> 1) & 3)) << 4));
                    ldm4(afl[mf][0], afl[mf][1], afl[mf][2], afl[mf][3], sb + 8192 + off);
                }
                #pragma unroll
                for (int mf = 0; mf < 4; mf++)
                    #pragma unroll
                    for (int nf = 0; nf < 4; nf++)
                        mma16816(acc[mf][nf], afl[mf], bfh[nf]);
            }
        }
    }

    // ---------------- epilogue ----------------
    int lr = lane >> 2;
    int lc = (lane & 3) * 2;

    if (EPI == 3) {
        // swiglu: tile cols [0,64)=gate (warp_n 0,1), [64,128)=up (warp_n 2,3)
        __syncthreads();                       // mainloop smem reads done
        float (*Us)[65] = (float (*)[65])smem; // 128 x 65 fp32
        if (warp_n >= 2) {
            #pragma unroll
            for (int mf = 0; mf < 4; mf++) {
                int rl0 = warp_m * 64 + mf * 16 + lr;
                #pragma unroll
                for (int nf = 0; nf < 4; nf++) {
                    int j = (warp_n - 2) * 32 + nf * 8 + lc;
                    Us[rl0][j]         = acc[mf][nf][0];
                    Us[rl0][j + 1]     = acc[mf][nf][1];
                    Us[rl0 + 8][j]     = acc[mf][nf][2];
                    Us[rl0 + 8][j + 1] = acc[mf][nf][3];
                }
            }
        }
        __syncthreads();
        if (warp_n < 2) {
            int colbase = n0 >> 1;             // tile t covers act cols t*64..
            #pragma unroll
            for (int mf = 0; mf < 4; mf++) {
                int rl0 = warp_m * 64 + mf * 16 + lr;
                #pragma unroll
                for (int half = 0; half < 2; half++) {
                    int rl = rl0 + half * 8;
                    int m = m0 + rl;
                    if (m >= Mlim) continue;
                    size_t rowoff = ((size_t)e * S_ + m) * I_ + colbase;
                    #pragma unroll
                    for (int nf = 0; nf < 4; nf++) {
                        int j = warp_n * 32 + nf * 8 + lc;
                        #pragma unroll
                        for (int q = 0; q < 2; q++) {
                            float g = acc[mf][nf][half * 2 + q];
                            float u = Us[rl][j + q];
                            float a = g / (1.f + __expf(-g)) * u;
                            split1(a, &actH[rowoff + j + q], &actL[rowoff + j + q]);
                        }
                    }
                }
            }
        }
        return;
    }

    #pragma unroll
    for (int mf = 0; mf < 4; mf++) {
        int r0g = m0 + warp_m * 64 + mf * 16 + lr;
        int r1g = r0g + 8;
        if (EPI == 2) {
            int tokA = 0, tokB = 0; float wA = 0.f, wB = 0.f;
            bool vA = (r0g < Mlim), vB = (r1g < Mlim);
            if (vA) { tokA = toklist[e * S_ + r0g]; wA = tokw[e * S_ + r0g]; }
            if (vB) { tokB = toklist[e * S_ + r1g]; wB = tokw[e * S_ + r1g]; }
            #pragma unroll
            for (int nf = 0; nf < 4; nf++) {
                int col = n0 + warp_n * 32 + nf * 8 + lc;
                if (vA) {
                    atomicAdd(&C[(size_t)tokA * H_ + col],     wA * acc[mf][nf][0]);
                    atomicAdd(&C[(size_t)tokA * H_ + col + 1], wA * acc[mf][nf][1]);
                }
                if (vB) {
                    atomicAdd(&C[(size_t)tokB * H_ + col],     wB * acc[mf][nf][2]);
                    atomicAdd(&C[(size_t)tokB * H_ + col + 1], wB * acc[mf][nf][3]);
                }
            }
        } else {
            #pragma unroll
            for (int nf = 0; nf < 4; nf++) {
                int col = n0 + warp_n * 32 + nf * 8 + lc;
                if (r0g < Mlim) {
                    float2 v = make_float2(acc[mf][nf][0], acc[mf][nf][1]);
                    if (EPI == 1) {
                        const float* a2 = addsrc + (size_t)r0g * ldc + col;
                        v.x += a2[0]; v.y += a2[1];
                    }
                    *(float2*)(Ce + (size_t)r0g * ldc + col) = v;
                }
                if (r1g < Mlim) {
                    float2 v = make_float2(acc[mf][nf][2], acc[mf][nf][3]);
                    if (EPI == 1) {
                        const float* a2 = addsrc + (size_t)r1g * ldc + col;
                        v.x += a2[0]; v.y += a2[1];
                    }
                    *(float2*)(Ce + (size_t)r1g * ldc + col) = v;
                }
            }
        }
    }
}

// ---------------------------------------------------------------------------
__global__ void split_kernel(const float* __restrict__ src,
                             bf16* __restrict__ h, bf16* __restrict__ l,
                             size_t n4) {
    size_t i = (size_t)blockIdx.x * blockDim.x + threadIdx.x;
    if (i >= n4) return;
    float4 v = ((const float4*)src)[i];
    split_store4(v, h + i * 4, l + i * 4);
}

// ws split with gate/up interleave permutation:
// dest row p (tile t=p/128, r=p%128): src = r<64 ? t*64+r : I + t*64 + (r-64)
__global__ void split_ws_perm(const float* __restrict__ ws,
                              bf16* __restrict__ h, bf16* __restrict__ l) {
    int e = blockIdx.z, p = blockIdx.y;
    int t = p >> 7, r = p & 127;
    int src = (r < 64) ? (t * 64 + r) : (I_ + t * 64 + (r - 64));
    const float* srow = ws + ((size_t)e * 2 * I_ + src) * H_;
    bf16* hr = h + ((size_t)e * 2 * I_ + p) * H_;
    bf16* lr = l + ((size_t)e * 2 * I_ + p) * H_;
    int i = threadIdx.x * 4;
    float4 v = *(const float4*)(srow + i);
    split_store4(v, hr + i, lr + i);
}

// ---------------------------------------------------------------------------
__global__ void zero_kernel(float* out, int* counts) {
    int i = blockIdx.x * blockDim.x + threadIdx.x;
    if (i < S_ * H_) out[i] = 0.0f;
    if (i < E_) counts[i] = 0;
}

__global__ void rmsnorm_hl(const float* __restrict__ x,
                           const float* __restrict__ w,
                           float* __restrict__ y,
                           bf16* __restrict__ yh, bf16* __restrict__ yl) {
    int row = blockIdx.x;
    int tid = threadIdx.x;
    __shared__ float red[256];
    const float* xr = x + (size_t)row * H_;
    float s = 0.0f;
    for (int c = tid; c < H_; c += 256) { float v = xr[c]; s += v * v; }
    red[tid] = s; __syncthreads();
    for (int o = 128; o > 0; o >>= 1) {
        if (tid < o) red[tid] += red[tid + o];
        __syncthreads();
    }
    float inv = rsqrtf(red[0] / (float)H_ + EPS_);
    for (int c = tid * 4; c < H_; c += 1024) {
        float4 v = *(const float4*)(xr + c);
        float4 wv = *(const float4*)(w + c);
        v.x *= inv * wv.x; v.y *= inv * wv.y;
        v.z *= inv * wv.z; v.w *= inv * wv.w;
        if (y) *(float4*)(y + (size_t)row * H_ + c) = v;
        split_store4(v, yh + (size_t)row * H_ + c, yl + (size_t)row * H_ + c);
    }
}

// ---------------------------------------------------------------------------
// Flash attention (fp32): 128 threads, 8x4 register tile, bf16 hi/lo output
// ---------------------------------------------------------------------------
__global__ __launch_bounds__(128)
void attn_flash(const float* __restrict__ qkv,
                bf16* __restrict__ oh, bf16* __restrict__ ol) {
    extern __shared__ float smf[];
    float* Qs  = smf;                      // [64][64]
    float* KPs = smf + 4096;               // [64][68]
    float* Vs  = smf + 4096 + 64 * 68;     // [64][64]

    int qt = blockIdx.x, h = blockIdx.y;
    int q0 = qt * 64;
    int kvh = h >> 2;
    int tid = threadIdx.x;
    int tx = tid & 15, ty = tid >> 4;      // ty 0..7

    #pragma unroll
    for (int l = 0; l < 8; l++) {
        int idx = tid + l * 128;
        int r = idx >> 4, dq = (idx & 15) * 4;
        *(float4*)&Qs[r * 64 + dq] =
            *(const float4*)&qkv[(size_t)(q0 + r) * QKV_O + h * 64 + dq];
    }

    float acc[8][4] = {};
    float rm[8], rl[8];
    #pragma unroll
    for (int i = 0; i < 8; i++) { rm[i] = -1e30f; rl[i] = 0.f; }

    int t0 = (q0 > 511) ? ((q0 - 511) >> 6) : 0;
    for (int kt = t0; kt <= qt; kt++) {
        int j0 = kt * 64;
        __syncthreads();
        #pragma unroll
        for (int l = 0; l < 8; l++) {
            int idx = tid + l * 128;
            int r = idx >> 4, dq = (idx & 15) * 4;
            *(float4*)&KPs[r * 68 + dq] =
                *(const float4*)&qkv[(size_t)(j0 + r) * QKV_O + H_ + kvh * 64 + dq];
            *(float4*)&Vs[r * 64 + dq] =
                *(const float4*)&qkv[(size_t)(j0 + r) * QKV_O + H_ + NKV_ * HD_ + kvh * 64 + dq];
        }
        __syncthreads();

        float s[8][4] = {};
        #pragma unroll
        for (int d0 = 0; d0 < 64; d0 += 4) {
            float4 k4[4];
            #pragma unroll
            for (int j = 0; j < 4; j++) k4[j] = *(const float4*)&KPs[(tx + 16 * j) * 68 + d0];
            #pragma unroll
            for (int i = 0; i < 8; i++) {
                float4 q4 = *(const float4*)&Qs[(ty * 8 + i) * 64 + d0];
                #pragma unroll
                for (int j = 0; j < 4; j++)
                    s[i][j] += q4.x * k4[j].x + q4.y * k4[j].y
                             + q4.z * k4[j].z + q4.w * k4[j].w;
            }
        }
        __syncthreads();

        #pragma unroll
        for (int i = 0; i < 8; i++) {
            int iq = q0 + ty * 8 + i;
            float p[4];
            float tm = -1e30f;
            #pragma unroll
            for (int j = 0; j < 4; j++) {
                int jk = j0 + tx + 16 * j;
                bool ok = (jk <= iq) && (iq - jk < WIN_);
                s[i][j] = ok ? s[i][j] * 0.125f : -1e30f;
                tm = fmaxf(tm, s[i][j]);
            }
            #pragma unroll
            for (int o = 1; o < 16; o <<= 1)
                tm = fmaxf(tm, __shfl_xor_sync(0xffffffffu, tm, o));
            float mn = fmaxf(rm[i], tm);
            float alpha = __expf(rm[i] - mn);
            rm[i] = mn;
            float ps = 0.f;
            #pragma unroll
            for (int j = 0; j < 4; j++) { p[j] = __expf(s[i][j] - mn); ps += p[j]; }
            #pragma unroll
            for (int o = 1; o < 16; o <<= 1)
                ps += __shfl_xor_sync(0xffffffffu, ps, o);
            rl[i] = rl[i] * alpha + ps;
            #pragma unroll
            for (int j = 0; j < 4; j++) {
                acc[i][j] *= alpha;
                KPs[(ty * 8 + i) * 68 + tx + 16 * j] = p[j];
            }
        }
        __syncthreads();

        #pragma unroll 2
        for (int n = 0; n < 64; n += 2) {
            float2 pv[8];
            float vva[4], vvb[4];
            #pragma unroll
            for (int i = 0; i < 8; i++)
                pv[i] = *(const float2*)&KPs[(ty * 8 + i) * 68 + n];
            #pragma unroll
            for (int j = 0; j < 4; j++) {
                vva[j] = Vs[n * 64 + tx + 16 * j];
                vvb[j] = Vs[(n + 1) * 64 + tx + 16 * j];
            }
            #pragma unroll
            for (int i = 0; i < 8; i++)
                #pragma unroll
                for (int j = 0; j < 4; j++)
                    acc[i][j] += pv[i].x * vva[j] + pv[i].y * vvb[j];
        }
    }

    #pragma unroll
    for (int i = 0; i < 8; i++) {
        float inv = 1.0f / rl[i];
        size_t base = (size_t)(q0 + ty * 8 + i) * H_ + h * 64;
        #pragma unroll
        for (int j = 0; j < 4; j++)
            split1(acc[i][j] * inv, &oh[base + tx + 16 * j], &ol[base + tx + 16 * j]);
    }
}

// ---------------------------------------------------------------------------
__global__ void router_kernel(const float* __restrict__ t,
                              const float* __restrict__ rw,
                              int* counts, int* toklist, float* tokw) {
    int warp = threadIdx.x >> 5;
    int lane = threadIdx.x & 31;
    int tok = blockIdx.x * 8 + warp;
    if (tok >= S_) return;
    const float* tr = t + (size_t)tok * H_;
    float logits[E_];
    for (int e = 0; e < E_; e++) {
        float s = 0.0f;
        for (int k = lane; k < H_; k += 32) s += tr[k] * rw[e * H_ + k];
        for (int o = 16; o > 0; o >>= 1) s += __shfl_xor_sync(0xffffffff, s, o);
        logits[e] = s;
    }
    if (lane == 0) {
        float mx = logits[0];
        for (int e = 1; e < E_; e++) mx = fmaxf(mx, logits[e]);
        float p[E_], sum = 0.0f;
        for (int e = 0; e < E_; e++) { p[e] = __expf(logits[e] - mx); sum += p[e]; }
        float invs = 1.0f / sum;
        for (int e = 0; e < E_; e++) p[e] *= invs;
        int b1 = 0;
        for (int e = 1; e < E_; e++) if (p[e] > p[b1]) b1 = e;
        int b2 = -1;
        for (int e = 0; e < E_; e++) {
            if (e == b1) continue;
            if (b2 < 0 || p[e] > p[b2]) b2 = e;
        }
        int pos1 = atomicAdd(&counts[b1], 1);
        toklist[b1 * S_ + pos1] = tok; tokw[b1 * S_ + pos1] = p[b1];
        int pos2 = atomicAdd(&counts[b2], 1);
        toklist[b2 * S_ + pos2] = tok; tokw[b2 * S_ + pos2] = p[b2];
    }
}

// ---------------------------------------------------------------------------
extern "C" void kernel_launch(void* const* d_in, const int* in_sizes, int n_in,
                              void* d_out, int out_size) {
    const float* hidden   = (const float*)d_in[0];
    const float* w_qkv    = (const float*)d_in[2];
    const float* w_o      = (const float*)d_in[3];
    const float* router_w = (const float*)d_in[4];
    const float* ws       = (const float*)d_in[5];
    const float* w2s      = (const float*)d_in[6];
    const float* ln1      = (const float*)d_in[7];
    const float* ln2      = (const float*)d_in[8];

    float* out    = (float*)d_out;
    float* resid2 = out + (size_t)S_ * H_;

    bf16 *wqh, *wql, *woh, *wol, *wsh, *wsl, *w2h, *w2l;
    bf16 *xnh, *xnl, *ath, *atl, *tnh, *tnl, *ach, *acl;
    float *qkv, *tnorm, *tokw;
    int *counts, *toklist;
    cudaGetSymbolAddress((void**)&wqh, g_wqkv_h); cudaGetSymbolAddress((void**)&wql, g_wqkv_l);
    cudaGetSymbolAddress((void**)&woh, g_wo_h);   cudaGetSymbolAddress((void**)&wol, g_wo_l);
    cudaGetSymbolAddress((void**)&wsh, g_ws_h);   cudaGetSymbolAddress((void**)&wsl, g_ws_l);
    cudaGetSymbolAddress((void**)&w2h, g_w2s_h);  cudaGetSymbolAddress((void**)&w2l, g_w2s_l);
    cudaGetSymbolAddress((void**)&xnh, g_xn_h);   cudaGetSymbolAddress((void**)&xnl, g_xn_l);
    cudaGetSymbolAddress((void**)&ath, g_at_h);   cudaGetSymbolAddress((void**)&atl, g_at_l);
    cudaGetSymbolAddress((void**)&tnh, g_tn_h);   cudaGetSymbolAddress((void**)&tnl, g_tn_l);
    cudaGetSymbolAddress((void**)&ach, g_act_h);  cudaGetSymbolAddress((void**)&acl, g_act_l);
    cudaGetSymbolAddress((void**)&qkv,   g_qkv);
    cudaGetSymbolAddress((void**)&tnorm, g_tnorm);
    cudaGetSymbolAddress((void**)&counts, g_counts);
    cudaGetSymbolAddress((void**)&toklist, g_toklist);
    cudaGetSymbolAddress((void**)&tokw,  g_tokw);

    const int GSMEM = 65536;
    cudaFuncSetAttribute(hmma2<0,0>, cudaFuncAttributeMaxDynamicSharedMemorySize, GSMEM);
    cudaFuncSetAttribute(hmma2<0,1>, cudaFuncAttributeMaxDynamicSharedMemorySize, GSMEM);
    cudaFuncSetAttribute(hmma2<1,3>, cudaFuncAttributeMaxDynamicSharedMemorySize, GSMEM);
    cudaFuncSetAttribute(hmma2<0,2>, cudaFuncAttributeMaxDynamicSharedMemorySize, GSMEM);
    int attn_smem = (64 * 64 + 64 * 68 + 64 * 64) * 4;
    cudaFuncSetAttribute(attn_flash, cudaFuncAttributeMaxDynamicSharedMemorySize, attn_smem);

    zero_kernel<<<(S_ * H_ + 255) / 256, 256>>>(out, counts);

    // weight split prepasses
    split_kernel<<<(QKV_O * H_ / 4 + 255) / 256, 256>>>(w_qkv, wqh, wql, QKV_O * H_ / 4);
    split_kernel<<<(H_ * H_ / 4 + 255) / 256, 256>>>(w_o, woh, wol, H_ * H_ / 4);
    split_ws_perm<<<dim3(1, 2 * I_, E_), 256>>>(ws, wsh, wsl);
    split_kernel<<<(int)(((size_t)E_ * H_ * I_ / 4 + 255) / 256), 256>>>(
        w2s, w2h, w2l, (size_t)E_ * H_ * I_ / 4);

    rmsnorm_hl<<<S_, 256>>>(hidden, ln1, nullptr, xnh, xnl);

    // QKV   (grid: x = M-tiles, y = N-tiles)
    hmma2<0,0><<<dim3(S_ / 128, QKV_O / 128, 1), 256, GSMEM>>>(
        xnh, xnl, wqh, wql, qkv, S_, QKV_O, H_, H_, QKV_O,
        nullptr, nullptr, nullptr, nullptr, nullptr, nullptr, 0, 0, 0);

    attn_flash<<<dim3(S_ / 64, NH_), 128, attn_smem>>>(qkv, ath, atl);

    // O proj + residual
    hmma2<0,1><<<dim3(S_ / 128, H_ / 128, 1), 256, GSMEM>>>(
        ath, atl, woh, wol, resid2, S_, H_, H_, H_, H_,
        hidden, nullptr, nullptr, nullptr, nullptr, nullptr, 0, 0, 0);

    rmsnorm_hl<<<S_, 256>>>(resid2, ln2, tnorm, tnh, tnl);
    router_kernel<<<S_ / 8, 256>>>(tnorm, router_w, counts, toklist, tokw);

    // MoE up+gate, swiglu fused epilogue -> act bf16 hi/lo planes
    hmma2<1,3><<<dim3(S_ / 128, 2 * I_ / 128, E_), 256, GSMEM>>>(
        tnh, tnl, wsh, wsl, nullptr, S_, 2 * I_, H_, H_, 0,
        nullptr, counts, toklist, nullptr, ach, acl,
        0, (size_t)2 * I_ * H_, 0);

    // MoE down (weighted scatter)
    hmma2<0,2><<<dim3(S_ / 128, H_ / 128, E_), 256, GSMEM>>>(
        ach, acl, w2h, w2l, out, S_, H_, I_, I_, H_,
        nullptr, counts, toklist, tokw, nullptr, nullptr,
        (size_t)S_ * I_, (size_t)H_ * I_, 0);
}

// round 9
// speedup vs baseline: 6.9592x; 1.5150x over previous
#include <cuda_runtime.h>
#include <cuda_bf16.h>
#include <cuda_fp16.h>
#include <math.h>
#include <stdint.h>

#define S_  2048
#define H_  1024
#define NH_ 16
#define NKV_ 4
#define HD_ 64
#define QKV_O 1536
#define I_  2816
#define E_  8
#define WIN_ 512
#define EPS_ 1e-5f

typedef __nv_bfloat16 bf16;
typedef __half f16;

// ---------------------------------------------------------------------------
// Scratch (static device globals)
// ---------------------------------------------------------------------------
__device__ bf16 g_wqkv_h[QKV_O * H_], g_wqkv_l[QKV_O * H_];
__device__ bf16 g_wo_h[H_ * H_],      g_wo_l[H_ * H_];
__device__ f16  g_ws_f[(size_t)E_ * 2 * I_ * H_];
__device__ f16  g_w2s_f[(size_t)E_ * H_ * I_];
__device__ bf16 g_xn_h[S_ * H_], g_xn_l[S_ * H_];
__device__ bf16 g_at_h[S_ * H_], g_at_l[S_ * H_];
__device__ f16  g_tn_f[S_ * H_];
__device__ f16  g_act_f[(size_t)E_ * S_ * I_];
__device__ float g_qkv[S_ * QKV_O];
__device__ float g_tnorm[S_ * H_];
__device__ int   g_counts[E_];
__device__ int   g_toklist[E_ * S_];
__device__ float g_tokw[E_ * S_];

// ---------------------------------------------------------------------------
__device__ __forceinline__ uint32_t smem_u32(const void* p) {
    uint32_t a;
    asm("{ .reg .u64 t; cvta.to.shared.u64 t, %1; cvt.u32.u64 %0, t; }"
        : "=r"(a) : "l"(p));
    return a;
}
__device__ __forceinline__ void ldm4(uint32_t& r0, uint32_t& r1,
                                     uint32_t& r2, uint32_t& r3, uint32_t addr) {
    asm volatile("ldmatrix.sync.aligned.m8n8.x4.shared.b16 {%0,%1,%2,%3}, [%4];"
                 : "=r"(r0), "=r"(r1), "=r"(r2), "=r"(r3) : "r"(addr));
}
__device__ __forceinline__ void mma_bf16(float* d, const uint32_t* a,
                                         const uint32_t* b) {
    asm volatile(
        "mma.sync.aligned.m16n8k16.row.col.f32.bf16.bf16.f32 "
        "{%0,%1,%2,%3}, {%4,%5,%6,%7}, {%8,%9}, {%0,%1,%2,%3};"
        : "+f"(d[0]), "+f"(d[1]), "+f"(d[2]), "+f"(d[3])
        : "r"(a[0]), "r"(a[1]), "r"(a[2]), "r"(a[3]), "r"(b[0]), "r"(b[1]));
}
__device__ __forceinline__ void mma_f16(float* d, const uint32_t* a,
                                        const uint32_t* b) {
    asm volatile(
        "mma.sync.aligned.m16n8k16.row.col.f32.f16.f16.f32 "
        "{%0,%1,%2,%3}, {%4,%5,%6,%7}, {%8,%9}, {%0,%1,%2,%3};"
        : "+f"(d[0]), "+f"(d[1]), "+f"(d[2]), "+f"(d[3])
        : "r"(a[0]), "r"(a[1]), "r"(a[2]), "r"(a[3]), "r"(b[0]), "r"(b[1]));
}
__device__ __forceinline__ void cp16(uint32_t dst, const void* src, int sz) {
    asm volatile("cp.async.cg.shared.global [%0], [%1], 16, %2;"
                 :: "r"(dst), "l"(src), "r"(sz));
}
__device__ __forceinline__ void cp_commit() {
    asm volatile("cp.async.commit_group;");
}
__device__ __forceinline__ void cp_wait0() {
    asm volatile("cp.async.wait_group 0;");
}

// split fp32 float4 -> bf16 hi/lo (8B each)
__device__ __forceinline__ void split_store4(float4 v, bf16* hp, bf16* lp) {
    __nv_bfloat162 h01 = __floats2bfloat162_rn(v.x, v.y);
    __nv_bfloat162 h23 = __floats2bfloat162_rn(v.z, v.w);
    float2 f01 = __bfloat1622float2(h01);
    float2 f23 = __bfloat1622float2(h23);
    __nv_bfloat162 l01 = __floats2bfloat162_rn(v.x - f01.x, v.y - f01.y);
    __nv_bfloat162 l23 = __floats2bfloat162_rn(v.z - f23.x, v.w - f23.y);
    *(uint2*)hp = make_uint2(*(uint32_t*)&h01, *(uint32_t*)&h23);
    *(uint2*)lp = make_uint2(*(uint32_t*)&l01, *(uint32_t*)&l23);
}
__device__ __forceinline__ void split1(float v, bf16* hp, bf16* lp) {
    bf16 hb = __float2bfloat16(v);
    *hp = hb;
    *lp = __float2bfloat16(v - __bfloat162float(hb));
}
__device__ __forceinline__ void cvt_store4(float4 v, f16* p) {
    __half2 a = __floats2half2_rn(v.x, v.y);
    __half2 b = __floats2half2_rn(v.z, v.w);
    *(uint2*)p = make_uint2(*(uint32_t*)&a, *(uint32_t*)&b);
}

// ---------------------------------------------------------------------------
// hmma2: bf16 3-term split GEMM (router-critical path). 128x128, BK=32,
// 8 warps, cp.async double-buffered, 2 CTAs/SM.
// EPI: 0=store 1=+addsrc
// ---------------------------------------------------------------------------
template<int EPI>
__global__ __launch_bounds__(256, 2)
void hmma2(const bf16* __restrict__ Ah, const bf16* __restrict__ Al,
           const bf16* __restrict__ Bh, const bf16* __restrict__ Bl,
           float* __restrict__ C, int M, int N, int K, int lda, int ldc,
           const float* __restrict__ addsrc)
{
    extern __shared__ char smem[];     // 2 stages x 4 planes x 8KB = 64KB
    int m0 = blockIdx.x * 128;
    int n0 = blockIdx.y * 128;

    int tid = threadIdx.x;
    int wid = tid >> 5;
    int lane = tid & 31;
    int warp_m = wid & 1;
    int warp_n = wid >> 1;

    uint32_t sbase = smem_u32(smem);

    auto issue = [&](int c, int buf) {
        int k0 = c * 32;
        #pragma unroll
        for (int l = 0; l < 8; l++) {
            int seg = tid + l * 256;
            int plane = seg >> 9;
            int row = (seg >> 2) & 127;
            int ch = seg & 3;
            uint32_t dst = sbase + buf * 32768 + plane * 8192
                         + row * 64 + ((ch ^ ((row >> 1) & 3)) << 4);
            const bf16* gsrc;
            if (plane < 2)
                gsrc = (plane ? Al : Ah) + (size_t)(m0 + row) * lda + k0 + ch * 8;
            else
                gsrc = ((plane == 3) ? Bl : Bh) + (size_t)(n0 + row) * K + k0 + ch * 8;
            cp16(dst, gsrc, 16);
        }
        cp_commit();
    };

    float acc[4][4][4] = {};
    const int nc = K / 32;
    issue(0, 0);

    for (int c = 0; c < nc; c++) {
        cp_wait0();
        __syncthreads();
        if (c + 1 < nc) issue(c + 1, (c + 1) & 1);

        uint32_t sb = sbase + (c & 1) * 32768;
        int mi = lane >> 3, r = lane & 7;

        #pragma unroll
        for (int ks = 0; ks < 2; ks++) {
            uint32_t afh[4][4], bfh[4][2];
            #pragma unroll
            for (int nfp = 0; nfp < 2; nfp++) {
                int n = warp_n * 32 + nfp * 16 + ((mi >> 1) << 3) + r;
                int ch = ks * 2 + (mi & 1);
                uint32_t off = (uint32_t)(n * 64 + ((ch ^ ((n >> 1) & 3)) << 4));
                uint32_t r0, r1, r2, r3;
                ldm4(r0, r1, r2, r3, sb + 2 * 8192 + off);
                bfh[nfp * 2 + 0][0] = r0; bfh[nfp * 2 + 0][1] = r1;
                bfh[nfp * 2 + 1][0] = r2; bfh[nfp * 2 + 1][1] = r3;
            }
            #pragma unroll
            for (int mf = 0; mf < 4; mf++) {
                int row = warp_m * 64 + mf * 16 + ((mi & 1) << 3) + r;
                int ch = ks * 2 + (mi >> 1);
                uint32_t off = (uint32_t)(row * 64 + ((ch ^ ((row >> 1) & 3)) << 4));
                ldm4(afh[mf][0], afh[mf][1], afh[mf][2], afh[mf][3], sb + off);
            }
            #pragma unroll
            for (int mf = 0; mf < 4; mf++)
                #pragma unroll
                for (int nf = 0; nf < 4; nf++)
                    mma_bf16(acc[mf][nf], afh[mf], bfh[nf]);
            {
                uint32_t bfl[4][2];
                #pragma unroll
                for (int nfp = 0; nfp < 2; nfp++) {
                    int n = warp_n * 32 + nfp * 16 + ((mi >> 1) << 3) + r;
                    int ch = ks * 2 + (mi & 1);
                    uint32_t off = (uint32_t)(n * 64 + ((ch ^ ((n >> 1) & 3)) << 4));
                    uint32_t r0, r1, r2, r3;
                    ldm4(r0, r1, r2, r3, sb + 3 * 8192 + off);
                    bfl[nfp * 2 + 0][0] = r0; bfl[nfp * 2 + 0][1] = r1;
                    bfl[nfp * 2 + 1][0] = r2; bfl[nfp * 2 + 1][1] = r3;
                }
                #pragma unroll
                for (int mf = 0; mf < 4; mf++)
                    #pragma unroll
                    for (int nf = 0; nf < 4; nf++)
                        mma_bf16(acc[mf][nf], afh[mf], bfl[nf]);
            }
            {
                uint32_t afl[4][4];
                #pragma unroll
                for (int mf = 0; mf < 4; mf++) {
                    int row = warp_m * 64 + mf * 16 + ((mi & 1) << 3) + r;
                    int ch = ks * 2 + (mi >> 1);
                    uint32_t off = (uint32_t)(row * 64 + ((ch ^ ((row >> 1) & 3)) << 4));
                    ldm4(afl[mf][0], afl[mf][1], afl[mf][2], afl[mf][3], sb + 8192 + off);
                }
                #pragma unroll
                for (int mf = 0; mf < 4; mf++)
                    #pragma unroll
                    for (int nf = 0; nf < 4; nf++)
                        mma_bf16(acc[mf][nf], afl[mf], bfh[nf]);
            }
        }
    }

    int lr = lane >> 2;
    int lc = (lane & 3) * 2;
    #pragma unroll
    for (int mf = 0; mf < 4; mf++) {
        int r0g = m0 + warp_m * 64 + mf * 16 + lr;
        int r1g = r0g + 8;
        #pragma unroll
        for (int nf = 0; nf < 4; nf++) {
            int col = n0 + warp_n * 32 + nf * 8 + lc;
            float2 v = make_float2(acc[mf][nf][0], acc[mf][nf][1]);
            float2 w = make_float2(acc[mf][nf][2], acc[mf][nf][3]);
            if (EPI == 1) {
                const float* a2 = addsrc + (size_t)r0g * ldc + col;
                const float* b2 = addsrc + (size_t)r1g * ldc + col;
                v.x += a2[0]; v.y += a2[1];
                w.x += b2[0]; w.y += b2[1];
            }
            *(float2*)(C + (size_t)r0g * ldc + col) = v;
            *(float2*)(C + (size_t)r1g * ldc + col) = w;
        }
    }
}

// ---------------------------------------------------------------------------
// hmma1: plain fp16 GEMM (MoE path, post-routing). 128x128 tile, BK=32,
// 8 warps, cp.async double-buffered (2 stages x 16KB), 2 CTAs/SM.
// GATHER: A rows via toklist. EPI: 2=weighted scatter 3=swiglu->act fp16
// ---------------------------------------------------------------------------
template<int GATHER, int EPI>
__global__ __launch_bounds__(256, 2)
void hmma1(const f16* __restrict__ A, const f16* __restrict__ B,
           float* __restrict__ C, int M, int N, int K, int lda,
           const int* __restrict__ counts,
           const int* __restrict__ toklist,
           const float* __restrict__ tokw,
           f16* __restrict__ actF,
           size_t sA, size_t sB)
{
    extern __shared__ char smem[];     // 2 stages x 2 planes x 8KB = 32KB
    __shared__ int rowsS[128];

    int e = blockIdx.z;
    int Mlim = counts[e];
    int m0 = blockIdx.x * 128;
    if (m0 >= Mlim) return;
    int n0 = blockIdx.y * 128;
    const f16* Ae = A + sA * e;
    const f16* Be = B + sB * e;

    int tid = threadIdx.x;
    int wid = tid >> 5;
    int lane = tid & 31;
    int warp_m = wid & 1;
    int warp_n = wid >> 1;

    if (GATHER) {
        if (tid < 128)
            rowsS[tid] = (m0 + tid < Mlim) ? toklist[e * S_ + m0 + tid] : -1;
        __syncthreads();
    }

    uint32_t sbase = smem_u32(smem);

    auto issue = [&](int c, int buf) {
        int k0 = c * 32;
        #pragma unroll
        for (int l = 0; l < 4; l++) {
            int seg = tid + l * 256;
            int plane = seg >> 9;            // 0=A 1=B
            int row = (seg >> 2) & 127;
            int ch = seg & 3;
            uint32_t dst = sbase + buf * 16384 + plane * 8192
                         + row * 64 + ((ch ^ ((row >> 1) & 3)) << 4);
            const f16* gsrc;
            int sz = 16;
            if (plane == 0) {
                int gr;
                if (GATHER) {
                    gr = rowsS[row];
                    if (gr < 0) { gr = 0; sz = 0; }
                } else {
                    gr = m0 + row;
                    if (gr >= Mlim) { gr = 0; sz = 0; }
                }
                gsrc = Ae + (size_t)gr * lda + k0 + ch * 8;
            } else {
                gsrc = Be + (size_t)(n0 + row) * K + k0 + ch * 8;
            }
            cp16(dst, gsrc, sz);
        }
        cp_commit();
    };

    float acc[4][4][4] = {};
    const int nc = K / 32;
    issue(0, 0);

    for (int c = 0; c < nc; c++) {
        cp_wait0();
        __syncthreads();
        if (c + 1 < nc) issue(c + 1, (c + 1) & 1);

        uint32_t sb = sbase + (c & 1) * 16384;
        int mi = lane >> 3, r = lane & 7;

        #pragma unroll
        for (int ks = 0; ks < 2; ks++) {
            uint32_t af[4][4], bf[4][2];
            #pragma unroll
            for (int nfp = 0; nfp < 2; nfp++) {
                int n = warp_n * 32 + nfp * 16 + ((mi >> 1) << 3) + r;
                int ch = ks * 2 + (mi & 1);
                uint32_t off = (uint32_t)(n * 64 + ((ch ^ ((n >> 1) & 3)) << 4));
                uint32_t r0, r1, r2, r3;
                ldm4(r0, r1, r2, r3, sb + 8192 + off);
                bf[nfp * 2 + 0][0] = r0; bf[nfp * 2 + 0][1] = r1;
                bf[nfp * 2 + 1][0] = r2; bf[nfp * 2 + 1][1] = r3;
            }
            #pragma unroll
            for (int mf = 0; mf < 4; mf++) {
                int row = warp_m * 64 + mf * 16 + ((mi & 1) << 3) + r;
                int ch = ks * 2 + (mi >> 1);
                uint32_t off = (uint32_t)(row * 64 + ((ch ^ ((row >> 1) & 3)) << 4));
                ldm4(af[mf][0], af[mf][1], af[mf][2], af[mf][3], sb + off);
            }
            #pragma unroll
            for (int mf = 0; mf < 4; mf++)
                #pragma unroll
                for (int nf = 0; nf < 4; nf++)
                    mma_f16(acc[mf][nf], af[mf], bf[nf]);
        }
    }

    int lr = lane >> 2;
    int lc = (lane & 3) * 2;

    if (EPI == 3) {
        // swiglu: tile cols [0,64)=gate (warp_n 0,1), [64,128)=up (warp_n 2,3)
        __syncthreads();
        float (*Us)[65] = (float (*)[65])smem;
        if (warp_n >= 2) {
            #pragma unroll
            for (int mf = 0; mf < 4; mf++) {
                int rl0 = warp_m * 64 + mf * 16 + lr;
                #pragma unroll
                for (int nf = 0; nf < 4; nf++) {
                    int j = (warp_n - 2) * 32 + nf * 8 + lc;
                    Us[rl0][j]         = acc[mf][nf][0];
                    Us[rl0][j + 1]     = acc[mf][nf][1];
                    Us[rl0 + 8][j]     = acc[mf][nf][2];
                    Us[rl0 + 8][j + 1] = acc[mf][nf][3];
                }
            }
        }
        __syncthreads();
        if (warp_n < 2) {
            int colbase = n0 >> 1;
            #pragma unroll
            for (int mf = 0; mf < 4; mf++) {
                int rl0 = warp_m * 64 + mf * 16 + lr;
                #pragma unroll
                for (int half = 0; half < 2; half++) {
                    int rl = rl0 + half * 8;
                    int m = m0 + rl;
                    if (m >= Mlim) continue;
                    size_t rowoff = ((size_t)e * S_ + m) * I_ + colbase;
                    #pragma unroll
                    for (int nf = 0; nf < 4; nf++) {
                        int j = warp_n * 32 + nf * 8 + lc;
                        #pragma unroll
                        for (int q = 0; q < 2; q++) {
                            float g = acc[mf][nf][half * 2 + q];
                            float u = Us[rl][j + q];
                            float a = g / (1.f + __expf(-g)) * u;
                            actF[rowoff + j + q] = __float2half_rn(a);
                        }
                    }
                }
            }
        }
        return;
    }

    // EPI == 2: weighted atomic scatter
    #pragma unroll
    for (int mf = 0; mf < 4; mf++) {
        int r0g = m0 + warp_m * 64 + mf * 16 + lr;
        int r1g = r0g + 8;
        int tokA = 0, tokB = 0; float wA = 0.f, wB = 0.f;
        bool vA = (r0g < Mlim), vB = (r1g < Mlim);
        if (vA) { tokA = toklist[e * S_ + r0g]; wA = tokw[e * S_ + r0g]; }
        if (vB) { tokB = toklist[e * S_ + r1g]; wB = tokw[e * S_ + r1g]; }
        #pragma unroll
        for (int nf = 0; nf < 4; nf++) {
            int col = n0 + warp_n * 32 + nf * 8 + lc;
            if (vA) {
                atomicAdd(&C[(size_t)tokA * H_ + col],     wA * acc[mf][nf][0]);
                atomicAdd(&C[(size_t)tokA * H_ + col + 1], wA * acc[mf][nf][1]);
            }
            if (vB) {
                atomicAdd(&C[(size_t)tokB * H_ + col],     wB * acc[mf][nf][2]);
                atomicAdd(&C[(size_t)tokB * H_ + col + 1], wB * acc[mf][nf][3]);
            }
        }
    }
}

// ---------------------------------------------------------------------------
__global__ void split_kernel(const float* __restrict__ src,
                             bf16* __restrict__ h, bf16* __restrict__ l,
                             size_t n4) {
    size_t i = (size_t)blockIdx.x * blockDim.x + threadIdx.x;
    if (i >= n4) return;
    float4 v = ((const float4*)src)[i];
    split_store4(v, h + i * 4, l + i * 4);
}

__global__ void cvt_kernel(const float* __restrict__ src,
                           f16* __restrict__ d, size_t n4) {
    size_t i = (size_t)blockIdx.x * blockDim.x + threadIdx.x;
    if (i >= n4) return;
    float4 v = ((const float4*)src)[i];
    cvt_store4(v, d + i * 4);
}

// ws -> fp16 with gate/up interleave permutation:
// dest row p (tile t=p/128, r=p%128): src = r<64 ? t*64+r : I + t*64 + (r-64)
__global__ void cvt_ws_perm(const float* __restrict__ ws,
                            f16* __restrict__ d) {
    int e = blockIdx.z, p = blockIdx.y;
    int t = p >> 7, r = p & 127;
    int src = (r < 64) ? (t * 64 + r) : (I_ + t * 64 + (r - 64));
    const float* srow = ws + ((size_t)e * 2 * I_ + src) * H_;
    f16* dr = d + ((size_t)e * 2 * I_ + p) * H_;
    int i = threadIdx.x * 4;
    float4 v = *(const float4*)(srow + i);
    cvt_store4(v, dr + i);
}

// ---------------------------------------------------------------------------
__global__ void zero_kernel(float* out, int* counts) {
    int i = blockIdx.x * blockDim.x + threadIdx.x;
    if (i < S_ * H_) out[i] = 0.0f;
    if (i < E_) counts[i] = 0;
}

// RMSNorm -> bf16 hi/lo planes (ln1 path)
__global__ void rmsnorm_hl(const float* __restrict__ x,
                           const float* __restrict__ w,
                           bf16* __restrict__ yh, bf16* __restrict__ yl) {
    int row = blockIdx.x;
    int tid = threadIdx.x;
    __shared__ float red[256];
    const float* xr = x + (size_t)row * H_;
    float s = 0.0f;
    for (int c = tid; c < H_; c += 256) { float v = xr[c]; s += v * v; }
    red[tid] = s; __syncthreads();
    for (int o = 128; o > 0; o >>= 1) {
        if (tid < o) red[tid] += red[tid + o];
        __syncthreads();
    }
    float inv = rsqrtf(red[0] / (float)H_ + EPS_);
    for (int c = tid * 4; c < H_; c += 1024) {
        float4 v = *(const float4*)(xr + c);
        float4 wv = *(const float4*)(w + c);
        v.x *= inv * wv.x; v.y *= inv * wv.y;
        v.z *= inv * wv.z; v.w *= inv * wv.w;
        split_store4(v, yh + (size_t)row * H_ + c, yl + (size_t)row * H_ + c);
    }
}

// RMSNorm -> fp32 (router) + fp16 plane (MoE A) (ln2 path)
__global__ void rmsnorm_f16(const float* __restrict__ x,
                            const float* __restrict__ w,
                            float* __restrict__ y,
                            f16* __restrict__ yf) {
    int row = blockIdx.x;
    int tid = threadIdx.x;
    __shared__ float red[256];
    const float* xr = x + (size_t)row * H_;
    float s = 0.0f;
    for (int c = tid; c < H_; c += 256) { float v = xr[c]; s += v * v; }
    red[tid] = s; __syncthreads();
    for (int o = 128; o > 0; o >>= 1) {
        if (tid < o) red[tid] += red[tid + o];
        __syncthreads();
    }
    float inv = rsqrtf(red[0] / (float)H_ + EPS_);
    for (int c = tid * 4; c < H_; c += 1024) {
        float4 v = *(const float4*)(xr + c);
        float4 wv = *(const float4*)(w + c);
        v.x *= inv * wv.x; v.y *= inv * wv.y;
        v.z *= inv * wv.z; v.w *= inv * wv.w;
        *(float4*)(y + (size_t)row * H_ + c) = v;
        cvt_store4(v, yf + (size_t)row * H_ + c);
    }
}

// ---------------------------------------------------------------------------
// Flash attention (fp32): 128 threads, 8x4 register tile, bf16 hi/lo output
// ---------------------------------------------------------------------------
__global__ __launch_bounds__(128)
void attn_flash(const float* __restrict__ qkv,
                bf16* __restrict__ oh, bf16* __restrict__ ol) {
    extern __shared__ float smf[];
    float* Qs  = smf;
    float* KPs = smf + 4096;
    float* Vs  = smf + 4096 + 64 * 68;

    int qt = blockIdx.x, h = blockIdx.y;
    int q0 = qt * 64;
    int kvh = h >> 2;
    int tid = threadIdx.x;
    int tx = tid & 15, ty = tid >> 4;

    #pragma unroll
    for (int l = 0; l < 8; l++) {
        int idx = tid + l * 128;
        int r = idx >> 4, dq = (idx & 15) * 4;
        *(float4*)&Qs[r * 64 + dq] =
            *(const float4*)&qkv[(size_t)(q0 + r) * QKV_O + h * 64 + dq];
    }

    float acc[8][4] = {};
    float rm[8], rl[8];
    #pragma unroll
    for (int i = 0; i < 8; i++) { rm[i] = -1e30f; rl[i] = 0.f; }

    int t0 = (q0 > 511) ? ((q0 - 511) >> 6) : 0;
    for (int kt = t0; kt <= qt; kt++) {
        int j0 = kt * 64;
        __syncthreads();
        #pragma unroll
        for (int l = 0; l < 8; l++) {
            int idx = tid + l * 128;
            int r = idx >> 4, dq = (idx & 15) * 4;
            *(float4*)&KPs[r * 68 + dq] =
                *(const float4*)&qkv[(size_t)(j0 + r) * QKV_O + H_ + kvh * 64 + dq];
            *(float4*)&Vs[r * 64 + dq] =
                *(const float4*)&qkv[(size_t)(j0 + r) * QKV_O + H_ + NKV_ * HD_ + kvh * 64 + dq];
        }
        __syncthreads();

        float s[8][4] = {};
        #pragma unroll
        for (int d0 = 0; d0 < 64; d0 += 4) {
            float4 k4[4];
            #pragma unroll
            for (int j = 0; j < 4; j++) k4[j] = *(const float4*)&KPs[(tx + 16 * j) * 68 + d0];
            #pragma unroll
            for (int i = 0; i < 8; i++) {
                float4 q4 = *(const float4*)&Qs[(ty * 8 + i) * 64 + d0];
                #pragma unroll
                for (int j = 0; j < 4; j++)
                    s[i][j] += q4.x * k4[j].x + q4.y * k4[j].y
                             + q4.z * k4[j].z + q4.w * k4[j].w;
            }
        }
        __syncthreads();

        #pragma unroll
        for (int i = 0; i < 8; i++) {
            int iq = q0 + ty * 8 + i;
            float p[4];
            float tm = -1e30f;
            #pragma unroll
            for (int j = 0; j < 4; j++) {
                int jk = j0 + tx + 16 * j;
                bool ok = (jk <= iq) && (iq - jk < WIN_);
                s[i][j] = ok ? s[i][j] * 0.125f : -1e30f;
                tm = fmaxf(tm, s[i][j]);
            }
            #pragma unroll
            for (int o = 1; o < 16; o <<= 1)
                tm = fmaxf(tm, __shfl_xor_sync(0xffffffffu, tm, o));
            float mn = fmaxf(rm[i], tm);
            float alpha = __expf(rm[i] - mn);
            rm[i] = mn;
            float ps = 0.f;
            #pragma unroll
            for (int j = 0; j < 4; j++) { p[j] = __expf(s[i][j] - mn); ps += p[j]; }
            #pragma unroll
            for (int o = 1; o < 16; o <<= 1)
                ps += __shfl_xor_sync(0xffffffffu, ps, o);
            rl[i] = rl[i] * alpha + ps;
            #pragma unroll
            for (int j = 0; j < 4; j++) {
                acc[i][j] *= alpha;
                KPs[(ty * 8 + i) * 68 + tx + 16 * j] = p[j];
            }
        }
        __syncthreads();

        #pragma unroll 2
        for (int n = 0; n < 64; n += 2) {
            float2 pv[8];
            float vva[4], vvb[4];
            #pragma unroll
            for (int i = 0; i < 8; i++)
                pv[i] = *(const float2*)&KPs[(ty * 8 + i) * 68 + n];
            #pragma unroll
            for (int j = 0; j < 4; j++) {
                vva[j] = Vs[n * 64 + tx + 16 * j];
                vvb[j] = Vs[(n + 1) * 64 + tx + 16 * j];
            }
            #pragma unroll
            for (int i = 0; i < 8; i++)
                #pragma unroll
                for (int j = 0; j < 4; j++)
                    acc[i][j] += pv[i].x * vva[j] + pv[i].y * vvb[j];
        }
    }

    #pragma unroll
    for (int i = 0; i < 8; i++) {
        float inv = 1.0f / rl[i];
        size_t base = (size_t)(q0 + ty * 8 + i) * H_ + h * 64;
        #pragma unroll
        for (int j = 0; j < 4; j++)
            split1(acc[i][j] * inv, &oh[base + tx + 16 * j], &ol[base + tx + 16 * j]);
    }
}

// ---------------------------------------------------------------------------
__global__ void router_kernel(const float* __restrict__ t,
                              const float* __restrict__ rw,
                              int* counts, int* toklist, float* tokw) {
    int warp = threadIdx.x >> 5;
    int lane = threadIdx.x & 31;
    int tok = blockIdx.x * 8 + warp;
    if (tok >= S_) return;
    const float* tr = t + (size_t)tok * H_;
    float logits[E_];
    for (int e = 0; e < E_; e++) {
        float s = 0.0f;
        for (int k = lane; k < H_; k += 32) s += tr[k] * rw[e * H_ + k];
        for (int o = 16; o > 0; o >>= 1) s += __shfl_xor_sync(0xffffffff, s, o);
        logits[e] = s;
    }
    if (lane == 0) {
        float mx = logits[0];
        for (int e = 1; e < E_; e++) mx = fmaxf(mx, logits[e]);
        float p[E_], sum = 0.0f;
        for (int e = 0; e < E_; e++) { p[e] = __expf(logits[e] - mx); sum += p[e]; }
        float invs = 1.0f / sum;
        for (int e = 0; e < E_; e++) p[e] *= invs;
        int b1 = 0;
        for (int e = 1; e < E_; e++) if (p[e] > p[b1]) b1 = e;
        int b2 = -1;
        for (int e = 0; e < E_; e++) {
            if (e == b1) continue;
            if (b2 < 0 || p[e] > p[b2]) b2 = e;
        }
        int pos1 = atomicAdd(&counts[b1], 1);
        toklist[b1 * S_ + pos1] = tok; tokw[b1 * S_ + pos1] = p[b1];
        int pos2 = atomicAdd(&counts[b2], 1);
        toklist[b2 * S_ + pos2] = tok; tokw[b2 * S_ + pos2] = p[b2];
    }
}

// ---------------------------------------------------------------------------
extern "C" void kernel_launch(void* const* d_in, const int* in_sizes, int n_in,
                              void* d_out, int out_size) {
    const float* hidden   = (const float*)d_in[0];
    const float* w_qkv    = (const float*)d_in[2];
    const float* w_o      = (const float*)d_in[3];
    const float* router_w = (const float*)d_in[4];
    const float* ws       = (const float*)d_in[5];
    const float* w2s      = (const float*)d_in[6];
    const float* ln1      = (const float*)d_in[7];
    const float* ln2      = (const float*)d_in[8];

    float* out    = (float*)d_out;
    float* resid2 = out + (size_t)S_ * H_;

    bf16 *wqh, *wql, *woh, *wol, *xnh, *xnl, *ath, *atl;
    f16 *wsf, *w2f, *tnf, *actf;
    float *qkv, *tnorm, *tokw;
    int *counts, *toklist;
    cudaGetSymbolAddress((void**)&wqh, g_wqkv_h); cudaGetSymbolAddress((void**)&wql, g_wqkv_l);
    cudaGetSymbolAddress((void**)&woh, g_wo_h);   cudaGetSymbolAddress((void**)&wol, g_wo_l);
    cudaGetSymbolAddress((void**)&wsf, g_ws_f);
    cudaGetSymbolAddress((void**)&w2f, g_w2s_f);
    cudaGetSymbolAddress((void**)&xnh, g_xn_h);   cudaGetSymbolAddress((void**)&xnl, g_xn_l);
    cudaGetSymbolAddress((void**)&ath, g_at_h);   cudaGetSymbolAddress((void**)&atl, g_at_l);
    cudaGetSymbolAddress((void**)&tnf, g_tn_f);
    cudaGetSymbolAddress((void**)&actf, g_act_f);
    cudaGetSymbolAddress((void**)&qkv,   g_qkv);
    cudaGetSymbolAddress((void**)&tnorm, g_tnorm);
    cudaGetSymbolAddress((void**)&counts, g_counts);
    cudaGetSymbolAddress((void**)&toklist, g_toklist);
    cudaGetSymbolAddress((void**)&tokw,  g_tokw);

    const int GSMEM2 = 65536;
    const int GSMEM_UP = 34048;   // max(32KB mainloop, 33.3KB swiglu Us)
    const int GSMEM_DN = 32768;
    cudaFuncSetAttribute(hmma2<0>, cudaFuncAttributeMaxDynamicSharedMemorySize, GSMEM2);
    cudaFuncSetAttribute(hmma2<1>, cudaFuncAttributeMaxDynamicSharedMemorySize, GSMEM2);
    cudaFuncSetAttribute(hmma1<1,3>, cudaFuncAttributeMaxDynamicSharedMemorySize, GSMEM_UP);
    cudaFuncSetAttribute(hmma1<0,2>, cudaFuncAttributeMaxDynamicSharedMemorySize, GSMEM_DN);
    int attn_smem = (64 * 64 + 64 * 68 + 64 * 64) * 4;
    cudaFuncSetAttribute(attn_flash, cudaFuncAttributeMaxDynamicSharedMemorySize, attn_smem);

    zero_kernel<<<(S_ * H_ + 255) / 256, 256>>>(out, counts);

    // weight prepasses
    split_kernel<<<(QKV_O * H_ / 4 + 255) / 256, 256>>>(w_qkv, wqh, wql, QKV_O * H_ / 4);
    split_kernel<<<(H_ * H_ / 4 + 255) / 256, 256>>>(w_o, woh, wol, H_ * H_ / 4);
    cvt_ws_perm<<<dim3(1, 2 * I_, E_), 256>>>(ws, wsf);
    cvt_kernel<<<(int)(((size_t)E_ * H_ * I_ / 4 + 255) / 256), 256>>>(
        w2s, w2f, (size_t)E_ * H_ * I_ / 4);

    rmsnorm_hl<<<S_, 256>>>(hidden, ln1, xnh, xnl);

    // QKV (bf16 3-term)
    hmma2<0><<<dim3(S_ / 128, QKV_O / 128, 1), 256, GSMEM2>>>(
        xnh, xnl, wqh, wql, qkv, S_, QKV_O, H_, H_, QKV_O, nullptr);

    attn_flash<<<dim3(S_ / 64, NH_), 128, attn_smem>>>(qkv, ath, atl);

    // O proj + residual (bf16 3-term)
    hmma2<1><<<dim3(S_ / 128, H_ / 128, 1), 256, GSMEM2>>>(
        ath, atl, woh, wol, resid2, S_, H_, H_, H_, H_, hidden);

    rmsnorm_f16<<<S_, 256>>>(resid2, ln2, tnorm, tnf);
    router_kernel<<<S_ / 8, 256>>>(tnorm, router_w, counts, toklist, tokw);

    // MoE up+gate (fp16, gathered A, swiglu fused) -> act fp16
    hmma1<1,3><<<dim3(S_ / 128, 2 * I_ / 128, E_), 256, GSMEM_UP>>>(
        tnf, wsf, nullptr, S_, 2 * I_, H_, H_,
        counts, toklist, nullptr, actf,
        0, (size_t)2 * I_ * H_);

    // MoE down (fp16, weighted scatter)
    hmma1<0,2><<<dim3(S_ / 128, H_ / 128, E_), 256, GSMEM_DN>>>(
        actf, w2f, out, S_, H_, I_, I_,
        counts, toklist, tokw, nullptr,
        (size_t)S_ * I_, (size_t)H_ * I_);
}

// round 10
// speedup vs baseline: 7.2667x; 1.0442x over previous
#include <cuda_runtime.h>
#include <cuda_bf16.h>
#include <cuda_fp16.h>
#include <math.h>
#include <stdint.h>

#define S_  2048
#define H_  1024
#define NH_ 16
#define NKV_ 4
#define HD_ 64
#define QKV_O 1536
#define I_  2816
#define E_  8
#define WIN_ 512
#define EPS_ 1e-5f

typedef __nv_bfloat16 bf16;
typedef __half f16;

// ---------------------------------------------------------------------------
// Scratch (static device globals)
// ---------------------------------------------------------------------------
__device__ bf16 g_wqkv_h[QKV_O * H_], g_wqkv_l[QKV_O * H_];
__device__ bf16 g_wo_h[H_ * H_],      g_wo_l[H_ * H_];
__device__ f16  g_ws_f[(size_t)E_ * 2 * I_ * H_];
__device__ f16  g_w2s_f[(size_t)E_ * H_ * I_];
__device__ bf16 g_xn_h[S_ * H_], g_xn_l[S_ * H_];
__device__ bf16 g_at_h[S_ * H_], g_at_l[S_ * H_];
__device__ f16  g_tn_f[S_ * H_];
__device__ f16  g_act_f[(size_t)E_ * S_ * I_];
__device__ float g_qkv[S_ * QKV_O];
__device__ float g_tnorm[S_ * H_];
__device__ int   g_counts[E_];
__device__ int   g_toklist[E_ * S_];
__device__ float g_tokw[E_ * S_];

// ---------------------------------------------------------------------------
__device__ __forceinline__ uint32_t smem_u32(const void* p) {
    uint32_t a;
    asm("{ .reg .u64 t; cvta.to.shared.u64 t, %1; cvt.u32.u64 %0, t; }"
        : "=r"(a) : "l"(p));
    return a;
}
__device__ __forceinline__ void ldm4(uint32_t& r0, uint32_t& r1,
                                     uint32_t& r2, uint32_t& r3, uint32_t addr) {
    asm volatile("ldmatrix.sync.aligned.m8n8.x4.shared.b16 {%0,%1,%2,%3}, [%4];"
                 : "=r"(r0), "=r"(r1), "=r"(r2), "=r"(r3) : "r"(addr));
}
__device__ __forceinline__ void mma_bf16(float* d, const uint32_t* a,
                                         const uint32_t* b) {
    asm volatile(
        "mma.sync.aligned.m16n8k16.row.col.f32.bf16.bf16.f32 "
        "{%0,%1,%2,%3}, {%4,%5,%6,%7}, {%8,%9}, {%0,%1,%2,%3};"
        : "+f"(d[0]), "+f"(d[1]), "+f"(d[2]), "+f"(d[3])
        : "r"(a[0]), "r"(a[1]), "r"(a[2]), "r"(a[3]), "r"(b[0]), "r"(b[1]));
}
__device__ __forceinline__ void mma_f16(float* d, const uint32_t* a,
                                        const uint32_t* b) {
    asm volatile(
        "mma.sync.aligned.m16n8k16.row.col.f32.f16.f16.f32 "
        "{%0,%1,%2,%3}, {%4,%5,%6,%7}, {%8,%9}, {%0,%1,%2,%3};"
        : "+f"(d[0]), "+f"(d[1]), "+f"(d[2]), "+f"(d[3])
        : "r"(a[0]), "r"(a[1]), "r"(a[2]), "r"(a[3]), "r"(b[0]), "r"(b[1]));
}
__device__ __forceinline__ void cp16(uint32_t dst, const void* src, int sz) {
    asm volatile("cp.async.cg.shared.global [%0], [%1], 16, %2;"
                 :: "r"(dst), "l"(src), "r"(sz));
}
__device__ __forceinline__ void cp_commit() {
    asm volatile("cp.async.commit_group;");
}
__device__ __forceinline__ void cp_wait0() {
    asm volatile("cp.async.wait_group 0;");
}
__device__ __forceinline__ void cp_wait1() {
    asm volatile("cp.async.wait_group 1;");
}

// split fp32 float4 -> bf16 hi/lo (8B each)
__device__ __forceinline__ void split_store4(float4 v, bf16* hp, bf16* lp) {
    __nv_bfloat162 h01 = __floats2bfloat162_rn(v.x, v.y);
    __nv_bfloat162 h23 = __floats2bfloat162_rn(v.z, v.w);
    float2 f01 = __bfloat1622float2(h01);
    float2 f23 = __bfloat1622float2(h23);
    __nv_bfloat162 l01 = __floats2bfloat162_rn(v.x - f01.x, v.y - f01.y);
    __nv_bfloat162 l23 = __floats2bfloat162_rn(v.z - f23.x, v.w - f23.y);
    *(uint2*)hp = make_uint2(*(uint32_t*)&h01, *(uint32_t*)&h23);
    *(uint2*)lp = make_uint2(*(uint32_t*)&l01, *(uint32_t*)&l23);
}
__device__ __forceinline__ void split1(float v, bf16* hp, bf16* lp) {
    bf16 hb = __float2bfloat16(v);
    *hp = hb;
    *lp = __float2bfloat16(v - __bfloat162float(hb));
}
__device__ __forceinline__ void cvt_store4(float4 v, f16* p) {
    __half2 a = __floats2half2_rn(v.x, v.y);
    __half2 b = __floats2half2_rn(v.z, v.w);
    *(uint2*)p = make_uint2(*(uint32_t*)&a, *(uint32_t*)&b);
}

// ---------------------------------------------------------------------------
// hmma2: bf16 3-term split GEMM (router-critical path). 128x128, BK=32,
// 8 warps, cp.async double-buffered, 2 CTAs/SM.
// EPI: 0=store 1=+addsrc
// ---------------------------------------------------------------------------
template<int EPI>
__global__ __launch_bounds__(256, 2)
void hmma2(const bf16* __restrict__ Ah, const bf16* __restrict__ Al,
           const bf16* __restrict__ Bh, const bf16* __restrict__ Bl,
           float* __restrict__ C, int M, int N, int K, int lda, int ldc,
           const float* __restrict__ addsrc)
{
    extern __shared__ char smem[];     // 2 stages x 4 planes x 8KB = 64KB
    int m0 = blockIdx.x * 128;
    int n0 = blockIdx.y * 128;

    int tid = threadIdx.x;
    int wid = tid >> 5;
    int lane = tid & 31;
    int warp_m = wid & 1;
    int warp_n = wid >> 1;

    uint32_t sbase = smem_u32(smem);

    auto issue = [&](int c, int buf) {
        int k0 = c * 32;
        #pragma unroll
        for (int l = 0; l < 8; l++) {
            int seg = tid + l * 256;
            int plane = seg >> 9;
            int row = (seg >> 2) & 127;
            int ch = seg & 3;
            uint32_t dst = sbase + buf * 32768 + plane * 8192
                         + row * 64 + ((ch ^ ((row >> 1) & 3)) << 4);
            const bf16* gsrc;
            if (plane < 2)
                gsrc = (plane ? Al : Ah) + (size_t)(m0 + row) * lda + k0 + ch * 8;
            else
                gsrc = ((plane == 3) ? Bl : Bh) + (size_t)(n0 + row) * K + k0 + ch * 8;
            cp16(dst, gsrc, 16);
        }
        cp_commit();
    };

    float acc[4][4][4] = {};
    const int nc = K / 32;
    issue(0, 0);

    for (int c = 0; c < nc; c++) {
        cp_wait0();
        __syncthreads();
        if (c + 1 < nc) issue(c + 1, (c + 1) & 1);

        uint32_t sb = sbase + (c & 1) * 32768;
        int mi = lane >> 3, r = lane & 7;

        #pragma unroll
        for (int ks = 0; ks < 2; ks++) {
            uint32_t afh[4][4], bfh[4][2];
            #pragma unroll
            for (int nfp = 0; nfp < 2; nfp++) {
                int n = warp_n * 32 + nfp * 16 + ((mi >> 1) << 3) + r;
                int ch = ks * 2 + (mi & 1);
                uint32_t off = (uint32_t)(n * 64 + ((ch ^ ((n >> 1) & 3)) << 4));
                uint32_t r0, r1, r2, r3;
                ldm4(r0, r1, r2, r3, sb + 2 * 8192 + off);
                bfh[nfp * 2 + 0][0] = r0; bfh[nfp * 2 + 0][1] = r1;
                bfh[nfp * 2 + 1][0] = r2; bfh[nfp * 2 + 1][1] = r3;
            }
            #pragma unroll
            for (int mf = 0; mf < 4; mf++) {
                int row = warp_m * 64 + mf * 16 + ((mi & 1) << 3) + r;
                int ch = ks * 2 + (mi >> 1);
                uint32_t off = (uint32_t)(row * 64 + ((ch ^ ((row >> 1) & 3)) << 4));
                ldm4(afh[mf][0], afh[mf][1], afh[mf][2], afh[mf][3], sb + off);
            }
            #pragma unroll
            for (int mf = 0; mf < 4; mf++)
                #pragma unroll
                for (int nf = 0; nf < 4; nf++)
                    mma_bf16(acc[mf][nf], afh[mf], bfh[nf]);
            {
                uint32_t bfl[4][2];
                #pragma unroll
                for (int nfp = 0; nfp < 2; nfp++) {
                    int n = warp_n * 32 + nfp * 16 + ((mi >> 1) << 3) + r;
                    int ch = ks * 2 + (mi & 1);
                    uint32_t off = (uint32_t)(n * 64 + ((ch ^ ((n >> 1) & 3)) << 4));
                    uint32_t r0, r1, r2, r3;
                    ldm4(r0, r1, r2, r3, sb + 3 * 8192 + off);
                    bfl[nfp * 2 + 0][0] = r0; bfl[nfp * 2 + 0][1] = r1;
                    bfl[nfp * 2 + 1][0] = r2; bfl[nfp * 2 + 1][1] = r3;
                }
                #pragma unroll
                for (int mf = 0; mf < 4; mf++)
                    #pragma unroll
                    for (int nf = 0; nf < 4; nf++)
                        mma_bf16(acc[mf][nf], afh[mf], bfl[nf]);
            }
            {
                uint32_t afl[4][4];
                #pragma unroll
                for (int mf = 0; mf < 4; mf++) {
                    int row = warp_m * 64 + mf * 16 + ((mi & 1) << 3) + r;
                    int ch = ks * 2 + (mi >> 1);
                    uint32_t off = (uint32_t)(row * 64 + ((ch ^ ((row >> 1) & 3)) << 4));
                    ldm4(afl[mf][0], afl[mf][1], afl[mf][2], afl[mf][3], sb + 8192 + off);
                }
                #pragma unroll
                for (int mf = 0; mf < 4; mf++)
                    #pragma unroll
                    for (int nf = 0; nf < 4; nf++)
                        mma_bf16(acc[mf][nf], afl[mf], bfh[nf]);
            }
        }
    }

    int lr = lane >> 2;
    int lc = (lane & 3) * 2;
    #pragma unroll
    for (int mf = 0; mf < 4; mf++) {
        int r0g = m0 + warp_m * 64 + mf * 16 + lr;
        int r1g = r0g + 8;
        #pragma unroll
        for (int nf = 0; nf < 4; nf++) {
            int col = n0 + warp_n * 32 + nf * 8 + lc;
            float2 v = make_float2(acc[mf][nf][0], acc[mf][nf][1]);
            float2 w = make_float2(acc[mf][nf][2], acc[mf][nf][3]);
            if (EPI == 1) {
                const float* a2 = addsrc + (size_t)r0g * ldc + col;
                const float* b2 = addsrc + (size_t)r1g * ldc + col;
                v.x += a2[0]; v.y += a2[1];
                w.x += b2[0]; w.y += b2[1];
            }
            *(float2*)(C + (size_t)r0g * ldc + col) = v;
            *(float2*)(C + (size_t)r1g * ldc + col) = w;
        }
    }
}

// ---------------------------------------------------------------------------
// hmma1: plain fp16 GEMM (MoE path). 128x128 tile, BK=64, 8 warps,
// 3-stage cp.async pipeline (2 chunks in flight), 2 CTAs/SM.
// Smem rows: 128B, 8 chunks, swizzle ch ^ (row & 7).
// GATHER: A rows via toklist. EPI: 2=weighted scatter 3=swiglu->act fp16
// ---------------------------------------------------------------------------
template<int GATHER, int EPI>
__global__ __launch_bounds__(256, 2)
void hmma1(const f16* __restrict__ A, const f16* __restrict__ B,
           float* __restrict__ C, int M, int N, int K, int lda,
           const int* __restrict__ counts,
           const int* __restrict__ toklist,
           const float* __restrict__ tokw,
           f16* __restrict__ actF,
           size_t sA, size_t sB)
{
    extern __shared__ char smem[];     // 3 stages x (A 16KB + B 16KB) = 96KB
    __shared__ int rowsS[128];

    int e = blockIdx.z;
    int Mlim = counts[e];
    int m0 = blockIdx.x * 128;
    if (m0 >= Mlim) return;
    int n0 = blockIdx.y * 128;
    const f16* Ae = A + sA * e;
    const f16* Be = B + sB * e;

    int tid = threadIdx.x;
    int wid = tid >> 5;
    int lane = tid & 31;
    int warp_m = wid & 1;
    int warp_n = wid >> 1;

    if (GATHER) {
        if (tid < 128)
            rowsS[tid] = (m0 + tid < Mlim) ? toklist[e * S_ + m0 + tid] : -1;
        __syncthreads();
    }

    uint32_t sbase = smem_u32(smem);

    auto issue = [&](int c, int buf) {
        int k0 = c * 64;
        #pragma unroll
        for (int l = 0; l < 8; l++) {
            int seg = tid + l * 256;
            int plane = seg >> 10;           // 0=A 1=B (1024 segs each)
            int row = (seg >> 3) & 127;
            int ch = seg & 7;
            uint32_t dst = sbase + buf * 32768 + plane * 16384
                         + row * 128 + ((ch ^ (row & 7)) << 4);
            const f16* gsrc;
            int sz = 16;
            if (plane == 0) {
                int gr;
                if (GATHER) {
                    gr = rowsS[row];
                    if (gr < 0) { gr = 0; sz = 0; }
                } else {
                    gr = m0 + row;
                    if (gr >= Mlim) { gr = 0; sz = 0; }
                }
                gsrc = Ae + (size_t)gr * lda + k0 + ch * 8;
            } else {
                gsrc = Be + (size_t)(n0 + row) * K + k0 + ch * 8;
            }
            cp16(dst, gsrc, sz);
        }
        cp_commit();
    };

    float acc[4][4][4] = {};
    const int nc = K / 64;
    issue(0, 0);
    if (nc > 1) issue(1, 1);

    for (int c = 0; c < nc; c++) {
        if (c + 1 < nc) cp_wait1(); else cp_wait0();
        __syncthreads();
        if (c + 2 < nc) issue(c + 2, (c + 2) % 3);

        uint32_t sb = sbase + (c % 3) * 32768;
        int mi = lane >> 3, r = lane & 7;

        #pragma unroll
        for (int ks = 0; ks < 4; ks++) {
            uint32_t af[4][4], bf[4][2];
            #pragma unroll
            for (int nfp = 0; nfp < 2; nfp++) {
                int n = warp_n * 32 + nfp * 16 + ((mi >> 1) << 3) + r;
                int ch = ks * 2 + (mi & 1);
                uint32_t off = (uint32_t)(n * 128 + ((ch ^ (n & 7)) << 4));
                uint32_t r0, r1, r2, r3;
                ldm4(r0, r1, r2, r3, sb + 16384 + off);
                bf[nfp * 2 + 0][0] = r0; bf[nfp * 2 + 0][1] = r1;
                bf[nfp * 2 + 1][0] = r2; bf[nfp * 2 + 1][1] = r3;
            }
            #pragma unroll
            for (int mf = 0; mf < 4; mf++) {
                int row = warp_m * 64 + mf * 16 + ((mi & 1) << 3) + r;
                int ch = ks * 2 + (mi >> 1);
                uint32_t off = (uint32_t)(row * 128 + ((ch ^ (row & 7)) << 4));
                ldm4(af[mf][0], af[mf][1], af[mf][2], af[mf][3], sb + off);
            }
            #pragma unroll
            for (int mf = 0; mf < 4; mf++)
                #pragma unroll
                for (int nf = 0; nf < 4; nf++)
                    mma_f16(acc[mf][nf], af[mf], bf[nf]);
        }
    }

    int lr = lane >> 2;
    int lc = (lane & 3) * 2;

    if (EPI == 3) {
        // swiglu: tile cols [0,64)=gate (warp_n 0,1), [64,128)=up (warp_n 2,3)
        __syncthreads();
        float (*Us)[65] = (float (*)[65])smem;
        if (warp_n >= 2) {
            #pragma unroll
            for (int mf = 0; mf < 4; mf++) {
                int rl0 = warp_m * 64 + mf * 16 + lr;
                #pragma unroll
                for (int nf = 0; nf < 4; nf++) {
                    int j = (warp_n - 2) * 32 + nf * 8 + lc;
                    Us[rl0][j]         = acc[mf][nf][0];
                    Us[rl0][j + 1]     = acc[mf][nf][1];
                    Us[rl0 + 8][j]     = acc[mf][nf][2];
                    Us[rl0 + 8][j + 1] = acc[mf][nf][3];
                }
            }
        }
        __syncthreads();
        if (warp_n < 2) {
            int colbase = n0 >> 1;
            #pragma unroll
            for (int mf = 0; mf < 4; mf++) {
                int rl0 = warp_m * 64 + mf * 16 + lr;
                #pragma unroll
                for (int half = 0; half < 2; half++) {
                    int rl = rl0 + half * 8;
                    int m = m0 + rl;
                    if (m >= Mlim) continue;
                    size_t rowoff = ((size_t)e * S_ + m) * I_ + colbase;
                    #pragma unroll
                    for (int nf = 0; nf < 4; nf++) {
                        int j = warp_n * 32 + nf * 8 + lc;
                        #pragma unroll
                        for (int q = 0; q < 2; q++) {
                            float g = acc[mf][nf][half * 2 + q];
                            float u = Us[rl][j + q];
                            float a = g / (1.f + __expf(-g)) * u;
                            actF[rowoff + j + q] = __float2half_rn(a);
                        }
                    }
                }
            }
        }
        return;
    }

    // EPI == 2: weighted atomic scatter
    #pragma unroll
    for (int mf = 0; mf < 4; mf++) {
        int r0g = m0 + warp_m * 64 + mf * 16 + lr;
        int r1g = r0g + 8;
        int tokA = 0, tokB = 0; float wA = 0.f, wB = 0.f;
        bool vA = (r0g < Mlim), vB = (r1g < Mlim);
        if (vA) { tokA = toklist[e * S_ + r0g]; wA = tokw[e * S_ + r0g]; }
        if (vB) { tokB = toklist[e * S_ + r1g]; wB = tokw[e * S_ + r1g]; }
        #pragma unroll
        for (int nf = 0; nf < 4; nf++) {
            int col = n0 + warp_n * 32 + nf * 8 + lc;
            if (vA) {
                atomicAdd(&C[(size_t)tokA * H_ + col],     wA * acc[mf][nf][0]);
                atomicAdd(&C[(size_t)tokA * H_ + col + 1], wA * acc[mf][nf][1]);
            }
            if (vB) {
                atomicAdd(&C[(size_t)tokB * H_ + col],     wB * acc[mf][nf][2]);
                atomicAdd(&C[(size_t)tokB * H_ + col + 1], wB * acc[mf][nf][3]);
            }
        }
    }
}

// ---------------------------------------------------------------------------
__global__ void split_kernel(const float* __restrict__ src,
                             bf16* __restrict__ h, bf16* __restrict__ l,
                             size_t n4) {
    size_t i = (size_t)blockIdx.x * blockDim.x + threadIdx.x;
    if (i >= n4) return;
    float4 v = ((const float4*)src)[i];
    split_store4(v, h + i * 4, l + i * 4);
}

__global__ void cvt_kernel(const float* __restrict__ src,
                           f16* __restrict__ d, size_t n4) {
    size_t i = (size_t)blockIdx.x * blockDim.x + threadIdx.x;
    if (i >= n4) return;
    float4 v = ((const float4*)src)[i];
    cvt_store4(v, d + i * 4);
}

// ws -> fp16 with gate/up interleave permutation:
// dest row p (tile t=p/128, r=p%128): src = r<64 ? t*64+r : I + t*64 + (r-64)
__global__ void cvt_ws_perm(const float* __restrict__ ws,
                            f16* __restrict__ d) {
    int e = blockIdx.z, p = blockIdx.y;
    int t = p >> 7, r = p & 127;
    int src = (r < 64) ? (t * 64 + r) : (I_ + t * 64 + (r - 64));
    const float* srow = ws + ((size_t)e * 2 * I_ + src) * H_;
    f16* dr = d + ((size_t)e * 2 * I_ + p) * H_;
    int i = threadIdx.x * 4;
    float4 v = *(const float4*)(srow + i);
    cvt_store4(v, dr + i);
}

// ---------------------------------------------------------------------------
__global__ void zero_kernel(float* out, int* counts) {
    int i = blockIdx.x * blockDim.x + threadIdx.x;
    if (i < S_ * H_) out[i] = 0.0f;
    if (i < E_) counts[i] = 0;
}

// RMSNorm -> bf16 hi/lo planes (ln1 path)
__global__ void rmsnorm_hl(const float* __restrict__ x,
                           const float* __restrict__ w,
                           bf16* __restrict__ yh, bf16* __restrict__ yl) {
    int row = blockIdx.x;
    int tid = threadIdx.x;
    __shared__ float red[256];
    const float* xr = x + (size_t)row * H_;
    float s = 0.0f;
    for (int c = tid; c < H_; c += 256) { float v = xr[c]; s += v * v; }
    red[tid] = s; __syncthreads();
    for (int o = 128; o > 0; o >>= 1) {
        if (tid < o) red[tid] += red[tid + o];
        __syncthreads();
    }
    float inv = rsqrtf(red[0] / (float)H_ + EPS_);
    for (int c = tid * 4; c < H_; c += 1024) {
        float4 v = *(const float4*)(xr + c);
        float4 wv = *(const float4*)(w + c);
        v.x *= inv * wv.x; v.y *= inv * wv.y;
        v.z *= inv * wv.z; v.w *= inv * wv.w;
        split_store4(v, yh + (size_t)row * H_ + c, yl + (size_t)row * H_ + c);
    }
}

// RMSNorm -> fp32 (router) + fp16 plane (MoE A) (ln2 path)
__global__ void rmsnorm_f16(const float* __restrict__ x,
                            const float* __restrict__ w,
                            float* __restrict__ y,
                            f16* __restrict__ yf) {
    int row = blockIdx.x;
    int tid = threadIdx.x;
    __shared__ float red[256];
    const float* xr = x + (size_t)row * H_;
    float s = 0.0f;
    for (int c = tid; c < H_; c += 256) { float v = xr[c]; s += v * v; }
    red[tid] = s; __syncthreads();
    for (int o = 128; o > 0; o >>= 1) {
        if (tid < o) red[tid] += red[tid + o];
        __syncthreads();
    }
    float inv = rsqrtf(red[0] / (float)H_ + EPS_);
    for (int c = tid * 4; c < H_; c += 1024) {
        float4 v = *(const float4*)(xr + c);
        float4 wv = *(const float4*)(w + c);
        v.x *= inv * wv.x; v.y *= inv * wv.y;
        v.z *= inv * wv.z; v.w *= inv * wv.w;
        *(float4*)(y + (size_t)row * H_ + c) = v;
        cvt_store4(v, yf + (size_t)row * H_ + c);
    }
}

// ---------------------------------------------------------------------------
// Flash attention (fp32): 128 threads, 8x4 register tile, bf16 hi/lo output
// ---------------------------------------------------------------------------
__global__ __launch_bounds__(128)
void attn_flash(const float* __restrict__ qkv,
                bf16* __restrict__ oh, bf16* __restrict__ ol) {
    extern __shared__ float smf[];
    float* Qs  = smf;
    float* KPs = smf + 4096;
    float* Vs  = smf + 4096 + 64 * 68;

    int qt = blockIdx.x, h = blockIdx.y;
    int q0 = qt * 64;
    int kvh = h >> 2;
    int tid = threadIdx.x;
    int tx = tid & 15, ty = tid >> 4;

    #pragma unroll
    for (int l = 0; l < 8; l++) {
        int idx = tid + l * 128;
        int r = idx >> 4, dq = (idx & 15) * 4;
        *(float4*)&Qs[r * 64 + dq] =
            *(const float4*)&qkv[(size_t)(q0 + r) * QKV_O + h * 64 + dq];
    }

    float acc[8][4] = {};
    float rm[8], rl[8];
    #pragma unroll
    for (int i = 0; i < 8; i++) { rm[i] = -1e30f; rl[i] = 0.f; }

    int t0 = (q0 > 511) ? ((q0 - 511) >> 6) : 0;
    for (int kt = t0; kt <= qt; kt++) {
        int j0 = kt * 64;
        __syncthreads();
        #pragma unroll
        for (int l = 0; l < 8; l++) {
            int idx = tid + l * 128;
            int r = idx >> 4, dq = (idx & 15) * 4;
            *(float4*)&KPs[r * 68 + dq] =
                *(const float4*)&qkv[(size_t)(j0 + r) * QKV_O + H_ + kvh * 64 + dq];
            *(float4*)&Vs[r * 64 + dq] =
                *(const float4*)&qkv[(size_t)(j0 + r) * QKV_O + H_ + NKV_ * HD_ + kvh * 64 + dq];
        }
        __syncthreads();

        float s[8][4] = {};
        #pragma unroll
        for (int d0 = 0; d0 < 64; d0 += 4) {
            float4 k4[4];
            #pragma unroll
            for (int j = 0; j < 4; j++) k4[j] = *(const float4*)&KPs[(tx + 16 * j) * 68 + d0];
            #pragma unroll
            for (int i = 0; i < 8; i++) {
                float4 q4 = *(const float4*)&Qs[(ty * 8 + i) * 64 + d0];
                #pragma unroll
                for (int j = 0; j < 4; j++)
                    s[i][j] += q4.x * k4[j].x + q4.y * k4[j].y
                             + q4.z * k4[j].z + q4.w * k4[j].w;
            }
        }
        __syncthreads();

        #pragma unroll
        for (int i = 0; i < 8; i++) {
            int iq = q0 + ty * 8 + i;
            float p[4];
            float tm = -1e30f;
            #pragma unroll
            for (int j = 0; j < 4; j++) {
                int jk = j0 + tx + 16 * j;
                bool ok = (jk <= iq) && (iq - jk < WIN_);
                s[i][j] = ok ? s[i][j] * 0.125f : -1e30f;
                tm = fmaxf(tm, s[i][j]);
            }
            #pragma unroll
            for (int o = 1; o < 16; o <<= 1)
                tm = fmaxf(tm, __shfl_xor_sync(0xffffffffu, tm, o));
            float mn = fmaxf(rm[i], tm);
            float alpha = __expf(rm[i] - mn);
            rm[i] = mn;
            float ps = 0.f;
            #pragma unroll
            for (int j = 0; j < 4; j++) { p[j] = __expf(s[i][j] - mn); ps += p[j]; }
            #pragma unroll
            for (int o = 1; o < 16; o <<= 1)
                ps += __shfl_xor_sync(0xffffffffu, ps, o);
            rl[i] = rl[i] * alpha + ps;
            #pragma unroll
            for (int j = 0; j < 4; j++) {
                acc[i][j] *= alpha;
                KPs[(ty * 8 + i) * 68 + tx + 16 * j] = p[j];
            }
        }
        __syncthreads();

        #pragma unroll 2
        for (int n = 0; n < 64; n += 2) {
            float2 pv[8];
            float vva[4], vvb[4];
            #pragma unroll
            for (int i = 0; i < 8; i++)
                pv[i] = *(const float2*)&KPs[(ty * 8 + i) * 68 + n];
            #pragma unroll
            for (int j = 0; j < 4; j++) {
                vva[j] = Vs[n * 64 + tx + 16 * j];
                vvb[j] = Vs[(n + 1) * 64 + tx + 16 * j];
            }
            #pragma unroll
            for (int i = 0; i < 8; i++)
                #pragma unroll
                for (int j = 0; j < 4; j++)
                    acc[i][j] += pv[i].x * vva[j] + pv[i].y * vvb[j];
        }
    }

    #pragma unroll
    for (int i = 0; i < 8; i++) {
        float inv = 1.0f / rl[i];
        size_t base = (size_t)(q0 + ty * 8 + i) * H_ + h * 64;
        #pragma unroll
        for (int j = 0; j < 4; j++)
            split1(acc[i][j] * inv, &oh[base + tx + 16 * j], &ol[base + tx + 16 * j]);
    }
}

// ---------------------------------------------------------------------------
__global__ void router_kernel(const float* __restrict__ t,
                              const float* __restrict__ rw,
                              int* counts, int* toklist, float* tokw) {
    int warp = threadIdx.x >> 5;
    int lane = threadIdx.x & 31;
    int tok = blockIdx.x * 8 + warp;
    if (tok >= S_) return;
    const float* tr = t + (size_t)tok * H_;
    float logits[E_];
    for (int e = 0; e < E_; e++) {
        float s = 0.0f;
        for (int k = lane; k < H_; k += 32) s += tr[k] * rw[e * H_ + k];
        for (int o = 16; o > 0; o >>= 1) s += __shfl_xor_sync(0xffffffff, s, o);
        logits[e] = s;
    }
    if (lane == 0) {
        float mx = logits[0];
        for (int e = 1; e < E_; e++) mx = fmaxf(mx, logits[e]);
        float p[E_], sum = 0.0f;
        for (int e = 0; e < E_; e++) { p[e] = __expf(logits[e] - mx); sum += p[e]; }
        float invs = 1.0f / sum;
        for (int e = 0; e < E_; e++) p[e] *= invs;
        int b1 = 0;
        for (int e = 1; e < E_; e++) if (p[e] > p[b1]) b1 = e;
        int b2 = -1;
        for (int e = 0; e < E_; e++) {
            if (e == b1) continue;
            if (b2 < 0 || p[e] > p[b2]) b2 = e;
        }
        int pos1 = atomicAdd(&counts[b1], 1);
        toklist[b1 * S_ + pos1] = tok; tokw[b1 * S_ + pos1] = p[b1];
        int pos2 = atomicAdd(&counts[b2], 1);
        toklist[b2 * S_ + pos2] = tok; tokw[b2 * S_ + pos2] = p[b2];
    }
}

// ---------------------------------------------------------------------------
extern "C" void kernel_launch(void* const* d_in, const int* in_sizes, int n_in,
                              void* d_out, int out_size) {
    const float* hidden   = (const float*)d_in[0];
    const float* w_qkv    = (const float*)d_in[2];
    const float* w_o      = (const float*)d_in[3];
    const float* router_w = (const float*)d_in[4];
    const float* ws       = (const float*)d_in[5];
    const float* w2s      = (const float*)d_in[6];
    const float* ln1      = (const float*)d_in[7];
    const float* ln2      = (const float*)d_in[8];

    float* out    = (float*)d_out;
    float* resid2 = out + (size_t)S_ * H_;

    bf16 *wqh, *wql, *woh, *wol, *xnh, *xnl, *ath, *atl;
    f16 *wsf, *w2f, *tnf, *actf;
    float *qkv, *tnorm, *tokw;
    int *counts, *toklist;
    cudaGetSymbolAddress((void**)&wqh, g_wqkv_h); cudaGetSymbolAddress((void**)&wql, g_wqkv_l);
    cudaGetSymbolAddress((void**)&woh, g_wo_h);   cudaGetSymbolAddress((void**)&wol, g_wo_l);
    cudaGetSymbolAddress((void**)&wsf, g_ws_f);
    cudaGetSymbolAddress((void**)&w2f, g_w2s_f);
    cudaGetSymbolAddress((void**)&xnh, g_xn_h);   cudaGetSymbolAddress((void**)&xnl, g_xn_l);
    cudaGetSymbolAddress((void**)&ath, g_at_h);   cudaGetSymbolAddress((void**)&atl, g_at_l);
    cudaGetSymbolAddress((void**)&tnf, g_tn_f);
    cudaGetSymbolAddress((void**)&actf, g_act_f);
    cudaGetSymbolAddress((void**)&qkv,   g_qkv);
    cudaGetSymbolAddress((void**)&tnorm, g_tnorm);
    cudaGetSymbolAddress((void**)&counts, g_counts);
    cudaGetSymbolAddress((void**)&toklist, g_toklist);
    cudaGetSymbolAddress((void**)&tokw,  g_tokw);

    const int GSMEM2 = 65536;
    const int GSMEM1 = 98304;      // 3 stages x 32KB
    cudaFuncSetAttribute(hmma2<0>, cudaFuncAttributeMaxDynamicSharedMemorySize, GSMEM2);
    cudaFuncSetAttribute(hmma2<1>, cudaFuncAttributeMaxDynamicSharedMemorySize, GSMEM2);
    cudaFuncSetAttribute(hmma1<1,3>, cudaFuncAttributeMaxDynamicSharedMemorySize, GSMEM1);
    cudaFuncSetAttribute(hmma1<0,2>, cudaFuncAttributeMaxDynamicSharedMemorySize, GSMEM1);
    int attn_smem = (64 * 64 + 64 * 68 + 64 * 64) * 4;
    cudaFuncSetAttribute(attn_flash, cudaFuncAttributeMaxDynamicSharedMemorySize, attn_smem);

    zero_kernel<<<(S_ * H_ + 255) / 256, 256>>>(out, counts);

    // weight prepasses
    split_kernel<<<(QKV_O * H_ / 4 + 255) / 256, 256>>>(w_qkv, wqh, wql, QKV_O * H_ / 4);
    split_kernel<<<(H_ * H_ / 4 + 255) / 256, 256>>>(w_o, woh, wol, H_ * H_ / 4);
    cvt_ws_perm<<<dim3(1, 2 * I_, E_), 256>>>(ws, wsf);
    cvt_kernel<<<(int)(((size_t)E_ * H_ * I_ / 4 + 255) / 256), 256>>>(
        w2s, w2f, (size_t)E_ * H_ * I_ / 4);

    rmsnorm_hl<<<S_, 256>>>(hidden, ln1, xnh, xnl);

    // QKV (bf16 3-term)
    hmma2<0><<<dim3(S_ / 128, QKV_O / 128, 1), 256, GSMEM2>>>(
        xnh, xnl, wqh, wql, qkv, S_, QKV_O, H_, H_, QKV_O, nullptr);

    attn_flash<<<dim3(S_ / 64, NH_), 128, attn_smem>>>(qkv, ath, atl);

    // O proj + residual (bf16 3-term)
    hmma2<1><<<dim3(S_ / 128, H_ / 128, 1), 256, GSMEM2>>>(
        ath, atl, woh, wol, resid2, S_, H_, H_, H_, H_, hidden);

    rmsnorm_f16<<<S_, 256>>>(resid2, ln2, tnorm, tnf);
    router_kernel<<<S_ / 8, 256>>>(tnorm, router_w, counts, toklist, tokw);

    // MoE up+gate (fp16, gathered A, swiglu fused) -> act fp16
    hmma1<1,3><<<dim3(S_ / 128, 2 * I_ / 128, E_), 256, GSMEM1>>>(
        tnf, wsf, nullptr, S_, 2 * I_, H_, H_,
        counts, toklist, nullptr, actf,
        0, (size_t)2 * I_ * H_);

    // MoE down (fp16, weighted scatter)
    hmma1<0,2><<<dim3(S_ / 128, H_ / 128, E_), 256, GSMEM1>>>(
        actf, w2f, out, S_, H_, I_, I_,
        counts, toklist, tokw, nullptr,
        (size_t)S_ * I_, (size_t)H_ * I_);
}

// round 11
// speedup vs baseline: 7.5190x; 1.0347x over previous
#include <cuda_runtime.h>
#include <cuda_bf16.h>
#include <cuda_fp16.h>
#include <math.h>
#include <stdint.h>

#define S_  2048
#define H_  1024
#define NH_ 16
#define NKV_ 4
#define HD_ 64
#define QKV_O 1536
#define I_  2816
#define E_  8
#define WIN_ 512
#define EPS_ 1e-5f

typedef __nv_bfloat16 bf16;
typedef __half f16;
typedef unsigned long long u64;

// ---------------------------------------------------------------------------
// Scratch (static device globals)
// ---------------------------------------------------------------------------
__device__ bf16 g_wqkv_h[QKV_O * H_], g_wqkv_l[QKV_O * H_];
__device__ bf16 g_wo_h[H_ * H_],      g_wo_l[H_ * H_];
__device__ f16  g_ws_f[(size_t)E_ * 2 * I_ * H_];
__device__ f16  g_w2s_f[(size_t)E_ * H_ * I_];
__device__ bf16 g_xn_h[S_ * H_], g_xn_l[S_ * H_];
__device__ bf16 g_at_h[S_ * H_], g_at_l[S_ * H_];
__device__ f16  g_tn_f[S_ * H_];
__device__ f16  g_act_f[(size_t)E_ * S_ * I_];
__device__ float g_y[(size_t)E_ * S_ * H_];        // per-slot MoE outputs
__device__ float g_qkv[S_ * QKV_O];
__device__ float g_tnorm[S_ * H_];
__device__ int   g_counts[E_];
__device__ int   g_toklist[E_ * S_];
__device__ float g_tokw[E_ * S_];
__device__ int   g_tokslot[S_ * 2];
__device__ float g_tokw2[S_ * 2];

// ---------------------------------------------------------------------------
__device__ __forceinline__ uint32_t smem_u32(const void* p) {
    uint32_t a;
    asm("{ .reg .u64 t; cvta.to.shared.u64 t, %1; cvt.u32.u64 %0, t; }"
        : "=r"(a) : "l"(p));
    return a;
}
__device__ __forceinline__ void ldm4(uint32_t& r0, uint32_t& r1,
                                     uint32_t& r2, uint32_t& r3, uint32_t addr) {
    asm volatile("ldmatrix.sync.aligned.m8n8.x4.shared.b16 {%0,%1,%2,%3}, [%4];"
                 : "=r"(r0), "=r"(r1), "=r"(r2), "=r"(r3) : "r"(addr));
}
__device__ __forceinline__ void mma_bf16(float* d, const uint32_t* a,
                                         const uint32_t* b) {
    asm volatile(
        "mma.sync.aligned.m16n8k16.row.col.f32.bf16.bf16.f32 "
        "{%0,%1,%2,%3}, {%4,%5,%6,%7}, {%8,%9}, {%0,%1,%2,%3};"
        : "+f"(d[0]), "+f"(d[1]), "+f"(d[2]), "+f"(d[3])
        : "r"(a[0]), "r"(a[1]), "r"(a[2]), "r"(a[3]), "r"(b[0]), "r"(b[1]));
}
__device__ __forceinline__ void mma_f16(float* d, const uint32_t* a,
                                        const uint32_t* b) {
    asm volatile(
        "mma.sync.aligned.m16n8k16.row.col.f32.f16.f16.f32 "
        "{%0,%1,%2,%3}, {%4,%5,%6,%7}, {%8,%9}, {%0,%1,%2,%3};"
        : "+f"(d[0]), "+f"(d[1]), "+f"(d[2]), "+f"(d[3])
        : "r"(a[0]), "r"(a[1]), "r"(a[2]), "r"(a[3]), "r"(b[0]), "r"(b[1]));
}
__device__ __forceinline__ void cp16(uint32_t dst, const void* src, int sz) {
    asm volatile("cp.async.cg.shared.global [%0], [%1], 16, %2;"
                 :: "r"(dst), "l"(src), "r"(sz));
}
__device__ __forceinline__ void cp_commit() {
    asm volatile("cp.async.commit_group;");
}
__device__ __forceinline__ void cp_wait0() {
    asm volatile("cp.async.wait_group 0;");
}
__device__ __forceinline__ void cp_wait1() {
    asm volatile("cp.async.wait_group 1;");
}

// packed f32x2 helpers
__device__ __forceinline__ u64 pack2(float lo, float hi) {
    u64 r; asm("mov.b64 %0, {%1,%2};" : "=l"(r) : "f"(lo), "f"(hi)); return r;
}
__device__ __forceinline__ void unpack2(u64 v, float& lo, float& hi) {
    asm("mov.b64 {%0,%1}, %2;" : "=f"(lo), "=f"(hi) : "l"(v));
}
__device__ __forceinline__ void ffma2(u64& d, u64 a, u64 b) {
    asm("fma.rn.f32x2 %0, %1, %2, %0;" : "+l"(d) : "l"(a), "l"(b));
}
__device__ __forceinline__ void mulf2(u64& d, u64 a) {
    asm("mul.rn.f32x2 %0, %0, %1;" : "+l"(d) : "l"(a));
}

// split fp32 float4 -> bf16 hi/lo (8B each)
__device__ __forceinline__ void split_store4(float4 v, bf16* hp, bf16* lp) {
    __nv_bfloat162 h01 = __floats2bfloat162_rn(v.x, v.y);
    __nv_bfloat162 h23 = __floats2bfloat162_rn(v.z, v.w);
    float2 f01 = __bfloat1622float2(h01);
    float2 f23 = __bfloat1622float2(h23);
    __nv_bfloat162 l01 = __floats2bfloat162_rn(v.x - f01.x, v.y - f01.y);
    __nv_bfloat162 l23 = __floats2bfloat162_rn(v.z - f23.x, v.w - f23.y);
    *(uint2*)hp = make_uint2(*(uint32_t*)&h01, *(uint32_t*)&h23);
    *(uint2*)lp = make_uint2(*(uint32_t*)&l01, *(uint32_t*)&l23);
}
__device__ __forceinline__ void split1(float v, bf16* hp, bf16* lp) {
    bf16 hb = __float2bfloat16(v);
    *hp = hb;
    *lp = __float2bfloat16(v - __bfloat162float(hb));
}
__device__ __forceinline__ void cvt_store4(float4 v, f16* p) {
    __half2 a = __floats2half2_rn(v.x, v.y);
    __half2 b = __floats2half2_rn(v.z, v.w);
    *(uint2*)p = make_uint2(*(uint32_t*)&a, *(uint32_t*)&b);
}

// ---------------------------------------------------------------------------
// hmma2: bf16 3-term split GEMM (router-critical path). 128x128, BK=32,
// 8 warps, cp.async double-buffered, 2 CTAs/SM.  EPI: 0=store 1=+addsrc
// ---------------------------------------------------------------------------
template<int EPI>
__global__ __launch_bounds__(256, 2)
void hmma2(const bf16* __restrict__ Ah, const bf16* __restrict__ Al,
           const bf16* __restrict__ Bh, const bf16* __restrict__ Bl,
           float* __restrict__ C, int M, int N, int K, int lda, int ldc,
           const float* __restrict__ addsrc)
{
    extern __shared__ char smem[];
    int m0 = blockIdx.x * 128;
    int n0 = blockIdx.y * 128;

    int tid = threadIdx.x;
    int wid = tid >> 5;
    int lane = tid & 31;
    int warp_m = wid & 1;
    int warp_n = wid >> 1;

    uint32_t sbase = smem_u32(smem);

    auto issue = [&](int c, int buf) {
        int k0 = c * 32;
        #pragma unroll
        for (int l = 0; l < 8; l++) {
            int seg = tid + l * 256;
            int plane = seg >> 9;
            int row = (seg >> 2) & 127;
            int ch = seg & 3;
            uint32_t dst = sbase + buf * 32768 + plane * 8192
                         + row * 64 + ((ch ^ ((row >> 1) & 3)) << 4);
            const bf16* gsrc;
            if (plane < 2)
                gsrc = (plane ? Al : Ah) + (size_t)(m0 + row) * lda + k0 + ch * 8;
            else
                gsrc = ((plane == 3) ? Bl : Bh) + (size_t)(n0 + row) * K + k0 + ch * 8;
            cp16(dst, gsrc, 16);
        }
        cp_commit();
    };

    float acc[4][4][4] = {};
    const int nc = K / 32;
    issue(0, 0);

    for (int c = 0; c < nc; c++) {
        cp_wait0();
        __syncthreads();
        if (c + 1 < nc) issue(c + 1, (c + 1) & 1);

        uint32_t sb = sbase + (c & 1) * 32768;
        int mi = lane >> 3, r = lane & 7;

        #pragma unroll
        for (int ks = 0; ks < 2; ks++) {
            uint32_t afh[4][4], bfh[4][2];
            #pragma unroll
            for (int nfp = 0; nfp < 2; nfp++) {
                int n = warp_n * 32 + nfp * 16 + ((mi >> 1) << 3) + r;
                int ch = ks * 2 + (mi & 1);
                uint32_t off = (uint32_t)(n * 64 + ((ch ^ ((n >> 1) & 3)) << 4));
                uint32_t r0, r1, r2, r3;
                ldm4(r0, r1, r2, r3, sb + 2 * 8192 + off);
                bfh[nfp * 2 + 0][0] = r0; bfh[nfp * 2 + 0][1] = r1;
                bfh[nfp * 2 + 1][0] = r2; bfh[nfp * 2 + 1][1] = r3;
            }
            #pragma unroll
            for (int mf = 0; mf < 4; mf++) {
                int row = warp_m * 64 + mf * 16 + ((mi & 1) << 3) + r;
                int ch = ks * 2 + (mi >> 1);
                uint32_t off = (uint32_t)(row * 64 + ((ch ^ ((row >> 1) & 3)) << 4));
                ldm4(afh[mf][0], afh[mf][1], afh[mf][2], afh[mf][3], sb + off);
            }
            #pragma unroll
            for (int mf = 0; mf < 4; mf++)
                #pragma unroll
                for (int nf = 0; nf < 4; nf++)
                    mma_bf16(acc[mf][nf], afh[mf], bfh[nf]);
            {
                uint32_t bfl[4][2];
                #pragma unroll
                for (int nfp = 0; nfp < 2; nfp++) {
                    int n = warp_n * 32 + nfp * 16 + ((mi >> 1) << 3) + r;
                    int ch = ks * 2 + (mi & 1);
                    uint32_t off = (uint32_t)(n * 64 + ((ch ^ ((n >> 1) & 3)) << 4));
                    uint32_t r0, r1, r2, r3;
                    ldm4(r0, r1, r2, r3, sb + 3 * 8192 + off);
                    bfl[nfp * 2 + 0][0] = r0; bfl[nfp * 2 + 0][1] = r1;
                    bfl[nfp * 2 + 1][0] = r2; bfl[nfp * 2 + 1][1] = r3;
                }
                #pragma unroll
                for (int mf = 0; mf < 4; mf++)
                    #pragma unroll
                    for (int nf = 0; nf < 4; nf++)
                        mma_bf16(acc[mf][nf], afh[mf], bfl[nf]);
            }
            {
                uint32_t afl[4][4];
                #pragma unroll
                for (int mf = 0; mf < 4; mf++) {
                    int row = warp_m * 64 + mf * 16 + ((mi & 1) << 3) + r;
                    int ch = ks * 2 + (mi >> 1);
                    uint32_t off = (uint32_t)(row * 64 + ((ch ^ ((row >> 1) & 3)) << 4));
                    ldm4(afl[mf][0], afl[mf][1], afl[mf][2], afl[mf][3], sb + 8192 + off);
                }
                #pragma unroll
                for (int mf = 0; mf < 4; mf++)
                    #pragma unroll
                    for (int nf = 0; nf < 4; nf++)
                        mma_bf16(acc[mf][nf], afl[mf], bfh[nf]);
            }
        }
    }

    int lr = lane >> 2;
    int lc = (lane & 3) * 2;
    #pragma unroll
    for (int mf = 0; mf < 4; mf++) {
        int r0g = m0 + warp_m * 64 + mf * 16 + lr;
        int r1g = r0g + 8;
        #pragma unroll
        for (int nf = 0; nf < 4; nf++) {
            int col = n0 + warp_n * 32 + nf * 8 + lc;
            float2 v = make_float2(acc[mf][nf][0], acc[mf][nf][1]);
            float2 w = make_float2(acc[mf][nf][2], acc[mf][nf][3]);
            if (EPI == 1) {
                const float* a2 = addsrc + (size_t)r0g * ldc + col;
                const float* b2 = addsrc + (size_t)r1g * ldc + col;
                v.x += a2[0]; v.y += a2[1];
                w.x += b2[0]; w.y += b2[1];
            }
            *(float2*)(C + (size_t)r0g * ldc + col) = v;
            *(float2*)(C + (size_t)r1g * ldc + col) = w;
        }
    }
}

// ---------------------------------------------------------------------------
// hmma1: plain fp16 GEMM (MoE path). 128x128 tile, BK=64, 8 warps,
// 3-stage cp.async pipeline, 2 CTAs/SM.
// GATHER: A rows via toklist.
// EPI: 0=dense per-slot store to C (ldc)  3=swiglu->act fp16
// ---------------------------------------------------------------------------
template<int GATHER, int EPI>
__global__ __launch_bounds__(256, 2)
void hmma1(const f16* __restrict__ A, const f16* __restrict__ B,
           float* __restrict__ C, int M, int N, int K, int lda, int ldc,
           const int* __restrict__ counts,
           const int* __restrict__ toklist,
           f16* __restrict__ actF,
           size_t sA, size_t sB, size_t sC)
{
    extern __shared__ char smem[];
    __shared__ int rowsS[128];

    int e = blockIdx.z;
    int Mlim = counts[e];
    int m0 = blockIdx.x * 128;
    if (m0 >= Mlim) return;
    int n0 = blockIdx.y * 128;
    const f16* Ae = A + sA * e;
    const f16* Be = B + sB * e;
    float*     Ce = C ? C + sC * e : nullptr;

    int tid = threadIdx.x;
    int wid = tid >> 5;
    int lane = tid & 31;
    int warp_m = wid & 1;
    int warp_n = wid >> 1;

    if (GATHER) {
        if (tid < 128)
            rowsS[tid] = (m0 + tid < Mlim) ? toklist[e * S_ + m0 + tid] : -1;
        __syncthreads();
    }

    uint32_t sbase = smem_u32(smem);

    auto issue = [&](int c, int buf) {
        int k0 = c * 64;
        #pragma unroll
        for (int l = 0; l < 8; l++) {
            int seg = tid + l * 256;
            int plane = seg >> 10;
            int row = (seg >> 3) & 127;
            int ch = seg & 7;
            uint32_t dst = sbase + buf * 32768 + plane * 16384
                         + row * 128 + ((ch ^ (row & 7)) << 4);
            const f16* gsrc;
            int sz = 16;
            if (plane == 0) {
                int gr;
                if (GATHER) {
                    gr = rowsS[row];
                    if (gr < 0) { gr = 0; sz = 0; }
                } else {
                    gr = m0 + row;
                    if (gr >= Mlim) { gr = 0; sz = 0; }
                }
                gsrc = Ae + (size_t)gr * lda + k0 + ch * 8;
            } else {
                gsrc = Be + (size_t)(n0 + row) * K + k0 + ch * 8;
            }
            cp16(dst, gsrc, sz);
        }
        cp_commit();
    };

    float acc[4][4][4] = {};
    const int nc = K / 64;
    issue(0, 0);
    if (nc > 1) issue(1, 1);

    for (int c = 0; c < nc; c++) {
        if (c + 1 < nc) cp_wait1(); else cp_wait0();
        __syncthreads();
        if (c + 2 < nc) issue(c + 2, (c + 2) % 3);

        uint32_t sb = sbase + (c % 3) * 32768;
        int mi = lane >> 3, r = lane & 7;

        #pragma unroll
        for (int ks = 0; ks < 4; ks++) {
            uint32_t af[4][4], bf[4][2];
            #pragma unroll
            for (int nfp = 0; nfp < 2; nfp++) {
                int n = warp_n * 32 + nfp * 16 + ((mi >> 1) << 3) + r;
                int ch = ks * 2 + (mi & 1);
                uint32_t off = (uint32_t)(n * 128 + ((ch ^ (n & 7)) << 4));
                uint32_t r0, r1, r2, r3;
                ldm4(r0, r1, r2, r3, sb + 16384 + off);
                bf[nfp * 2 + 0][0] = r0; bf[nfp * 2 + 0][1] = r1;
                bf[nfp * 2 + 1][0] = r2; bf[nfp * 2 + 1][1] = r3;
            }
            #pragma unroll
            for (int mf = 0; mf < 4; mf++) {
                int row = warp_m * 64 + mf * 16 + ((mi & 1) << 3) + r;
                int ch = ks * 2 + (mi >> 1);
                uint32_t off = (uint32_t)(row * 128 + ((ch ^ (row & 7)) << 4));
                ldm4(af[mf][0], af[mf][1], af[mf][2], af[mf][3], sb + off);
            }
            #pragma unroll
            for (int mf = 0; mf < 4; mf++)
                #pragma unroll
                for (int nf = 0; nf < 4; nf++)
                    mma_f16(acc[mf][nf], af[mf], bf[nf]);
        }
    }

    int lr = lane >> 2;
    int lc = (lane & 3) * 2;

    if (EPI == 3) {
        __syncthreads();
        float (*Us)[65] = (float (*)[65])smem;
        if (warp_n >= 2) {
            #pragma unroll
            for (int mf = 0; mf < 4; mf++) {
                int rl0 = warp_m * 64 + mf * 16 + lr;
                #pragma unroll
                for (int nf = 0; nf < 4; nf++) {
                    int j = (warp_n - 2) * 32 + nf * 8 + lc;
                    Us[rl0][j]         = acc[mf][nf][0];
                    Us[rl0][j + 1]     = acc[mf][nf][1];
                    Us[rl0 + 8][j]     = acc[mf][nf][2];
                    Us[rl0 + 8][j + 1] = acc[mf][nf][3];
                }
            }
        }
        __syncthreads();
        if (warp_n < 2) {
            int colbase = n0 >> 1;
            #pragma unroll
            for (int mf = 0; mf < 4; mf++) {
                int rl0 = warp_m * 64 + mf * 16 + lr;
                #pragma unroll
                for (int half = 0; half < 2; half++) {
                    int rl = rl0 + half * 8;
                    int m = m0 + rl;
                    if (m >= Mlim) continue;
                    size_t rowoff = ((size_t)e * S_ + m) * I_ + colbase;
                    #pragma unroll
                    for (int nf = 0; nf < 4; nf++) {
                        int j = warp_n * 32 + nf * 8 + lc;
                        #pragma unroll
                        for (int q = 0; q < 2; q++) {
                            float g = acc[mf][nf][half * 2 + q];
                            float u = Us[rl][j + q];
                            float a = g / (1.f + __expf(-g)) * u;
                            actF[rowoff + j + q] = __float2half_rn(a);
                        }
                    }
                }
            }
        }
        return;
    }

    // EPI == 0: dense per-slot store
    #pragma unroll
    for (int mf = 0; mf < 4; mf++) {
        int r0g = m0 + warp_m * 64 + mf * 16 + lr;
        int r1g = r0g + 8;
        #pragma unroll
        for (int nf = 0; nf < 4; nf++) {
            int col = n0 + warp_n * 32 + nf * 8 + lc;
            if (r0g < Mlim)
                *(float2*)(Ce + (size_t)r0g * ldc + col) =
                    make_float2(acc[mf][nf][0], acc[mf][nf][1]);
            if (r1g < Mlim)
                *(float2*)(Ce + (size_t)r1g * ldc + col) =
                    make_float2(acc[mf][nf][2], acc[mf][nf][3]);
        }
    }
}

// ---------------------------------------------------------------------------
__global__ void split_kernel(const float* __restrict__ src,
                             bf16* __restrict__ h, bf16* __restrict__ l,
                             size_t n4) {
    size_t i = (size_t)blockIdx.x * blockDim.x + threadIdx.x;
    if (i >= n4) return;
    float4 v = ((const float4*)src)[i];
    split_store4(v, h + i * 4, l + i * 4);
}

__global__ void cvt_kernel(const float* __restrict__ src,
                           f16* __restrict__ d, size_t n4) {
    size_t i = (size_t)blockIdx.x * blockDim.x + threadIdx.x;
    if (i >= n4) return;
    float4 v = ((const float4*)src)[i];
    cvt_store4(v, d + i * 4);
}

// ws -> fp16 with gate/up interleave permutation
__global__ void cvt_ws_perm(const float* __restrict__ ws,
                            f16* __restrict__ d) {
    int e = blockIdx.z, p = blockIdx.y;
    int t = p >> 7, r = p & 127;
    int src = (r < 64) ? (t * 64 + r) : (I_ + t * 64 + (r - 64));
    const float* srow = ws + ((size_t)e * 2 * I_ + src) * H_;
    f16* dr = d + ((size_t)e * 2 * I_ + p) * H_;
    int i = threadIdx.x * 4;
    float4 v = *(const float4*)(srow + i);
    cvt_store4(v, dr + i);
}

// ---------------------------------------------------------------------------
__global__ void zero_counts(int* counts) {
    if (threadIdx.x < E_) counts[threadIdx.x] = 0;
}

// RMSNorm -> bf16 hi/lo planes (ln1 path)
__global__ void rmsnorm_hl(const float* __restrict__ x,
                           const float* __restrict__ w,
                           bf16* __restrict__ yh, bf16* __restrict__ yl) {
    int row = blockIdx.x;
    int tid = threadIdx.x;
    __shared__ float red[256];
    const float* xr = x + (size_t)row * H_;
    float s = 0.0f;
    for (int c = tid; c < H_; c += 256) { float v = xr[c]; s += v * v; }
    red[tid] = s; __syncthreads();
    for (int o = 128; o > 0; o >>= 1) {
        if (tid < o) red[tid] += red[tid + o];
        __syncthreads();
    }
    float inv = rsqrtf(red[0] / (float)H_ + EPS_);
    for (int c = tid * 4; c < H_; c += 1024) {
        float4 v = *(const float4*)(xr + c);
        float4 wv = *(const float4*)(w + c);
        v.x *= inv * wv.x; v.y *= inv * wv.y;
        v.z *= inv * wv.z; v.w *= inv * wv.w;
        split_store4(v, yh + (size_t)row * H_ + c, yl + (size_t)row * H_ + c);
    }
}

// RMSNorm -> fp32 (router) + fp16 plane (MoE A) (ln2 path)
__global__ void rmsnorm_f16(const float* __restrict__ x,
                            const float* __restrict__ w,
                            float* __restrict__ y,
                            f16* __restrict__ yf) {
    int row = blockIdx.x;
    int tid = threadIdx.x;
    __shared__ float red[256];
    const float* xr = x + (size_t)row * H_;
    float s = 0.0f;
    for (int c = tid; c < H_; c += 256) { float v = xr[c]; s += v * v; }
    red[tid] = s; __syncthreads();
    for (int o = 128; o > 0; o >>= 1) {
        if (tid < o) red[tid] += red[tid + o];
        __syncthreads();
    }
    float inv = rsqrtf(red[0] / (float)H_ + EPS_);
    for (int c = tid * 4; c < H_; c += 1024) {
        float4 v = *(const float4*)(xr + c);
        float4 wv = *(const float4*)(w + c);
        v.x *= inv * wv.x; v.y *= inv * wv.y;
        v.z *= inv * wv.z; v.w *= inv * wv.w;
        *(float4*)(y + (size_t)row * H_ + c) = v;
        cvt_store4(v, yf + (size_t)row * H_ + c);
    }
}

// ---------------------------------------------------------------------------
// Flash attention (fp32, f32x2-packed math): 128 threads, 8x4 register tile
// ---------------------------------------------------------------------------
__global__ __launch_bounds__(128)
void attn_flash(const float* __restrict__ qkv,
                bf16* __restrict__ oh, bf16* __restrict__ ol) {
    extern __shared__ float smf[];
    float* Qs  = smf;                      // [64][64]
    float* KPs = smf + 4096;               // [64][68]
    float* Vs  = smf + 4096 + 64 * 68;     // [64][64]

    int qt = blockIdx.x, h = blockIdx.y;
    int q0 = qt * 64;
    int kvh = h >> 2;
    int tid = threadIdx.x;
    int tx = tid & 15, ty = tid >> 4;

    #pragma unroll
    for (int l = 0; l < 8; l++) {
        int idx = tid + l * 128;
        int r = idx >> 4, dq = (idx & 15) * 4;
        *(float4*)&Qs[r * 64 + dq] =
            *(const float4*)&qkv[(size_t)(q0 + r) * QKV_O + h * 64 + dq];
    }

    u64 acc2[8][4];
    #pragma unroll
    for (int i = 0; i < 8; i++)
        #pragma unroll
        for (int j = 0; j < 4; j++) acc2[i][j] = 0ull;
    float rm[8], rl[8];
    #pragma unroll
    for (int i = 0; i < 8; i++) { rm[i] = -1e30f; rl[i] = 0.f; }

    int t0 = (q0 > 511) ? ((q0 - 511) >> 6) : 0;
    for (int kt = t0; kt <= qt; kt++) {
        int j0 = kt * 64;
        __syncthreads();
        #pragma unroll
        for (int l = 0; l < 8; l++) {
            int idx = tid + l * 128;
            int r = idx >> 4, dq = (idx & 15) * 4;
            *(float4*)&KPs[r * 68 + dq] =
                *(const float4*)&qkv[(size_t)(j0 + r) * QKV_O + H_ + kvh * 64 + dq];
            *(float4*)&Vs[r * 64 + dq] =
                *(const float4*)&qkv[(size_t)(j0 + r) * QKV_O + H_ + NKV_ * HD_ + kvh * 64 + dq];
        }
        __syncthreads();

        // S = Q K^T with packed f32x2
        u64 s2[8][4];
        #pragma unroll
        for (int i = 0; i < 8; i++)
            #pragma unroll
            for (int j = 0; j < 4; j++) s2[i][j] = 0ull;
        #pragma unroll
        for (int d0 = 0; d0 < 64; d0 += 4) {
            u64 ka[4], kb[4];
            #pragma unroll
            for (int j = 0; j < 4; j++) {
                const u64* kp = (const u64*)&KPs[(tx + 16 * j) * 68 + d0];
                ka[j] = kp[0]; kb[j] = kp[1];
            }
            #pragma unroll
            for (int i = 0; i < 8; i++) {
                const u64* qp = (const u64*)&Qs[(ty * 8 + i) * 64 + d0];
                u64 qa = qp[0], qb = qp[1];
                #pragma unroll
                for (int j = 0; j < 4; j++) {
                    ffma2(s2[i][j], qa, ka[j]);
                    ffma2(s2[i][j], qb, kb[j]);
                }
            }
        }
        __syncthreads();

        #pragma unroll
        for (int i = 0; i < 8; i++) {
            int iq = q0 + ty * 8 + i;
            float p[4], s[4];
            float tm = -1e30f;
            #pragma unroll
            for (int j = 0; j < 4; j++) {
                float lo, hi;
                unpack2(s2[i][j], lo, hi);
                int jk = j0 + tx + 16 * j;
                bool ok = (jk <= iq) && (iq - jk < WIN_);
                s[j] = ok ? (lo + hi) * 0.125f : -1e30f;
                tm = fmaxf(tm, s[j]);
            }
            #pragma unroll
            for (int o = 1; o < 16; o <<= 1)
                tm = fmaxf(tm, __shfl_xor_sync(0xffffffffu, tm, o));
            float mn = fmaxf(rm[i], tm);
            float alpha = __expf(rm[i] - mn);
            rm[i] = mn;
            float ps = 0.f;
            #pragma unroll
            for (int j = 0; j < 4; j++) { p[j] = __expf(s[j] - mn); ps += p[j]; }
            #pragma unroll
            for (int o = 1; o < 16; o <<= 1)
                ps += __shfl_xor_sync(0xffffffffu, ps, o);
            rl[i] = rl[i] * alpha + ps;
            u64 alpha2 = pack2(alpha, alpha);
            #pragma unroll
            for (int j = 0; j < 4; j++) {
                mulf2(acc2[i][j], alpha2);
                KPs[(ty * 8 + i) * 68 + tx + 16 * j] = p[j];
            }
        }
        __syncthreads();

        // O += P V with packed f32x2 (pairs along n)
        #pragma unroll 2
        for (int n = 0; n < 64; n += 2) {
            u64 pv2[8];
            #pragma unroll
            for (int i = 0; i < 8; i++)
                pv2[i] = *(const u64*)&KPs[(ty * 8 + i) * 68 + n];
            u64 v2[4];
            #pragma unroll
            for (int j = 0; j < 4; j++)
                v2[j] = pack2(Vs[n * 64 + tx + 16 * j],
                              Vs[(n + 1) * 64 + tx + 16 * j]);
            #pragma unroll
            for (int i = 0; i < 8; i++)
                #pragma unroll
                for (int j = 0; j < 4; j++)
                    ffma2(acc2[i][j], pv2[i], v2[j]);
        }
    }

    #pragma unroll
    for (int i = 0; i < 8; i++) {
        float inv = 1.0f / rl[i];
        size_t base = (size_t)(q0 + ty * 8 + i) * H_ + h * 64;
        #pragma unroll
        for (int j = 0; j < 4; j++) {
            float lo, hi;
            unpack2(acc2[i][j], lo, hi);
            split1((lo + hi) * inv, &oh[base + tx + 16 * j], &ol[base + tx + 16 * j]);
        }
    }
}

// ---------------------------------------------------------------------------
__global__ void router_kernel(const float* __restrict__ t,
                              const float* __restrict__ rw,
                              int* counts, int* toklist, float* tokw,
                              int* tokslot, float* tokw2) {
    int warp = threadIdx.x >> 5;
    int lane = threadIdx.x & 31;
    int tok = blockIdx.x * 8 + warp;
    if (tok >= S_) return;
    const float* tr = t + (size_t)tok * H_;
    float logits[E_];
    for (int e = 0; e < E_; e++) {
        float s = 0.0f;
        for (int k = lane; k < H_; k += 32) s += tr[k] * rw[e * H_ + k];
        for (int o = 16; o > 0; o >>= 1) s += __shfl_xor_sync(0xffffffff, s, o);
        logits[e] = s;
    }
    if (lane == 0) {
        float mx = logits[0];
        for (int e = 1; e < E_; e++) mx = fmaxf(mx, logits[e]);
        float p[E_], sum = 0.0f;
        for (int e = 0; e < E_; e++) { p[e] = __expf(logits[e] - mx); sum += p[e]; }
        float invs = 1.0f / sum;
        for (int e = 0; e < E_; e++) p[e] *= invs;
        int b1 = 0;
        for (int e = 1; e < E_; e++) if (p[e] > p[b1]) b1 = e;
        int b2 = -1;
        for (int e = 0; e < E_; e++) {
            if (e == b1) continue;
            if (b2 < 0 || p[e] > p[b2]) b2 = e;
        }
        int pos1 = atomicAdd(&counts[b1], 1);
        toklist[b1 * S_ + pos1] = tok; tokw[b1 * S_ + pos1] = p[b1];
        tokslot[tok * 2] = b1 * S_ + pos1; tokw2[tok * 2] = p[b1];
        int pos2 = atomicAdd(&counts[b2], 1);
        toklist[b2 * S_ + pos2] = tok; tokw[b2 * S_ + pos2] = p[b2];
        tokslot[tok * 2 + 1] = b2 * S_ + pos2; tokw2[tok * 2 + 1] = p[b2];
    }
}

// out[tok] = w1 * y[slot1] + w2 * y[slot2]
__global__ void combine_kernel(const float* __restrict__ y,
                               const int* __restrict__ tokslot,
                               const float* __restrict__ tokw2,
                               float* __restrict__ out) {
    int tok = blockIdx.x;
    int c = threadIdx.x * 4;
    int s1 = tokslot[tok * 2], s2 = tokslot[tok * 2 + 1];
    float w1 = tokw2[tok * 2], w2 = tokw2[tok * 2 + 1];
    float4 a = *(const float4*)&y[(size_t)s1 * H_ + c];
    float4 b = *(const float4*)&y[(size_t)s2 * H_ + c];
    float4 o;
    o.x = w1 * a.x + w2 * b.x;
    o.y = w1 * a.y + w2 * b.y;
    o.z = w1 * a.z + w2 * b.z;
    o.w = w1 * a.w + w2 * b.w;
    *(float4*)&out[(size_t)tok * H_ + c] = o;
}

// ---------------------------------------------------------------------------
extern "C" void kernel_launch(void* const* d_in, const int* in_sizes, int n_in,
                              void* d_out, int out_size) {
    const float* hidden   = (const float*)d_in[0];
    const float* w_qkv    = (const float*)d_in[2];
    const float* w_o      = (const float*)d_in[3];
    const float* router_w = (const float*)d_in[4];
    const float* ws       = (const float*)d_in[5];
    const float* w2s      = (const float*)d_in[6];
    const float* ln1      = (const float*)d_in[7];
    const float* ln2      = (const float*)d_in[8];

    float* out    = (float*)d_out;
    float* resid2 = out + (size_t)S_ * H_;

    bf16 *wqh, *wql, *woh, *wol, *xnh, *xnl, *ath, *atl;
    f16 *wsf, *w2f, *tnf, *actf;
    float *qkv, *tnorm, *tokw, *tokw2, *yb;
    int *counts, *toklist, *tokslot;
    cudaGetSymbolAddress((void**)&wqh, g_wqkv_h); cudaGetSymbolAddress((void**)&wql, g_wqkv_l);
    cudaGetSymbolAddress((void**)&woh, g_wo_h);   cudaGetSymbolAddress((void**)&wol, g_wo_l);
    cudaGetSymbolAddress((void**)&wsf, g_ws_f);
    cudaGetSymbolAddress((void**)&w2f, g_w2s_f);
    cudaGetSymbolAddress((void**)&xnh, g_xn_h);   cudaGetSymbolAddress((void**)&xnl, g_xn_l);
    cudaGetSymbolAddress((void**)&ath, g_at_h);   cudaGetSymbolAddress((void**)&atl, g_at_l);
    cudaGetSymbolAddress((void**)&tnf, g_tn_f);
    cudaGetSymbolAddress((void**)&actf, g_act_f);
    cudaGetSymbolAddress((void**)&yb, g_y);
    cudaGetSymbolAddress((void**)&qkv,   g_qkv);
    cudaGetSymbolAddress((void**)&tnorm, g_tnorm);
    cudaGetSymbolAddress((void**)&counts, g_counts);
    cudaGetSymbolAddress((void**)&toklist, g_toklist);
    cudaGetSymbolAddress((void**)&tokw,  g_tokw);
    cudaGetSymbolAddress((void**)&tokslot, g_tokslot);
    cudaGetSymbolAddress((void**)&tokw2, g_tokw2);

    const int GSMEM2 = 65536;
    const int GSMEM1 = 98304;
    cudaFuncSetAttribute(hmma2<0>, cudaFuncAttributeMaxDynamicSharedMemorySize, GSMEM2);
    cudaFuncSetAttribute(hmma2<1>, cudaFuncAttributeMaxDynamicSharedMemorySize, GSMEM2);
    cudaFuncSetAttribute(hmma1<1,3>, cudaFuncAttributeMaxDynamicSharedMemorySize, GSMEM1);
    cudaFuncSetAttribute(hmma1<0,0>, cudaFuncAttributeMaxDynamicSharedMemorySize, GSMEM1);
    int attn_smem = (64 * 64 + 64 * 68 + 64 * 64) * 4;
    cudaFuncSetAttribute(attn_flash, cudaFuncAttributeMaxDynamicSharedMemorySize, attn_smem);

    zero_counts<<<1, 32>>>(counts);

    // weight prepasses
    split_kernel<<<(QKV_O * H_ / 4 + 255) / 256, 256>>>(w_qkv, wqh, wql, QKV_O * H_ / 4);
    split_kernel<<<(H_ * H_ / 4 + 255) / 256, 256>>>(w_o, woh, wol, H_ * H_ / 4);
    cvt_ws_perm<<<dim3(1, 2 * I_, E_), 256>>>(ws, wsf);
    cvt_kernel<<<(int)(((size_t)E_ * H_ * I_ / 4 + 255) / 256), 256>>>(
        w2s, w2f, (size_t)E_ * H_ * I_ / 4);

    rmsnorm_hl<<<S_, 256>>>(hidden, ln1, xnh, xnl);

    // QKV (bf16 3-term)
    hmma2<0><<<dim3(S_ / 128, QKV_O / 128, 1), 256, GSMEM2>>>(
        xnh, xnl, wqh, wql, qkv, S_, QKV_O, H_, H_, QKV_O, nullptr);

    attn_flash<<<dim3(S_ / 64, NH_), 128, attn_smem>>>(qkv, ath, atl);

    // O proj + residual (bf16 3-term)
    hmma2<1><<<dim3(S_ / 128, H_ / 128, 1), 256, GSMEM2>>>(
        ath, atl, woh, wol, resid2, S_, H_, H_, H_, H_, hidden);

    rmsnorm_f16<<<S_, 256>>>(resid2, ln2, tnorm, tnf);
    router_kernel<<<S_ / 8, 256>>>(tnorm, router_w, counts, toklist, tokw,
                                   tokslot, tokw2);

    // MoE up+gate (fp16, gathered A, swiglu fused) -> act fp16
    hmma1<1,3><<<dim3(S_ / 128, 2 * I_ / 128, E_), 256, GSMEM1>>>(
        tnf, wsf, nullptr, S_, 2 * I_, H_, H_, 0,
        counts, toklist, actf,
        0, (size_t)2 * I_ * H_, 0);

    // MoE down (fp16) -> dense per-slot y
    hmma1<0,0><<<dim3(S_ / 128, H_ / 128, E_), 256, GSMEM1>>>(
        actf, w2f, yb, S_, H_, I_, I_, H_,
        counts, toklist, nullptr,
        (size_t)S_ * I_, (size_t)H_ * I_, (size_t)S_ * H_);

    // combine: out[tok] = w1*y[slot1] + w2*y[slot2]
    combine_kernel<<<S_, 256>>>(yb, tokslot, tokw2, out);
}